// round 6
// baseline (speedup 1.0000x reference)
#include <cuda_runtime.h>
#include <cuda_bf16.h>
#include <cstdint>

// Problem dims
#define B_  4
#define S_  2048
#define DM_ 2048
#define H_  16
#define HD_ 128
#define SCALE_ 0.08838834764831843f   // 1/sqrt(128)

typedef __nv_bfloat16 bf16;

// ---------------- scratch (__device__ globals) ----------------
__device__ bf16 g_xh[(size_t)B_ * S_ * DM_];
__device__ bf16 g_xl[(size_t)B_ * S_ * DM_];
__device__ bf16 g_Qh[(size_t)B_ * S_ * DM_];
__device__ bf16 g_Ql[(size_t)B_ * S_ * DM_];
__device__ bf16 g_Kh[(size_t)B_ * S_ * HD_];
__device__ bf16 g_Kl[(size_t)B_ * S_ * HD_];
__device__ bf16 g_Vth[(size_t)B_ * HD_ * S_];     // [B][128][2048]
__device__ bf16 g_Vtl[(size_t)B_ * HD_ * S_];
__device__ bf16 g_attnh[(size_t)B_ * S_ * DM_];
__device__ bf16 g_attnl[(size_t)B_ * S_ * DM_];
__device__ bf16 g_Wqh[(size_t)DM_ * DM_];         // transposed [N][K]
__device__ bf16 g_Wql[(size_t)DM_ * DM_];
__device__ bf16 g_Wkh[(size_t)HD_ * DM_];
__device__ bf16 g_Wkl[(size_t)HD_ * DM_];
__device__ bf16 g_Wvh[(size_t)HD_ * DM_];
__device__ bf16 g_Wvl[(size_t)HD_ * DM_];
__device__ bf16 g_Woh[(size_t)DM_ * DM_];
__device__ bf16 g_Wol[(size_t)DM_ * DM_];
__device__ float g_rowsum[(size_t)B_ * H_ * S_];

// ---------------- tiling ----------------
// CTA tile 256(M) x 128(N), BK=32. 8 warps, warp tile 64x64 (wm=wid>>1, wn=wid&1).
#define LDT 40
#define TA_BYTES (256 * LDT * 2)          // 20480 per A array (hi or lo)
#define TB_BYTES (128 * LDT * 2)          // 10240 per B array
#define STAGE_BYTES (2 * TA_BYTES + 2 * TB_BYTES)   // 61440
#define AUX_OFF (3 * STAGE_BYTES)         // 184320  (rinv/bias: up to 256 floats)
#define SMEM_BYTES (AUX_OFF + 1536)       // 185856

// ---------------- low-level helpers ----------------
__device__ __forceinline__ uint32_t smem_u32(const void* p) {
    uint32_t a;
    asm("{ .reg .u64 t; cvta.to.shared.u64 t, %1; cvt.u32.u64 %0, t; }" : "=r"(a) : "l"(p));
    return a;
}
__device__ __forceinline__ void cp16(uint32_t s, const void* g) {
    asm volatile("cp.async.ca.shared.global [%0], [%1], 16;"
                 :: "r"(s), "l"(__cvta_generic_to_global(g)));
}
#define CP_COMMIT() asm volatile("cp.async.commit_group;" ::: "memory")
#define CP_WAIT1()  asm volatile("cp.async.wait_group 1;" ::: "memory")
__device__ __forceinline__ void ldsm4(uint32_t* r, uint32_t a) {
    asm volatile("ldmatrix.sync.aligned.m8n8.x4.shared.b16 {%0,%1,%2,%3}, [%4];"
        : "=r"(r[0]), "=r"(r[1]), "=r"(r[2]), "=r"(r[3]) : "r"(a));
}
__device__ __forceinline__ void mma_bf16(float* d, const uint32_t* a, uint32_t b0, uint32_t b1) {
    asm volatile("mma.sync.aligned.m16n8k16.row.col.f32.bf16.bf16.f32 "
        "{%0,%1,%2,%3}, {%4,%5,%6,%7}, {%8,%9}, {%0,%1,%2,%3};"
        : "+f"(d[0]), "+f"(d[1]), "+f"(d[2]), "+f"(d[3])
        : "r"(a[0]), "r"(a[1]), "r"(a[2]), "r"(a[3]), "r"(b0), "r"(b1));
}
__device__ __forceinline__ uint32_t bits2(__nv_bfloat162 h) {
    return *reinterpret_cast<uint32_t*>(&h);
}
__device__ __forceinline__ void split4(float4 v, uint32_t& h0, uint32_t& h1,
                                       uint32_t& l0, uint32_t& l1) {
    __nv_bfloat162 a = __floats2bfloat162_rn(v.x, v.y);
    __nv_bfloat162 b = __floats2bfloat162_rn(v.z, v.w);
    float2 fa = __bfloat1622float2(a);
    float2 fb = __bfloat1622float2(b);
    __nv_bfloat162 c = __floats2bfloat162_rn(v.x - fa.x, v.y - fa.y);
    __nv_bfloat162 d = __floats2bfloat162_rn(v.z - fb.x, v.w - fb.y);
    h0 = bits2(a); h1 = bits2(b); l0 = bits2(c); l1 = bits2(d);
}

// ---------------- tile movement ----------------
// cp.async one chunk: A 256x32 (hi+lo) + B 128x32 (hi+lo)
__device__ __forceinline__ void issue_tiles(char* buf,
    const bf16* __restrict__ Ahg, const bf16* __restrict__ Alg, size_t lda,
    const bf16* __restrict__ Bhg, const bf16* __restrict__ Blg, size_t ldb,
    int k0, int tid)
{
    uint32_t sA = smem_u32(buf);
#pragma unroll
    for (int i = 0; i < 4; i++) {
        int idx = i * 256 + tid;
        int r = idx >> 2, c8 = (idx & 3) * 8;
        uint32_t d = sA + r * (LDT * 2) + c8 * 2;
        cp16(d, Ahg + (size_t)r * lda + k0 + c8);
        cp16(d + TA_BYTES, Alg + (size_t)r * lda + k0 + c8);
    }
    uint32_t sB = sA + 2 * TA_BYTES;
#pragma unroll
    for (int i = 0; i < 2; i++) {
        int idx = i * 256 + tid;
        int r = idx >> 2, c8 = (idx & 3) * 8;
        uint32_t d = sB + r * (LDT * 2) + c8 * 2;
        cp16(d, Bhg + (size_t)r * ldb + k0 + c8);
        cp16(d + TB_BYTES, Blg + (size_t)r * ldb + k0 + c8);
    }
}
// cp.async B tiles only (PV)
__device__ __forceinline__ void issue_B(char* buf,
    const bf16* __restrict__ Bhg, const bf16* __restrict__ Blg, size_t ldb,
    int k0, int tid)
{
    uint32_t sB = smem_u32(buf) + 2 * TA_BYTES;
#pragma unroll
    for (int i = 0; i < 2; i++) {
        int idx = i * 256 + tid;
        int r = idx >> 2, c8 = (idx & 3) * 8;
        uint32_t d = sB + r * (LDT * 2) + c8 * 2;
        cp16(d, Bhg + (size_t)r * ldb + k0 + c8);
        cp16(d + TB_BYTES, Blg + (size_t)r * ldb + k0 + c8);
    }
}
// PV A path: load fp32 scores, normalize, write back, split to smem
__device__ __forceinline__ void fill_A_pv(char* buf, float* __restrict__ A, size_t lda,
                                          int k0, const float* __restrict__ rinv, int tid)
{
    bf16* Ah = (bf16*)buf;
    bf16* Al = (bf16*)(buf + TA_BYTES);
#pragma unroll
    for (int i = 0; i < 8; i++) {
        int idx = i * 256 + tid;
        int r = idx >> 3, c = (idx & 7) * 4;
        float4 v = *(float4*)(A + (size_t)r * lda + k0 + c);
        float ri = rinv[r];
        v.x *= ri; v.y *= ri; v.z *= ri; v.w *= ri;
        *(float4*)(A + (size_t)r * lda + k0 + c) = v;
        uint32_t h0, h1, l0, l1; split4(v, h0, h1, l0, l1);
        int o = r * LDT + c;
        *(uint2*)(Ah + o) = make_uint2(h0, h1);
        *(uint2*)(Al + o) = make_uint2(l0, l1);
    }
}

// ---------------- MMA compute: one 32-K chunk, warp 64x64, 3-term split ----------------
__device__ __forceinline__ void compute_chunk(float (*acc)[8][4], char* buf,
                                              int wm, int wn, int lane)
{
    bf16* Ah = (bf16*)buf;
    bf16* Al = (bf16*)(buf + TA_BYTES);
    bf16* Bh = (bf16*)(buf + 2 * TA_BYTES);
    bf16* Bl = (bf16*)(buf + 2 * TA_BYTES + TB_BYTES);
    const int ar = lane & 15;
    const int acs = (lane >> 4) << 3;
#pragma unroll
    for (int kk = 0; kk < 32; kk += 16) {
        const int ac = kk + acs;
        uint32_t aH[4][4], aL[4][4];
#pragma unroll
        for (int mt = 0; mt < 4; mt++) {
            ldsm4(aH[mt], smem_u32(Ah + (wm * 64 + mt * 16 + ar) * LDT + ac));
            ldsm4(aL[mt], smem_u32(Al + (wm * 64 + mt * 16 + ar) * LDT + ac));
        }
#pragma unroll
        for (int p = 0; p < 4; p++) {
            uint32_t bh[4], bl[4];
            ldsm4(bh, smem_u32(Bh + (wn * 64 + p * 16 + ar) * LDT + ac));
            ldsm4(bl, smem_u32(Bl + (wn * 64 + p * 16 + ar) * LDT + ac));
#pragma unroll
            for (int mt = 0; mt < 4; mt++) {
                mma_bf16(acc[mt][2 * p],     aH[mt], bh[0], bh[2]);
                mma_bf16(acc[mt][2 * p + 1], aH[mt], bh[1], bh[3]);
                mma_bf16(acc[mt][2 * p],     aH[mt], bl[0], bl[2]);
                mma_bf16(acc[mt][2 * p + 1], aH[mt], bl[1], bl[3]);
                mma_bf16(acc[mt][2 * p],     aL[mt], bh[0], bh[2]);
                mma_bf16(acc[mt][2 * p + 1], aL[mt], bh[1], bh[3]);
            }
        }
    }
}

// generic pipelined core
__device__ __forceinline__ void gemm_core(float (*acc)[8][4],
    const bf16* __restrict__ Ahg, const bf16* __restrict__ Alg, size_t lda,
    const bf16* __restrict__ Bhg, const bf16* __restrict__ Blg, size_t ldb,
    int Kdim, char* smem)
{
    const int tid = threadIdx.x, wid = tid >> 5, lane = tid & 31;
    const int wm = wid >> 1, wn = wid & 1;
    const int nC = Kdim >> 5;
    issue_tiles(smem, Ahg, Alg, lda, Bhg, Blg, ldb, 0, tid); CP_COMMIT();
    issue_tiles(smem + STAGE_BYTES, Ahg, Alg, lda, Bhg, Blg, ldb, 32, tid); CP_COMMIT();
#pragma unroll 1
    for (int c = 0; c < nC; c++) {
        CP_WAIT1();
        __syncthreads();
        if (c + 2 < nC)
            issue_tiles(smem + ((c + 2) % 3) * STAGE_BYTES, Ahg, Alg, lda,
                        Bhg, Blg, ldb, (c + 2) * 32, tid);
        CP_COMMIT();
        compute_chunk(acc, smem + (c % 3) * STAGE_BYTES, wm, wn, lane);
    }
    __syncthreads();
}

// PV pipelined core (A = fp32 scores, normalized in place)
__device__ __forceinline__ void gemm_core_pv(float (*acc)[8][4],
    float* __restrict__ A, size_t lda,
    const bf16* __restrict__ Bhg, const bf16* __restrict__ Blg, size_t ldb,
    int Kdim, char* smem, const float* __restrict__ rinv)
{
    const int tid = threadIdx.x, wid = tid >> 5, lane = tid & 31;
    const int wm = wid >> 1, wn = wid & 1;
    const int nC = Kdim >> 5;
    issue_B(smem, Bhg, Blg, ldb, 0, tid); CP_COMMIT();
    issue_B(smem + STAGE_BYTES, Bhg, Blg, ldb, 32, tid); CP_COMMIT();
#pragma unroll 1
    for (int c = 0; c < nC; c++) {
        CP_WAIT1();
        fill_A_pv(smem + (c % 3) * STAGE_BYTES, A, lda, c * 32, rinv, tid);
        __syncthreads();
        if (c + 2 < nC)
            issue_B(smem + ((c + 2) % 3) * STAGE_BYTES, Bhg, Blg, ldb, (c + 2) * 32, tid);
        CP_COMMIT();
        compute_chunk(acc, smem + (c % 3) * STAGE_BYTES, wm, wn, lane);
    }
    __syncthreads();
}

// stage one 128-row half (h=0: rows 0-127, h=1: 128-255) into stg[128][132]
__device__ __forceinline__ void stage_half(float (*acc)[8][4], float* stg,
                                           int wid, int lane, int h)
{
    int wm = wid >> 1, wn = wid & 1;
    if ((wm >> 1) != h) return;
    int r0 = (wm & 1) * 64 + (lane >> 2), c0 = wn * 64 + (lane & 3) * 2;
#pragma unroll
    for (int mt = 0; mt < 4; mt++)
#pragma unroll
        for (int nt = 0; nt < 8; nt++) {
            int r = r0 + mt * 16, c = c0 + nt * 8;
            *(float2*)&stg[r * 132 + c] = make_float2(acc[mt][nt][0], acc[mt][nt][1]);
            *(float2*)&stg[(r + 8) * 132 + c] = make_float2(acc[mt][nt][2], acc[mt][nt][3]);
        }
}

#define ZERO_ACC(acc) \
    _Pragma("unroll") for (int i_ = 0; i_ < 4; i_++) \
    _Pragma("unroll") for (int j_ = 0; j_ < 8; j_++) \
    _Pragma("unroll") for (int q_ = 0; q_ < 4; q_++) acc[i_][j_][q_] = 0.0f;

// ---------------- prep kernels ----------------
__global__ void split_x_kernel(const float* __restrict__ x, bf16* __restrict__ xh,
                               bf16* __restrict__ xl, int n4) {
    int i = blockIdx.x * blockDim.x + threadIdx.x;
    if (i >= n4) return;
    float4 v = *(const float4*)(x + 4 * (size_t)i);
    uint32_t h0, h1, l0, l1; split4(v, h0, h1, l0, l1);
    *(uint2*)(xh + 4 * (size_t)i) = make_uint2(h0, h1);
    *(uint2*)(xl + 4 * (size_t)i) = make_uint2(l0, l1);
}
__global__ void transpose_split_kernel(const float* __restrict__ src,
                                       bf16* __restrict__ dh, bf16* __restrict__ dl,
                                       int M, int N) {
    __shared__ float t[32][33];
    int bx = blockIdx.x * 32, by = blockIdx.y * 32;
    int x = threadIdx.x, y0 = threadIdx.y;
#pragma unroll
    for (int j = 0; j < 32; j += 8)
        t[y0 + j][x] = src[(size_t)(by + y0 + j) * N + bx + x];
    __syncthreads();
#pragma unroll
    for (int j = 0; j < 32; j += 8) {
        float v = t[x][y0 + j];
        bf16 h = __float2bfloat16_rn(v);
        bf16 l = __float2bfloat16_rn(v - __bfloat162float(h));
        size_t o = (size_t)(bx + y0 + j) * M + by + x;
        dh[o] = h; dl[o] = l;
    }
}
__global__ void zero_kernel(float* p, int n) {
    int i = blockIdx.x * blockDim.x + threadIdx.x;
    if (i < n) p[i] = 0.0f;
}

// ---------------- proj GEMM, split epilogue ----------------
__global__ __launch_bounds__(256, 1) void mma_proj_split(
    const bf16* __restrict__ Ahg, const bf16* __restrict__ Alg, size_t lda,
    const bf16* __restrict__ Bhg, const bf16* __restrict__ Blg, size_t ldb,
    const float* __restrict__ bias,
    bf16* __restrict__ Ch, bf16* __restrict__ Cl, size_t ldc, int Kdim)
{
    extern __shared__ __align__(16) char smem[];
    const int tid = threadIdx.x, wid = tid >> 5, lane = tid & 31;
    const int row0 = blockIdx.y * 256, col0 = blockIdx.x * 128;

    float* bs = (float*)(smem + AUX_OFF);
    if (tid < 128) bs[tid] = bias[col0 + tid];

    float acc[4][8][4];
    ZERO_ACC(acc)
    gemm_core(acc, Ahg + (size_t)row0 * lda, Alg + (size_t)row0 * lda, lda,
              Bhg + (size_t)col0 * ldb, Blg + (size_t)col0 * ldb, ldb, Kdim, smem);

    float* stg = (float*)smem;
#pragma unroll 1
    for (int hf = 0; hf < 2; hf++) {
        stage_half(acc, stg, wid, lane, hf);
        __syncthreads();
#pragma unroll 1
        for (int i = 0; i < 16; i++) {
            int rr = i * 8 + wid, c4 = lane * 4;
            float4 v = *(float4*)&stg[rr * 132 + c4];
            v.x += bs[c4]; v.y += bs[c4 + 1]; v.z += bs[c4 + 2]; v.w += bs[c4 + 3];
            uint32_t h0, h1, l0, l1; split4(v, h0, h1, l0, l1);
            size_t o = (size_t)(row0 + hf * 128 + rr) * ldc + col0 + c4;
            *(uint2*)(Ch + o) = make_uint2(h0, h1);
            *(uint2*)(Cl + o) = make_uint2(l0, l1);
        }
        __syncthreads();
    }
}

// ---------------- V projection, transposed split epilogue ----------------
__global__ __launch_bounds__(256, 1) void mma_vproj(
    const bf16* __restrict__ Ahg, const bf16* __restrict__ Alg,
    const bf16* __restrict__ Bhg, const bf16* __restrict__ Blg,
    const float* __restrict__ bias, bf16* __restrict__ Vth, bf16* __restrict__ Vtl)
{
    extern __shared__ __align__(16) char smem[];
    const int tid = threadIdx.x, wid = tid >> 5, lane = tid & 31;
    const int row0 = blockIdx.y * 256;

    float* bs = (float*)(smem + AUX_OFF);
    if (tid < 128) bs[tid] = bias[tid];

    float acc[4][8][4];
    ZERO_ACC(acc)
    gemm_core(acc, Ahg + (size_t)row0 * DM_, Alg + (size_t)row0 * DM_, DM_,
              Bhg, Blg, DM_, DM_, smem);

    float* stg = (float*)smem;
    int b = row0 >> 11;
    int s0 = row0 & (S_ - 1);
    bf16* Vbh = Vth + (size_t)b * HD_ * S_;
    bf16* Vbl = Vtl + (size_t)b * HD_ * S_;
#pragma unroll 1
    for (int hf = 0; hf < 2; hf++) {
        stage_half(acc, stg, wid, lane, hf);
        __syncthreads();
        int s0h = s0 + hf * 128;
#pragma unroll 1
        for (int i = 0; i < 64; i++) {
            int idx = i * 256 + tid;
            int m = idx & 127, n = idx >> 7;
            float v = stg[m * 132 + n] + bs[n];
            bf16 h = __float2bfloat16_rn(v);
            bf16 l = __float2bfloat16_rn(v - __bfloat162float(h));
            Vbh[(size_t)n * S_ + s0h + m] = h;
            Vbl[(size_t)n * S_ + s0h + m] = l;
        }
        __syncthreads();
    }
}

// ---------------- scores: E = exp(scale * Q Kt) + rowsums ----------------
__global__ __launch_bounds__(256, 1) void mma_scores(
    const bf16* __restrict__ Qh, const bf16* __restrict__ Ql,
    const bf16* __restrict__ Kh, const bf16* __restrict__ Kl,
    float* __restrict__ scores, float* __restrict__ rowsum)
{
    extern __shared__ __align__(16) char smem[];
    const int tid = threadIdx.x, wid = tid >> 5, lane = tid & 31;
    const int bh = blockIdx.z;
    const int b = bh >> 4, hd = bh & 15;
    const int row0 = blockIdx.y * 256, col0 = blockIdx.x * 128;

    float acc[4][8][4];
    ZERO_ACC(acc)
    gemm_core(acc,
        Qh + ((size_t)b * S_ + row0) * DM_ + hd * HD_,
        Ql + ((size_t)b * S_ + row0) * DM_ + hd * HD_, DM_,
        Kh + ((size_t)b * S_ + col0) * HD_,
        Kl + ((size_t)b * S_ + col0) * HD_, HD_, HD_, smem);

    float* stg = (float*)smem;
#pragma unroll 1
    for (int hf = 0; hf < 2; hf++) {
        stage_half(acc, stg, wid, lane, hf);
        __syncthreads();
        float* Crow = scores + ((size_t)bh * S_ + row0 + hf * 128) * S_ + col0;
        float* rs = rowsum + (size_t)bh * S_ + row0 + hf * 128;
#pragma unroll 1
        for (int i = 0; i < 16; i++) {
            int rr = i * 8 + wid, c4 = lane * 4;
            float4 v = *(float4*)&stg[rr * 132 + c4];
            float4 e;
            e.x = __expf(v.x * SCALE_); e.y = __expf(v.y * SCALE_);
            e.z = __expf(v.z * SCALE_); e.w = __expf(v.w * SCALE_);
            *(float4*)&Crow[(size_t)rr * S_ + c4] = e;
            float s = e.x + e.y + e.z + e.w;
            s += __shfl_xor_sync(0xFFFFFFFFu, s, 1);
            s += __shfl_xor_sync(0xFFFFFFFFu, s, 2);
            s += __shfl_xor_sync(0xFFFFFFFFu, s, 4);
            s += __shfl_xor_sync(0xFFFFFFFFu, s, 8);
            s += __shfl_xor_sync(0xFFFFFFFFu, s, 16);
            if (lane == 0) atomicAdd(&rs[rr], s);
        }
        __syncthreads();
    }
}

// ---------------- normalize scores in place + PV (split epilogue) ----------------
__global__ __launch_bounds__(256, 1) void mma_softmax_pv(
    float* __restrict__ scores, const float* __restrict__ rowsum,
    const bf16* __restrict__ Vth, const bf16* __restrict__ Vtl,
    bf16* __restrict__ attnh, bf16* __restrict__ attnl)
{
    extern __shared__ __align__(16) char smem[];
    const int tid = threadIdx.x, wid = tid >> 5, lane = tid & 31;
    const int bh = blockIdx.y;
    const int b = bh >> 4, hd = bh & 15;
    const int row0 = blockIdx.x * 256;

    float* rinv = (float*)(smem + AUX_OFF);
    rinv[tid] = 1.0f / rowsum[(size_t)bh * S_ + row0 + tid];
    __syncthreads();

    float acc[4][8][4];
    ZERO_ACC(acc)
    gemm_core_pv(acc, scores + ((size_t)bh * S_ + row0) * S_, S_,
                 Vth + (size_t)b * HD_ * S_, Vtl + (size_t)b * HD_ * S_, S_,
                 S_, smem, rinv);

    float* stg = (float*)smem;
#pragma unroll 1
    for (int hf = 0; hf < 2; hf++) {
        stage_half(acc, stg, wid, lane, hf);
        __syncthreads();
        bf16* Cbh = attnh + ((size_t)b * S_ + row0 + hf * 128) * DM_ + hd * HD_;
        bf16* Cbl = attnl + ((size_t)b * S_ + row0 + hf * 128) * DM_ + hd * HD_;
#pragma unroll 1
        for (int i = 0; i < 16; i++) {
            int rr = i * 8 + wid, c4 = lane * 4;
            float4 v = *(float4*)&stg[rr * 132 + c4];
            uint32_t h0, h1, l0, l1; split4(v, h0, h1, l0, l1);
            size_t o = (size_t)rr * DM_ + c4;
            *(uint2*)(Cbh + o) = make_uint2(h0, h1);
            *(uint2*)(Cbl + o) = make_uint2(l0, l1);
        }
        __syncthreads();
    }
}

// ---------------- output GEMM (fp32 + bias epilogue) ----------------
__global__ __launch_bounds__(256, 1) void mma_out(
    const bf16* __restrict__ Ahg, const bf16* __restrict__ Alg,
    const bf16* __restrict__ Bhg, const bf16* __restrict__ Blg,
    const float* __restrict__ bias, float* __restrict__ C)
{
    extern __shared__ __align__(16) char smem[];
    const int tid = threadIdx.x, wid = tid >> 5, lane = tid & 31;
    const int row0 = blockIdx.y * 256, col0 = blockIdx.x * 128;

    float* bs = (float*)(smem + AUX_OFF);
    if (tid < 128) bs[tid] = bias[col0 + tid];

    float acc[4][8][4];
    ZERO_ACC(acc)
    gemm_core(acc, Ahg + (size_t)row0 * DM_, Alg + (size_t)row0 * DM_, DM_,
              Bhg + (size_t)col0 * DM_, Blg + (size_t)col0 * DM_, DM_, DM_, smem);

    float* stg = (float*)smem;
#pragma unroll 1
    for (int hf = 0; hf < 2; hf++) {
        stage_half(acc, stg, wid, lane, hf);
        __syncthreads();
#pragma unroll 1
        for (int i = 0; i < 16; i++) {
            int rr = i * 8 + wid, c4 = lane * 4;
            float4 v = *(float4*)&stg[rr * 132 + c4];
            v.x += bs[c4]; v.y += bs[c4 + 1]; v.z += bs[c4 + 2]; v.w += bs[c4 + 3];
            *(float4*)&C[(size_t)(row0 + hf * 128 + rr) * DM_ + col0 + c4] = v;
        }
        __syncthreads();
    }
}

// ---------------- launch ----------------
extern "C" void kernel_launch(void* const* d_in, const int* in_sizes, int n_in,
                              void* d_out, int out_size)
{
    const float* x  = (const float*)d_in[0];
    const float* Wq = (const float*)d_in[1];
    const float* bq = (const float*)d_in[2];
    const float* Wk = (const float*)d_in[3];
    const float* bk = (const float*)d_in[4];
    const float* Wv = (const float*)d_in[5];
    const float* bv = (const float*)d_in[6];
    const float* Wo = (const float*)d_in[7];
    const float* bo = (const float*)d_in[8];

    float* out = (float*)d_out;
    float* scores = out + (size_t)B_ * S_ * DM_;

    bf16 *pxh, *pxl, *pQh, *pQl, *pKh, *pKl, *pVth, *pVtl, *pAh, *pAl;
    bf16 *pWqh, *pWql, *pWkh, *pWkl, *pWvh, *pWvl, *pWoh, *pWol;
    float* pRS;
    cudaGetSymbolAddress((void**)&pxh, g_xh);   cudaGetSymbolAddress((void**)&pxl, g_xl);
    cudaGetSymbolAddress((void**)&pQh, g_Qh);   cudaGetSymbolAddress((void**)&pQl, g_Ql);
    cudaGetSymbolAddress((void**)&pKh, g_Kh);   cudaGetSymbolAddress((void**)&pKl, g_Kl);
    cudaGetSymbolAddress((void**)&pVth, g_Vth); cudaGetSymbolAddress((void**)&pVtl, g_Vtl);
    cudaGetSymbolAddress((void**)&pAh, g_attnh); cudaGetSymbolAddress((void**)&pAl, g_attnl);
    cudaGetSymbolAddress((void**)&pWqh, g_Wqh); cudaGetSymbolAddress((void**)&pWql, g_Wql);
    cudaGetSymbolAddress((void**)&pWkh, g_Wkh); cudaGetSymbolAddress((void**)&pWkl, g_Wkl);
    cudaGetSymbolAddress((void**)&pWvh, g_Wvh); cudaGetSymbolAddress((void**)&pWvl, g_Wvl);
    cudaGetSymbolAddress((void**)&pWoh, g_Woh); cudaGetSymbolAddress((void**)&pWol, g_Wol);
    cudaGetSymbolAddress((void**)&pRS, g_rowsum);

    static int smem_set = 0;
    if (!smem_set) {
        cudaFuncSetAttribute(mma_proj_split, cudaFuncAttributeMaxDynamicSharedMemorySize, SMEM_BYTES);
        cudaFuncSetAttribute(mma_vproj, cudaFuncAttributeMaxDynamicSharedMemorySize, SMEM_BYTES);
        cudaFuncSetAttribute(mma_scores, cudaFuncAttributeMaxDynamicSharedMemorySize, SMEM_BYTES);
        cudaFuncSetAttribute(mma_softmax_pv, cudaFuncAttributeMaxDynamicSharedMemorySize, SMEM_BYTES);
        cudaFuncSetAttribute(mma_out, cudaFuncAttributeMaxDynamicSharedMemorySize, SMEM_BYTES);
        smem_set = 1;
    }

    const int M = B_ * S_;   // 8192
    split_x_kernel<<<(M * DM_ / 4 + 255) / 256, 256>>>(x, pxh, pxl, M * DM_ / 4);
    transpose_split_kernel<<<dim3(DM_ / 32, DM_ / 32), dim3(32, 8)>>>(Wq, pWqh, pWql, DM_, DM_);
    transpose_split_kernel<<<dim3(HD_ / 32, DM_ / 32), dim3(32, 8)>>>(Wk, pWkh, pWkl, DM_, HD_);
    transpose_split_kernel<<<dim3(HD_ / 32, DM_ / 32), dim3(32, 8)>>>(Wv, pWvh, pWvl, DM_, HD_);
    transpose_split_kernel<<<dim3(DM_ / 32, DM_ / 32), dim3(32, 8)>>>(Wo, pWoh, pWol, DM_, DM_);
    zero_kernel<<<(B_ * H_ * S_ + 255) / 256, 256>>>(pRS, B_ * H_ * S_);

    mma_proj_split<<<dim3(DM_ / 128, M / 256), 256, SMEM_BYTES>>>(
        pxh, pxl, DM_, pWqh, pWql, DM_, bq, pQh, pQl, DM_, DM_);
    mma_proj_split<<<dim3(1, M / 256), 256, SMEM_BYTES>>>(
        pxh, pxl, DM_, pWkh, pWkl, DM_, bk, pKh, pKl, HD_, DM_);
    mma_vproj<<<dim3(1, M / 256), 256, SMEM_BYTES>>>(
        pxh, pxl, pWvh, pWvl, bv, pVth, pVtl);

    mma_scores<<<dim3(S_ / 128, S_ / 256, B_ * H_), 256, SMEM_BYTES>>>(
        pQh, pQl, pKh, pKl, scores, pRS);
    mma_softmax_pv<<<dim3(S_ / 256, B_ * H_), 256, SMEM_BYTES>>>(
        scores, pRS, pVth, pVtl, pAh, pAl);

    mma_out<<<dim3(DM_ / 128, M / 256), 256, SMEM_BYTES>>>(
        pAh, pAl, pWoh, pWol, bo, out);
}

// round 7
// speedup vs baseline: 1.3957x; 1.3957x over previous
#include <cuda_runtime.h>
#include <cuda_bf16.h>
#include <cstdint>

// Problem dims
#define B_  4
#define S_  2048
#define DM_ 2048
#define H_  16
#define HD_ 128
#define SCALE_ 0.08838834764831843f   // 1/sqrt(128)

typedef __nv_bfloat16 bf16;

// ---------------- scratch (__device__ globals) ----------------
__device__ bf16 g_xh[(size_t)B_ * S_ * DM_];
__device__ bf16 g_xl[(size_t)B_ * S_ * DM_];
__device__ bf16 g_Qh[(size_t)B_ * S_ * DM_];
__device__ bf16 g_Ql[(size_t)B_ * S_ * DM_];
__device__ bf16 g_Kh[(size_t)B_ * S_ * HD_];
__device__ bf16 g_Kl[(size_t)B_ * S_ * HD_];
__device__ bf16 g_Vth[(size_t)B_ * HD_ * S_];     // [B][128][2048]
__device__ bf16 g_Vtl[(size_t)B_ * HD_ * S_];
__device__ bf16 g_attnh[(size_t)B_ * S_ * DM_];
__device__ bf16 g_attnl[(size_t)B_ * S_ * DM_];
__device__ bf16 g_Wqh[(size_t)DM_ * DM_];         // transposed [N][K]
__device__ bf16 g_Wql[(size_t)DM_ * DM_];
__device__ bf16 g_Wkh[(size_t)HD_ * DM_];
__device__ bf16 g_Wkl[(size_t)HD_ * DM_];
__device__ bf16 g_Wvh[(size_t)HD_ * DM_];
__device__ bf16 g_Wvl[(size_t)HD_ * DM_];
__device__ bf16 g_Woh[(size_t)DM_ * DM_];
__device__ bf16 g_Wol[(size_t)DM_ * DM_];
__device__ float g_rowsum[(size_t)B_ * H_ * S_];

// ---------------- smem layout ----------------
// 2-stage pipeline. Stage = {Ah, Al, Bh, Bl}, each 128 x 40 bf16 = 10240 B.
#define TILE_B     10240
#define STAGE_BYTES (4 * TILE_B)          // 40960
#define AUX_OFF    81920
#define RED_OFF    82432
#define SMEM_BYTES 83456
#define LDT 40

// ---------------- low-level helpers ----------------
__device__ __forceinline__ uint32_t smem_u32(const void* p) {
    uint32_t a;
    asm("{ .reg .u64 t; cvta.to.shared.u64 t, %1; cvt.u32.u64 %0, t; }" : "=r"(a) : "l"(p));
    return a;
}
__device__ __forceinline__ void cp16(uint32_t s, const void* g) {
    asm volatile("cp.async.ca.shared.global [%0], [%1], 16;"
                 :: "r"(s), "l"(__cvta_generic_to_global(g)));
}
#define CP_COMMIT() asm volatile("cp.async.commit_group;" ::: "memory")
#define CP_WAIT1()  asm volatile("cp.async.wait_group 1;" ::: "memory")
__device__ __forceinline__ void ldsm4(uint32_t* r, uint32_t a) {
    asm volatile("ldmatrix.sync.aligned.m8n8.x4.shared.b16 {%0,%1,%2,%3}, [%4];"
        : "=r"(r[0]), "=r"(r[1]), "=r"(r[2]), "=r"(r[3]) : "r"(a));
}
__device__ __forceinline__ void mma_bf16(float* d, const uint32_t* a, uint32_t b0, uint32_t b1) {
    asm volatile("mma.sync.aligned.m16n8k16.row.col.f32.bf16.bf16.f32 "
        "{%0,%1,%2,%3}, {%4,%5,%6,%7}, {%8,%9}, {%0,%1,%2,%3};"
        : "+f"(d[0]), "+f"(d[1]), "+f"(d[2]), "+f"(d[3])
        : "r"(a[0]), "r"(a[1]), "r"(a[2]), "r"(a[3]), "r"(b0), "r"(b1));
}
__device__ __forceinline__ uint32_t bits2(__nv_bfloat162 h) {
    return *reinterpret_cast<uint32_t*>(&h);
}
__device__ __forceinline__ void split4(float4 v, uint32_t& h0, uint32_t& h1,
                                       uint32_t& l0, uint32_t& l1) {
    __nv_bfloat162 a = __floats2bfloat162_rn(v.x, v.y);
    __nv_bfloat162 b = __floats2bfloat162_rn(v.z, v.w);
    float2 fa = __bfloat1622float2(a);
    float2 fb = __bfloat1622float2(b);
    __nv_bfloat162 c = __floats2bfloat162_rn(v.x - fa.x, v.y - fa.y);
    __nv_bfloat162 d = __floats2bfloat162_rn(v.z - fb.x, v.w - fb.y);
    h0 = bits2(a); h1 = bits2(b); l0 = bits2(c); l1 = bits2(d);
}

// ---------------- tile movement (cp.async) ----------------
// one chunk: A 128x32 (hi+lo) + B 128x32 (hi+lo) via cp.async
__device__ __forceinline__ void issue_tiles(char* buf,
    const bf16* __restrict__ Ahg, const bf16* __restrict__ Alg, size_t lda,
    const bf16* __restrict__ Bhg, const bf16* __restrict__ Blg, size_t ldb,
    int k0, int tid)
{
    uint32_t sA = smem_u32(buf);
#pragma unroll
    for (int i = 0; i < 2; i++) {
        int idx = i * 256 + tid;            // 0..511
        int r = idx >> 2, c8 = (idx & 3) * 8;
        uint32_t d = sA + r * (LDT * 2) + c8 * 2;
        cp16(d, Ahg + (size_t)r * lda + k0 + c8);
        cp16(d + TILE_B, Alg + (size_t)r * lda + k0 + c8);
    }
    uint32_t sB = sA + 2 * TILE_B;
#pragma unroll
    for (int i = 0; i < 2; i++) {
        int idx = i * 256 + tid;
        int r = idx >> 2, c8 = (idx & 3) * 8;
        uint32_t d = sB + r * (LDT * 2) + c8 * 2;
        cp16(d, Bhg + (size_t)r * ldb + k0 + c8);
        cp16(d + TILE_B, Blg + (size_t)r * ldb + k0 + c8);
    }
}
__device__ __forceinline__ void issue_B(char* buf,
    const bf16* __restrict__ Bhg, const bf16* __restrict__ Blg, size_t ldb,
    int k0, int tid)
{
    uint32_t sB = smem_u32(buf) + 2 * TILE_B;
#pragma unroll
    for (int i = 0; i < 2; i++) {
        int idx = i * 256 + tid;
        int r = idx >> 2, c8 = (idx & 3) * 8;
        uint32_t d = sB + r * (LDT * 2) + c8 * 2;
        cp16(d, Bhg + (size_t)r * ldb + k0 + c8);
        cp16(d + TILE_B, Blg + (size_t)r * ldb + k0 + c8);
    }
}
// PV A path: load fp32 scores, normalize, write back, split to smem
__device__ __forceinline__ void fill_A_pv(char* buf, float* __restrict__ A, size_t lda,
                                          int k0, const float* __restrict__ rinv, int tid)
{
    bf16* Ah = (bf16*)buf;
    bf16* Al = (bf16*)(buf + TILE_B);
#pragma unroll
    for (int i = 0; i < 4; i++) {
        int idx = i * 256 + tid;
        int r = idx >> 3, c = (idx & 7) * 4;
        float4 v = *(float4*)(A + (size_t)r * lda + k0 + c);
        float ri = rinv[r];
        v.x *= ri; v.y *= ri; v.z *= ri; v.w *= ri;
        *(float4*)(A + (size_t)r * lda + k0 + c) = v;
        uint32_t h0, h1, l0, l1; split4(v, h0, h1, l0, l1);
        int o = r * LDT + c;
        *(uint2*)(Ah + o) = make_uint2(h0, h1);
        *(uint2*)(Al + o) = make_uint2(l0, l1);
    }
}

// ---------------- MMA compute: one 32-K chunk, warp 32x64, 3-term split ----------------
__device__ __forceinline__ void compute_chunk(float (*acc)[8][4], char* buf,
                                              int wm, int wn, int lane)
{
    bf16* Ah = (bf16*)buf;
    bf16* Al = (bf16*)(buf + TILE_B);
    bf16* Bh = (bf16*)(buf + 2 * TILE_B);
    bf16* Bl = (bf16*)(buf + 3 * TILE_B);
    const int ar = lane & 15;
    const int acs = (lane >> 4) << 3;
#pragma unroll
    for (int kk = 0; kk < 32; kk += 16) {
        const int ac = kk + acs;
        uint32_t aH[2][4], aL[2][4];
#pragma unroll
        for (int mt = 0; mt < 2; mt++) {
            ldsm4(aH[mt], smem_u32(Ah + (wm * 32 + mt * 16 + ar) * LDT + ac));
            ldsm4(aL[mt], smem_u32(Al + (wm * 32 + mt * 16 + ar) * LDT + ac));
        }
#pragma unroll
        for (int p = 0; p < 4; p++) {
            uint32_t bh[4], bl[4];
            ldsm4(bh, smem_u32(Bh + (wn * 64 + p * 16 + ar) * LDT + ac));
            ldsm4(bl, smem_u32(Bl + (wn * 64 + p * 16 + ar) * LDT + ac));
#pragma unroll
            for (int mt = 0; mt < 2; mt++) {
                mma_bf16(acc[mt][2 * p],     aH[mt], bh[0], bh[2]);
                mma_bf16(acc[mt][2 * p + 1], aH[mt], bh[1], bh[3]);
                mma_bf16(acc[mt][2 * p],     aH[mt], bl[0], bl[2]);
                mma_bf16(acc[mt][2 * p + 1], aH[mt], bl[1], bl[3]);
                mma_bf16(acc[mt][2 * p],     aL[mt], bh[0], bh[2]);
                mma_bf16(acc[mt][2 * p + 1], aL[mt], bh[1], bh[3]);
            }
        }
    }
}

// generic pipelined core
__device__ __forceinline__ void gemm_core_bf(float (*acc)[8][4],
    const bf16* __restrict__ Ahg, const bf16* __restrict__ Alg, size_t lda,
    const bf16* __restrict__ Bhg, const bf16* __restrict__ Blg, size_t ldb,
    int Kdim, char* smem)
{
    const int tid = threadIdx.x, wid = tid >> 5, lane = tid & 31;
    const int wm = wid & 3, wn = wid >> 2;
    const int nC = Kdim >> 5;
    issue_tiles(smem, Ahg, Alg, lda, Bhg, Blg, ldb, 0, tid); CP_COMMIT();
    issue_tiles(smem + STAGE_BYTES, Ahg, Alg, lda, Bhg, Blg, ldb, 32, tid); CP_COMMIT();
#pragma unroll 1
    for (int c = 0; c < nC; c++) {
        char* buf = smem + (c & 1) * STAGE_BYTES;
        CP_WAIT1();
        __syncthreads();
        compute_chunk(acc, buf, wm, wn, lane);
        __syncthreads();
        if (c + 2 < nC)
            issue_tiles(buf, Ahg, Alg, lda, Bhg, Blg, ldb, (c + 2) * 32, tid);
        CP_COMMIT();
    }
    asm volatile("cp.async.wait_all;" ::: "memory");
    __syncthreads();
}

// PV pipelined core (A = fp32 scores, normalized in place)
__device__ __forceinline__ void gemm_core_pv(float (*acc)[8][4],
    float* __restrict__ A, size_t lda,
    const bf16* __restrict__ Bhg, const bf16* __restrict__ Blg, size_t ldb,
    int Kdim, char* smem, const float* __restrict__ rinv)
{
    const int tid = threadIdx.x, wid = tid >> 5, lane = tid & 31;
    const int wm = wid & 3, wn = wid >> 2;
    const int nC = Kdim >> 5;
    issue_B(smem, Bhg, Blg, ldb, 0, tid); CP_COMMIT();
    issue_B(smem + STAGE_BYTES, Bhg, Blg, ldb, 32, tid); CP_COMMIT();
#pragma unroll 1
    for (int c = 0; c < nC; c++) {
        char* buf = smem + (c & 1) * STAGE_BYTES;
        CP_WAIT1();
        fill_A_pv(buf, A, lda, c * 32, rinv, tid);
        __syncthreads();
        compute_chunk(acc, buf, wm, wn, lane);
        __syncthreads();
        if (c + 2 < nC)
            issue_B(buf, Bhg, Blg, ldb, (c + 2) * 32, tid);
        CP_COMMIT();
    }
    asm volatile("cp.async.wait_all;" ::: "memory");
    __syncthreads();
}

// stage acc (fp32) into smem [128][132]
__device__ __forceinline__ void stage_acc(float (*acc)[8][4], float* stg, int wid, int lane) {
    int wm = wid & 3, wn = wid >> 2;
    int r0 = wm * 32 + (lane >> 2), c0 = wn * 64 + (lane & 3) * 2;
#pragma unroll
    for (int mt = 0; mt < 2; mt++)
#pragma unroll
        for (int nt = 0; nt < 8; nt++) {
            int r = r0 + mt * 16, c = c0 + nt * 8;
            *(float2*)&stg[r * 132 + c] = make_float2(acc[mt][nt][0], acc[mt][nt][1]);
            *(float2*)&stg[(r + 8) * 132 + c] = make_float2(acc[mt][nt][2], acc[mt][nt][3]);
        }
}

#define ZERO_ACC(acc) \
    _Pragma("unroll") for (int i_ = 0; i_ < 2; i_++) \
    _Pragma("unroll") for (int j_ = 0; j_ < 8; j_++) \
    _Pragma("unroll") for (int q_ = 0; q_ < 4; q_++) acc[i_][j_][q_] = 0.0f;

// ---------------- prep kernels ----------------
__global__ void split_x_kernel(const float* __restrict__ x, bf16* __restrict__ xh,
                               bf16* __restrict__ xl, int n4) {
    int i = blockIdx.x * blockDim.x + threadIdx.x;
    if (i >= n4) return;
    float4 v = *(const float4*)(x + 4 * (size_t)i);
    uint32_t h0, h1, l0, l1; split4(v, h0, h1, l0, l1);
    *(uint2*)(xh + 4 * (size_t)i) = make_uint2(h0, h1);
    *(uint2*)(xl + 4 * (size_t)i) = make_uint2(l0, l1);
}
__global__ void transpose_split_kernel(const float* __restrict__ src,
                                       bf16* __restrict__ dh, bf16* __restrict__ dl,
                                       int M, int N) {
    __shared__ float t[32][33];
    int bx = blockIdx.x * 32, by = blockIdx.y * 32;
    int x = threadIdx.x, y0 = threadIdx.y;
#pragma unroll
    for (int j = 0; j < 32; j += 8)
        t[y0 + j][x] = src[(size_t)(by + y0 + j) * N + bx + x];
    __syncthreads();
#pragma unroll
    for (int j = 0; j < 32; j += 8) {
        float v = t[x][y0 + j];
        bf16 h = __float2bfloat16_rn(v);
        bf16 l = __float2bfloat16_rn(v - __bfloat162float(h));
        size_t o = (size_t)(bx + y0 + j) * M + by + x;
        dh[o] = h; dl[o] = l;
    }
}
__global__ void zero_kernel(float* p, int n) {
    int i = blockIdx.x * blockDim.x + threadIdx.x;
    if (i < n) p[i] = 0.0f;
}

// ---------------- proj GEMM, split epilogue ----------------
__global__ __launch_bounds__(256, 2) void mma_proj_split(
    const bf16* __restrict__ Ahg, const bf16* __restrict__ Alg, size_t lda,
    const bf16* __restrict__ Bhg, const bf16* __restrict__ Blg, size_t ldb,
    const float* __restrict__ bias,
    bf16* __restrict__ Ch, bf16* __restrict__ Cl, size_t ldc, int Kdim)
{
    extern __shared__ __align__(16) char smem[];
    const int tid = threadIdx.x, wid = tid >> 5, lane = tid & 31;
    const int row0 = blockIdx.y * 128, col0 = blockIdx.x * 128;

    float* bs = (float*)(smem + AUX_OFF);
    if (tid < 128) bs[tid] = bias[col0 + tid];

    float acc[2][8][4];
    ZERO_ACC(acc)
    gemm_core_bf(acc, Ahg + (size_t)row0 * lda, Alg + (size_t)row0 * lda, lda,
                 Bhg + (size_t)col0 * ldb, Blg + (size_t)col0 * ldb, ldb, Kdim, smem);

    float* stg = (float*)smem;
    stage_acc(acc, stg, wid, lane);
    __syncthreads();
#pragma unroll 1
    for (int i = 0; i < 16; i++) {
        int idx = i * 256 + tid;
        int rr = idx >> 5, c4 = (idx & 31) << 2;
        float4 v = *(float4*)&stg[rr * 132 + c4];
        v.x += bs[c4]; v.y += bs[c4 + 1]; v.z += bs[c4 + 2]; v.w += bs[c4 + 3];
        uint32_t h0, h1, l0, l1; split4(v, h0, h1, l0, l1);
        size_t o = (size_t)(row0 + rr) * ldc + col0 + c4;
        *(uint2*)(Ch + o) = make_uint2(h0, h1);
        *(uint2*)(Cl + o) = make_uint2(l0, l1);
    }
}

// ---------------- V projection, transposed split epilogue ----------------
__global__ __launch_bounds__(256, 2) void mma_vproj(
    const bf16* __restrict__ Ahg, const bf16* __restrict__ Alg,
    const bf16* __restrict__ Bhg, const bf16* __restrict__ Blg,
    const float* __restrict__ bias, bf16* __restrict__ Vth, bf16* __restrict__ Vtl)
{
    extern __shared__ __align__(16) char smem[];
    const int tid = threadIdx.x, wid = tid >> 5, lane = tid & 31;
    const int row0 = blockIdx.y * 128;

    float* bs = (float*)(smem + AUX_OFF);
    if (tid < 128) bs[tid] = bias[tid];

    float acc[2][8][4];
    ZERO_ACC(acc)
    gemm_core_bf(acc, Ahg + (size_t)row0 * DM_, Alg + (size_t)row0 * DM_, DM_,
                 Bhg, Blg, DM_, DM_, smem);

    float* stg = (float*)smem;
    stage_acc(acc, stg, wid, lane);
    __syncthreads();
    int b = row0 >> 11;
    int s0 = row0 & (S_ - 1);
    bf16* Vbh = Vth + (size_t)b * HD_ * S_;
    bf16* Vbl = Vtl + (size_t)b * HD_ * S_;
#pragma unroll 1
    for (int i = 0; i < 64; i++) {
        int idx = i * 256 + tid;
        int m = idx & 127, n = idx >> 7;
        float v = stg[m * 132 + n] + bs[n];
        bf16 h = __float2bfloat16_rn(v);
        bf16 l = __float2bfloat16_rn(v - __bfloat162float(h));
        Vbh[(size_t)n * S_ + s0 + m] = h;
        Vbl[(size_t)n * S_ + s0 + m] = l;
    }
}

// ---------------- scores: E = exp(scale * Q Kt) + rowsums ----------------
__global__ __launch_bounds__(256, 2) void mma_scores(
    const bf16* __restrict__ Qh, const bf16* __restrict__ Ql,
    const bf16* __restrict__ Kh, const bf16* __restrict__ Kl,
    float* __restrict__ scores, float* __restrict__ rowsum)
{
    extern __shared__ __align__(16) char smem[];
    const int tid = threadIdx.x, wid = tid >> 5, lane = tid & 31;
    const int bh = blockIdx.z;
    const int b = bh >> 4, hd = bh & 15;
    const int row0 = blockIdx.y * 128, col0 = blockIdx.x * 128;

    float acc[2][8][4];
    ZERO_ACC(acc)
    gemm_core_bf(acc,
        Qh + ((size_t)b * S_ + row0) * DM_ + hd * HD_,
        Ql + ((size_t)b * S_ + row0) * DM_ + hd * HD_, DM_,
        Kh + ((size_t)b * S_ + col0) * HD_,
        Kl + ((size_t)b * S_ + col0) * HD_, HD_, HD_, smem);

    float* stg = (float*)smem;
    float* red = (float*)(smem + RED_OFF);
    const int wm = wid & 3, wn = wid >> 2;
    const int r0 = wm * 32 + (lane >> 2), c0 = wn * 64 + (lane & 3) * 2;
    float sums[2][2] = {{0.f, 0.f}, {0.f, 0.f}};
#pragma unroll
    for (int mt = 0; mt < 2; mt++)
#pragma unroll
        for (int nt = 0; nt < 8; nt++) {
            float e0 = __expf(acc[mt][nt][0] * SCALE_);
            float e1 = __expf(acc[mt][nt][1] * SCALE_);
            float e2 = __expf(acc[mt][nt][2] * SCALE_);
            float e3 = __expf(acc[mt][nt][3] * SCALE_);
            int r = r0 + mt * 16, c = c0 + nt * 8;
            *(float2*)&stg[r * 132 + c] = make_float2(e0, e1);
            *(float2*)&stg[(r + 8) * 132 + c] = make_float2(e2, e3);
            sums[mt][0] += e0 + e1;
            sums[mt][1] += e2 + e3;
        }
#pragma unroll
    for (int mt = 0; mt < 2; mt++)
#pragma unroll
        for (int hh = 0; hh < 2; hh++) {
            float v = sums[mt][hh];
            v += __shfl_xor_sync(0xFFFFFFFFu, v, 1);
            v += __shfl_xor_sync(0xFFFFFFFFu, v, 2);
            sums[mt][hh] = v;
        }
    if ((lane & 3) == 0) {
#pragma unroll
        for (int mt = 0; mt < 2; mt++)
#pragma unroll
            for (int hh = 0; hh < 2; hh++)
                red[(wm * 32 + mt * 16 + hh * 8 + (lane >> 2)) * 2 + wn] = sums[mt][hh];
    }
    __syncthreads();
    if (tid < 128)
        atomicAdd(&rowsum[(size_t)bh * S_ + row0 + tid], red[tid * 2] + red[tid * 2 + 1]);

    float* Crow = scores + ((size_t)bh * S_ + row0) * S_ + col0;
#pragma unroll 1
    for (int i = 0; i < 16; i++) {
        int idx = i * 256 + tid;
        int rr = idx >> 5, c4 = (idx & 31) << 2;
        *(float4*)&Crow[(size_t)rr * S_ + c4] = *(float4*)&stg[rr * 132 + c4];
    }
}

// ---------------- normalize scores in place + PV (split epilogue) ----------------
__global__ __launch_bounds__(256, 2) void mma_softmax_pv(
    float* __restrict__ scores, const float* __restrict__ rowsum,
    const bf16* __restrict__ Vth, const bf16* __restrict__ Vtl,
    bf16* __restrict__ attnh, bf16* __restrict__ attnl)
{
    extern __shared__ __align__(16) char smem[];
    const int tid = threadIdx.x, wid = tid >> 5, lane = tid & 31;
    const int bh = blockIdx.y;
    const int b = bh >> 4, hd = bh & 15;
    const int row0 = blockIdx.x * 128;

    float* rinv = (float*)(smem + AUX_OFF);
    if (tid < 128) rinv[tid] = 1.0f / rowsum[(size_t)bh * S_ + row0 + tid];
    __syncthreads();

    float acc[2][8][4];
    ZERO_ACC(acc)
    gemm_core_pv(acc, scores + ((size_t)bh * S_ + row0) * S_, S_,
                 Vth + (size_t)b * HD_ * S_, Vtl + (size_t)b * HD_ * S_, S_,
                 S_, smem, rinv);

    float* stg = (float*)smem;
    stage_acc(acc, stg, wid, lane);
    __syncthreads();
    bf16* Cbh = attnh + ((size_t)b * S_ + row0) * DM_ + hd * HD_;
    bf16* Cbl = attnl + ((size_t)b * S_ + row0) * DM_ + hd * HD_;
#pragma unroll 1
    for (int i = 0; i < 16; i++) {
        int idx = i * 256 + tid;
        int rr = idx >> 5, c4 = (idx & 31) << 2;
        float4 v = *(float4*)&stg[rr * 132 + c4];
        uint32_t h0, h1, l0, l1; split4(v, h0, h1, l0, l1);
        size_t o = (size_t)rr * DM_ + c4;
        *(uint2*)(Cbh + o) = make_uint2(h0, h1);
        *(uint2*)(Cbl + o) = make_uint2(l0, l1);
    }
}

// ---------------- output GEMM (fp32 + bias epilogue) ----------------
__global__ __launch_bounds__(256, 2) void mma_out(
    const bf16* __restrict__ Ahg, const bf16* __restrict__ Alg,
    const bf16* __restrict__ Bhg, const bf16* __restrict__ Blg,
    const float* __restrict__ bias, float* __restrict__ C)
{
    extern __shared__ __align__(16) char smem[];
    const int tid = threadIdx.x, wid = tid >> 5, lane = tid & 31;
    const int row0 = blockIdx.y * 128, col0 = blockIdx.x * 128;

    float* bs = (float*)(smem + AUX_OFF);
    if (tid < 128) bs[tid] = bias[col0 + tid];

    float acc[2][8][4];
    ZERO_ACC(acc)
    gemm_core_bf(acc, Ahg + (size_t)row0 * DM_, Alg + (size_t)row0 * DM_, DM_,
                 Bhg + (size_t)col0 * DM_, Blg + (size_t)col0 * DM_, DM_, DM_, smem);

    float* stg = (float*)smem;
    stage_acc(acc, stg, wid, lane);
    __syncthreads();
#pragma unroll 1
    for (int i = 0; i < 16; i++) {
        int idx = i * 256 + tid;
        int rr = idx >> 5, c4 = (idx & 31) << 2;
        float4 v = *(float4*)&stg[rr * 132 + c4];
        v.x += bs[c4]; v.y += bs[c4 + 1]; v.z += bs[c4 + 2]; v.w += bs[c4 + 3];
        *(float4*)&C[(size_t)(row0 + rr) * DM_ + col0 + c4] = v;
    }
}

// ---------------- launch ----------------
extern "C" void kernel_launch(void* const* d_in, const int* in_sizes, int n_in,
                              void* d_out, int out_size)
{
    const float* x  = (const float*)d_in[0];
    const float* Wq = (const float*)d_in[1];
    const float* bq = (const float*)d_in[2];
    const float* Wk = (const float*)d_in[3];
    const float* bk = (const float*)d_in[4];
    const float* Wv = (const float*)d_in[5];
    const float* bv = (const float*)d_in[6];
    const float* Wo = (const float*)d_in[7];
    const float* bo = (const float*)d_in[8];

    float* out = (float*)d_out;
    float* scores = out + (size_t)B_ * S_ * DM_;

    bf16 *pxh, *pxl, *pQh, *pQl, *pKh, *pKl, *pVth, *pVtl, *pAh, *pAl;
    bf16 *pWqh, *pWql, *pWkh, *pWkl, *pWvh, *pWvl, *pWoh, *pWol;
    float* pRS;
    cudaGetSymbolAddress((void**)&pxh, g_xh);   cudaGetSymbolAddress((void**)&pxl, g_xl);
    cudaGetSymbolAddress((void**)&pQh, g_Qh);   cudaGetSymbolAddress((void**)&pQl, g_Ql);
    cudaGetSymbolAddress((void**)&pKh, g_Kh);   cudaGetSymbolAddress((void**)&pKl, g_Kl);
    cudaGetSymbolAddress((void**)&pVth, g_Vth); cudaGetSymbolAddress((void**)&pVtl, g_Vtl);
    cudaGetSymbolAddress((void**)&pAh, g_attnh); cudaGetSymbolAddress((void**)&pAl, g_attnl);
    cudaGetSymbolAddress((void**)&pWqh, g_Wqh); cudaGetSymbolAddress((void**)&pWql, g_Wql);
    cudaGetSymbolAddress((void**)&pWkh, g_Wkh); cudaGetSymbolAddress((void**)&pWkl, g_Wkl);
    cudaGetSymbolAddress((void**)&pWvh, g_Wvh); cudaGetSymbolAddress((void**)&pWvl, g_Wvl);
    cudaGetSymbolAddress((void**)&pWoh, g_Woh); cudaGetSymbolAddress((void**)&pWol, g_Wol);
    cudaGetSymbolAddress((void**)&pRS, g_rowsum);

    static int smem_set = 0;
    if (!smem_set) {
        cudaFuncSetAttribute(mma_proj_split, cudaFuncAttributeMaxDynamicSharedMemorySize, SMEM_BYTES);
        cudaFuncSetAttribute(mma_vproj, cudaFuncAttributeMaxDynamicSharedMemorySize, SMEM_BYTES);
        cudaFuncSetAttribute(mma_scores, cudaFuncAttributeMaxDynamicSharedMemorySize, SMEM_BYTES);
        cudaFuncSetAttribute(mma_softmax_pv, cudaFuncAttributeMaxDynamicSharedMemorySize, SMEM_BYTES);
        cudaFuncSetAttribute(mma_out, cudaFuncAttributeMaxDynamicSharedMemorySize, SMEM_BYTES);
        smem_set = 1;
    }

    const int M = B_ * S_;   // 8192
    split_x_kernel<<<(M * DM_ / 4 + 255) / 256, 256>>>(x, pxh, pxl, M * DM_ / 4);
    transpose_split_kernel<<<dim3(DM_ / 32, DM_ / 32), dim3(32, 8)>>>(Wq, pWqh, pWql, DM_, DM_);
    transpose_split_kernel<<<dim3(HD_ / 32, DM_ / 32), dim3(32, 8)>>>(Wk, pWkh, pWkl, DM_, HD_);
    transpose_split_kernel<<<dim3(HD_ / 32, DM_ / 32), dim3(32, 8)>>>(Wv, pWvh, pWvl, DM_, HD_);
    transpose_split_kernel<<<dim3(DM_ / 32, DM_ / 32), dim3(32, 8)>>>(Wo, pWoh, pWol, DM_, DM_);
    zero_kernel<<<(B_ * H_ * S_ + 255) / 256, 256>>>(pRS, B_ * H_ * S_);

    mma_proj_split<<<dim3(DM_ / 128, M / 128), 256, SMEM_BYTES>>>(
        pxh, pxl, DM_, pWqh, pWql, DM_, bq, pQh, pQl, DM_, DM_);
    mma_proj_split<<<dim3(1, M / 128), 256, SMEM_BYTES>>>(
        pxh, pxl, DM_, pWkh, pWkl, DM_, bk, pKh, pKl, HD_, DM_);
    mma_vproj<<<dim3(1, M / 128), 256, SMEM_BYTES>>>(
        pxh, pxl, pWvh, pWvl, bv, pVth, pVtl);

    mma_scores<<<dim3(S_ / 128, S_ / 128, B_ * H_), 256, SMEM_BYTES>>>(
        pQh, pQl, pKh, pKl, scores, pRS);
    mma_softmax_pv<<<dim3(S_ / 128, B_ * H_), 256, SMEM_BYTES>>>(
        scores, pRS, pVth, pVtl, pAh, pAl);

    mma_out<<<dim3(DM_ / 128, M / 128), 256, SMEM_BYTES>>>(
        pAh, pAl, pWoh, pWol, bo, out);
}

// round 8
// speedup vs baseline: 1.8825x; 1.3488x over previous
#include <cuda_runtime.h>
#include <cuda_fp16.h>
#include <cstdint>

// Problem dims
#define B_  4
#define S_  2048
#define DM_ 2048
#define H_  16
#define HD_ 128
#define SCALE_ 0.08838834764831843f   // 1/sqrt(128)

typedef __half h16;

// ---------------- scratch (__device__ globals) ----------------
__device__ h16 g_xh[(size_t)B_ * S_ * DM_];       // A-side: single fp16
__device__ h16 g_Qh[(size_t)B_ * S_ * DM_];       // A-side: single fp16
__device__ h16 g_Kh[(size_t)B_ * S_ * HD_];       // B-side: hi+lo
__device__ h16 g_Kl[(size_t)B_ * S_ * HD_];
__device__ h16 g_Vth[(size_t)B_ * HD_ * S_];      // B-side: hi+lo, [B][128][2048]
__device__ h16 g_Vtl[(size_t)B_ * HD_ * S_];
__device__ h16 g_attnh[(size_t)B_ * S_ * DM_];    // A-side: single fp16
__device__ h16 g_Wqh[(size_t)DM_ * DM_];          // B-side (transposed [N][K]): hi+lo
__device__ h16 g_Wql[(size_t)DM_ * DM_];
__device__ h16 g_Wkh[(size_t)HD_ * DM_];
__device__ h16 g_Wkl[(size_t)HD_ * DM_];
__device__ h16 g_Wvh[(size_t)HD_ * DM_];
__device__ h16 g_Wvl[(size_t)HD_ * DM_];
__device__ h16 g_Woh[(size_t)DM_ * DM_];
__device__ h16 g_Wol[(size_t)DM_ * DM_];
__device__ float g_rowsum[(size_t)B_ * H_ * S_];

// ---------------- smem layout ----------------
// 2-stage pipeline; stage = {A, Bh, Bl}, each 128 x 40 fp16 = 10240 B.
#define TILE_B     10240
#define STAGE_BYTES (3 * TILE_B)          // 30720; 2 stages = 61440
#define AUX_OFF    67584                  // after fp32 staging 128x132x4
#define RED_OFF    68096
#define SMEM_BYTES 69632
#define LDT 40

// ---------------- low-level helpers ----------------
__device__ __forceinline__ uint32_t smem_u32(const void* p) {
    uint32_t a;
    asm("{ .reg .u64 t; cvta.to.shared.u64 t, %1; cvt.u32.u64 %0, t; }" : "=r"(a) : "l"(p));
    return a;
}
__device__ __forceinline__ void cp16(uint32_t s, const void* g) {
    asm volatile("cp.async.ca.shared.global [%0], [%1], 16;"
                 :: "r"(s), "l"(__cvta_generic_to_global(g)));
}
#define CP_COMMIT() asm volatile("cp.async.commit_group;" ::: "memory")
#define CP_WAIT1()  asm volatile("cp.async.wait_group 1;" ::: "memory")
__device__ __forceinline__ void ldsm4(uint32_t* r, uint32_t a) {
    asm volatile("ldmatrix.sync.aligned.m8n8.x4.shared.b16 {%0,%1,%2,%3}, [%4];"
        : "=r"(r[0]), "=r"(r[1]), "=r"(r[2]), "=r"(r[3]) : "r"(a));
}
__device__ __forceinline__ void mma_fp16(float* d, const uint32_t* a, uint32_t b0, uint32_t b1) {
    asm volatile("mma.sync.aligned.m16n8k16.row.col.f32.f16.f16.f32 "
        "{%0,%1,%2,%3}, {%4,%5,%6,%7}, {%8,%9}, {%0,%1,%2,%3};"
        : "+f"(d[0]), "+f"(d[1]), "+f"(d[2]), "+f"(d[3])
        : "r"(a[0]), "r"(a[1]), "r"(a[2]), "r"(a[3]), "r"(b0), "r"(b1));
}
__device__ __forceinline__ uint32_t hbits2(__half2 h) {
    return *reinterpret_cast<uint32_t*>(&h);
}
// fp32x4 -> fp16 hi pair + fp16 lo pair
__device__ __forceinline__ void split4h(float4 v, uint32_t& h0, uint32_t& h1,
                                        uint32_t& l0, uint32_t& l1) {
    __half2 a = __floats2half2_rn(v.x, v.y);
    __half2 b = __floats2half2_rn(v.z, v.w);
    float2 fa = __half22float2(a);
    float2 fb = __half22float2(b);
    __half2 c = __floats2half2_rn(v.x - fa.x, v.y - fa.y);
    __half2 d = __floats2half2_rn(v.z - fb.x, v.w - fb.y);
    h0 = hbits2(a); h1 = hbits2(b); l0 = hbits2(c); l1 = hbits2(d);
}
__device__ __forceinline__ void pack4h(float4 v, uint32_t& h0, uint32_t& h1) {
    __half2 a = __floats2half2_rn(v.x, v.y);
    __half2 b = __floats2half2_rn(v.z, v.w);
    h0 = hbits2(a); h1 = hbits2(b);
}

// ---------------- tile movement (cp.async) ----------------
// one chunk: A 128x32 (single) + B 128x32 (hi+lo)
__device__ __forceinline__ void issue_tiles(char* buf,
    const h16* __restrict__ Ag, size_t lda,
    const h16* __restrict__ Bhg, const h16* __restrict__ Blg, size_t ldb,
    int k0, int tid)
{
    uint32_t sA = smem_u32(buf);
#pragma unroll
    for (int i = 0; i < 2; i++) {
        int idx = i * 256 + tid;            // 0..511
        int r = idx >> 2, c8 = (idx & 3) * 8;
        cp16(sA + r * (LDT * 2) + c8 * 2, Ag + (size_t)r * lda + k0 + c8);
    }
    uint32_t sB = sA + TILE_B;
#pragma unroll
    for (int i = 0; i < 2; i++) {
        int idx = i * 256 + tid;
        int r = idx >> 2, c8 = (idx & 3) * 8;
        uint32_t d = sB + r * (LDT * 2) + c8 * 2;
        cp16(d, Bhg + (size_t)r * ldb + k0 + c8);
        cp16(d + TILE_B, Blg + (size_t)r * ldb + k0 + c8);
    }
}
__device__ __forceinline__ void issue_B(char* buf,
    const h16* __restrict__ Bhg, const h16* __restrict__ Blg, size_t ldb,
    int k0, int tid)
{
    uint32_t sB = smem_u32(buf) + TILE_B;
#pragma unroll
    for (int i = 0; i < 2; i++) {
        int idx = i * 256 + tid;
        int r = idx >> 2, c8 = (idx & 3) * 8;
        uint32_t d = sB + r * (LDT * 2) + c8 * 2;
        cp16(d, Bhg + (size_t)r * ldb + k0 + c8);
        cp16(d + TILE_B, Blg + (size_t)r * ldb + k0 + c8);
    }
}
// PV A path: load fp32 scores, normalize, write back, single-fp16 to smem
__device__ __forceinline__ void fill_A_pv(char* buf, float* __restrict__ A, size_t lda,
                                          int k0, const float* __restrict__ rinv, int tid)
{
    h16* Ah = (h16*)buf;
#pragma unroll
    for (int i = 0; i < 4; i++) {
        int idx = i * 256 + tid;
        int r = idx >> 3, c = (idx & 7) * 4;
        float4 v = *(float4*)(A + (size_t)r * lda + k0 + c);
        float ri = rinv[r];
        v.x *= ri; v.y *= ri; v.z *= ri; v.w *= ri;
        *(float4*)(A + (size_t)r * lda + k0 + c) = v;
        uint32_t h0, h1; pack4h(v, h0, h1);
        *(uint2*)(Ah + r * LDT + c) = make_uint2(h0, h1);
    }
}

// ---------------- MMA compute: one 32-K chunk, warp 32x64, 2-term fp16 ----------------
__device__ __forceinline__ void compute_chunk(float (*acc)[8][4], char* buf,
                                              int wm, int wn, int lane)
{
    h16* Ah = (h16*)buf;
    h16* Bh = (h16*)(buf + TILE_B);
    h16* Bl = (h16*)(buf + 2 * TILE_B);
    const int ar = lane & 15;
    const int acs = (lane >> 4) << 3;
#pragma unroll
    for (int kk = 0; kk < 32; kk += 16) {
        const int ac = kk + acs;
        uint32_t aH[2][4];
#pragma unroll
        for (int mt = 0; mt < 2; mt++)
            ldsm4(aH[mt], smem_u32(Ah + (wm * 32 + mt * 16 + ar) * LDT + ac));
#pragma unroll
        for (int p = 0; p < 4; p++) {
            uint32_t bh[4], bl[4];
            ldsm4(bh, smem_u32(Bh + (wn * 64 + p * 16 + ar) * LDT + ac));
            ldsm4(bl, smem_u32(Bl + (wn * 64 + p * 16 + ar) * LDT + ac));
#pragma unroll
            for (int mt = 0; mt < 2; mt++) {
                mma_fp16(acc[mt][2 * p],     aH[mt], bh[0], bh[2]);
                mma_fp16(acc[mt][2 * p + 1], aH[mt], bh[1], bh[3]);
                mma_fp16(acc[mt][2 * p],     aH[mt], bl[0], bl[2]);
                mma_fp16(acc[mt][2 * p + 1], aH[mt], bl[1], bl[3]);
            }
        }
    }
}

// generic pipelined core (A single fp16, B hi+lo)
__device__ __forceinline__ void gemm_core_h(float (*acc)[8][4],
    const h16* __restrict__ Ag, size_t lda,
    const h16* __restrict__ Bhg, const h16* __restrict__ Blg, size_t ldb,
    int Kdim, char* smem)
{
    const int tid = threadIdx.x, wid = tid >> 5, lane = tid & 31;
    const int wm = wid & 3, wn = wid >> 2;
    const int nC = Kdim >> 5;
    issue_tiles(smem, Ag, lda, Bhg, Blg, ldb, 0, tid); CP_COMMIT();
    issue_tiles(smem + STAGE_BYTES, Ag, lda, Bhg, Blg, ldb, 32, tid); CP_COMMIT();
#pragma unroll 1
    for (int c = 0; c < nC; c++) {
        char* buf = smem + (c & 1) * STAGE_BYTES;
        CP_WAIT1();
        __syncthreads();
        compute_chunk(acc, buf, wm, wn, lane);
        __syncthreads();
        if (c + 2 < nC)
            issue_tiles(buf, Ag, lda, Bhg, Blg, ldb, (c + 2) * 32, tid);
        CP_COMMIT();
    }
    asm volatile("cp.async.wait_all;" ::: "memory");
    __syncthreads();
}

// PV pipelined core (A = fp32 scores, normalized in place, single fp16)
__device__ __forceinline__ void gemm_core_pv(float (*acc)[8][4],
    float* __restrict__ A, size_t lda,
    const h16* __restrict__ Bhg, const h16* __restrict__ Blg, size_t ldb,
    int Kdim, char* smem, const float* __restrict__ rinv)
{
    const int tid = threadIdx.x, wid = tid >> 5, lane = tid & 31;
    const int wm = wid & 3, wn = wid >> 2;
    const int nC = Kdim >> 5;
    issue_B(smem, Bhg, Blg, ldb, 0, tid); CP_COMMIT();
    issue_B(smem + STAGE_BYTES, Bhg, Blg, ldb, 32, tid); CP_COMMIT();
#pragma unroll 1
    for (int c = 0; c < nC; c++) {
        char* buf = smem + (c & 1) * STAGE_BYTES;
        CP_WAIT1();
        fill_A_pv(buf, A, lda, c * 32, rinv, tid);
        __syncthreads();
        compute_chunk(acc, buf, wm, wn, lane);
        __syncthreads();
        if (c + 2 < nC)
            issue_B(buf, Bhg, Blg, ldb, (c + 2) * 32, tid);
        CP_COMMIT();
    }
    asm volatile("cp.async.wait_all;" ::: "memory");
    __syncthreads();
}

// stage acc (fp32) into smem [128][132]
__device__ __forceinline__ void stage_acc(float (*acc)[8][4], float* stg, int wid, int lane) {
    int wm = wid & 3, wn = wid >> 2;
    int r0 = wm * 32 + (lane >> 2), c0 = wn * 64 + (lane & 3) * 2;
#pragma unroll
    for (int mt = 0; mt < 2; mt++)
#pragma unroll
        for (int nt = 0; nt < 8; nt++) {
            int r = r0 + mt * 16, c = c0 + nt * 8;
            *(float2*)&stg[r * 132 + c] = make_float2(acc[mt][nt][0], acc[mt][nt][1]);
            *(float2*)&stg[(r + 8) * 132 + c] = make_float2(acc[mt][nt][2], acc[mt][nt][3]);
        }
}

#define ZERO_ACC(acc) \
    _Pragma("unroll") for (int i_ = 0; i_ < 2; i_++) \
    _Pragma("unroll") for (int j_ = 0; j_ < 8; j_++) \
    _Pragma("unroll") for (int q_ = 0; q_ < 4; q_++) acc[i_][j_][q_] = 0.0f;

// ---------------- prep kernels ----------------
__global__ void split_x_kernel(const float* __restrict__ x, h16* __restrict__ xh, int n4) {
    int i = blockIdx.x * blockDim.x + threadIdx.x;
    if (i >= n4) return;
    float4 v = *(const float4*)(x + 4 * (size_t)i);
    uint32_t h0, h1; pack4h(v, h0, h1);
    *(uint2*)(xh + 4 * (size_t)i) = make_uint2(h0, h1);
}
__global__ void transpose_split_kernel(const float* __restrict__ src,
                                       h16* __restrict__ dh, h16* __restrict__ dl,
                                       int M, int N) {
    __shared__ float t[32][33];
    int bx = blockIdx.x * 32, by = blockIdx.y * 32;
    int x = threadIdx.x, y0 = threadIdx.y;
#pragma unroll
    for (int j = 0; j < 32; j += 8)
        t[y0 + j][x] = src[(size_t)(by + y0 + j) * N + bx + x];
    __syncthreads();
#pragma unroll
    for (int j = 0; j < 32; j += 8) {
        float v = t[x][y0 + j];
        h16 h = __float2half_rn(v);
        h16 l = __float2half_rn(v - __half2float(h));
        size_t o = (size_t)(bx + y0 + j) * M + by + x;
        dh[o] = h; dl[o] = l;
    }
}
__global__ void zero_kernel(float* p, int n) {
    int i = blockIdx.x * blockDim.x + threadIdx.x;
    if (i < n) p[i] = 0.0f;
}

// ---------------- proj GEMM; epilogue: single fp16 (Cl==nullptr) or hi/lo pair ----------------
__global__ __launch_bounds__(256, 2) void mma_proj(
    const h16* __restrict__ Ag, size_t lda,
    const h16* __restrict__ Bhg, const h16* __restrict__ Blg, size_t ldb,
    const float* __restrict__ bias,
    h16* __restrict__ Ch, h16* __restrict__ Cl, size_t ldc, int Kdim)
{
    extern __shared__ __align__(16) char smem[];
    const int tid = threadIdx.x, wid = tid >> 5, lane = tid & 31;
    const int row0 = blockIdx.y * 128, col0 = blockIdx.x * 128;

    float* bs = (float*)(smem + AUX_OFF);
    if (tid < 128) bs[tid] = bias[col0 + tid];

    float acc[2][8][4];
    ZERO_ACC(acc)
    gemm_core_h(acc, Ag + (size_t)row0 * lda, lda,
                Bhg + (size_t)col0 * ldb, Blg + (size_t)col0 * ldb, ldb, Kdim, smem);

    float* stg = (float*)smem;
    stage_acc(acc, stg, wid, lane);
    __syncthreads();
#pragma unroll 1
    for (int i = 0; i < 16; i++) {
        int idx = i * 256 + tid;
        int rr = idx >> 5, c4 = (idx & 31) << 2;
        float4 v = *(float4*)&stg[rr * 132 + c4];
        v.x += bs[c4]; v.y += bs[c4 + 1]; v.z += bs[c4 + 2]; v.w += bs[c4 + 3];
        size_t o = (size_t)(row0 + rr) * ldc + col0 + c4;
        if (Cl) {
            uint32_t h0, h1, l0, l1; split4h(v, h0, h1, l0, l1);
            *(uint2*)(Ch + o) = make_uint2(h0, h1);
            *(uint2*)(Cl + o) = make_uint2(l0, l1);
        } else {
            uint32_t h0, h1; pack4h(v, h0, h1);
            *(uint2*)(Ch + o) = make_uint2(h0, h1);
        }
    }
}

// ---------------- V projection, transposed hi/lo epilogue ----------------
__global__ __launch_bounds__(256, 2) void mma_vproj(
    const h16* __restrict__ Ag,
    const h16* __restrict__ Bhg, const h16* __restrict__ Blg,
    const float* __restrict__ bias, h16* __restrict__ Vth, h16* __restrict__ Vtl)
{
    extern __shared__ __align__(16) char smem[];
    const int tid = threadIdx.x, wid = tid >> 5, lane = tid & 31;
    const int row0 = blockIdx.y * 128;

    float* bs = (float*)(smem + AUX_OFF);
    if (tid < 128) bs[tid] = bias[tid];

    float acc[2][8][4];
    ZERO_ACC(acc)
    gemm_core_h(acc, Ag + (size_t)row0 * DM_, DM_, Bhg, Blg, DM_, DM_, smem);

    float* stg = (float*)smem;
    stage_acc(acc, stg, wid, lane);
    __syncthreads();
    int b = row0 >> 11;
    int s0 = row0 & (S_ - 1);
    h16* Vbh = Vth + (size_t)b * HD_ * S_;
    h16* Vbl = Vtl + (size_t)b * HD_ * S_;
#pragma unroll 1
    for (int i = 0; i < 64; i++) {
        int idx = i * 256 + tid;
        int m = idx & 127, n = idx >> 7;
        float v = stg[m * 132 + n] + bs[n];
        h16 h = __float2half_rn(v);
        h16 l = __float2half_rn(v - __half2float(h));
        Vbh[(size_t)n * S_ + s0 + m] = h;
        Vbl[(size_t)n * S_ + s0 + m] = l;
    }
}

// ---------------- scores: E = exp(scale * Q Kt) + rowsums ----------------
__global__ __launch_bounds__(256, 2) void mma_scores(
    const h16* __restrict__ Qh,
    const h16* __restrict__ Kh, const h16* __restrict__ Kl,
    float* __restrict__ scores, float* __restrict__ rowsum)
{
    extern __shared__ __align__(16) char smem[];
    const int tid = threadIdx.x, wid = tid >> 5, lane = tid & 31;
    const int bh = blockIdx.z;
    const int b = bh >> 4, hd = bh & 15;
    const int row0 = blockIdx.y * 128, col0 = blockIdx.x * 128;

    float acc[2][8][4];
    ZERO_ACC(acc)
    gemm_core_h(acc,
        Qh + ((size_t)b * S_ + row0) * DM_ + hd * HD_, DM_,
        Kh + ((size_t)b * S_ + col0) * HD_,
        Kl + ((size_t)b * S_ + col0) * HD_, HD_, HD_, smem);

    float* stg = (float*)smem;
    float* red = (float*)(smem + RED_OFF);
    const int wm = wid & 3, wn = wid >> 2;
    const int r0 = wm * 32 + (lane >> 2), c0 = wn * 64 + (lane & 3) * 2;
    float sums[2][2] = {{0.f, 0.f}, {0.f, 0.f}};
#pragma unroll
    for (int mt = 0; mt < 2; mt++)
#pragma unroll
        for (int nt = 0; nt < 8; nt++) {
            float e0 = __expf(acc[mt][nt][0] * SCALE_);
            float e1 = __expf(acc[mt][nt][1] * SCALE_);
            float e2 = __expf(acc[mt][nt][2] * SCALE_);
            float e3 = __expf(acc[mt][nt][3] * SCALE_);
            int r = r0 + mt * 16, c = c0 + nt * 8;
            *(float2*)&stg[r * 132 + c] = make_float2(e0, e1);
            *(float2*)&stg[(r + 8) * 132 + c] = make_float2(e2, e3);
            sums[mt][0] += e0 + e1;
            sums[mt][1] += e2 + e3;
        }
#pragma unroll
    for (int mt = 0; mt < 2; mt++)
#pragma unroll
        for (int hh = 0; hh < 2; hh++) {
            float v = sums[mt][hh];
            v += __shfl_xor_sync(0xFFFFFFFFu, v, 1);
            v += __shfl_xor_sync(0xFFFFFFFFu, v, 2);
            sums[mt][hh] = v;
        }
    if ((lane & 3) == 0) {
#pragma unroll
        for (int mt = 0; mt < 2; mt++)
#pragma unroll
            for (int hh = 0; hh < 2; hh++)
                red[(wm * 32 + mt * 16 + hh * 8 + (lane >> 2)) * 2 + wn] = sums[mt][hh];
    }
    __syncthreads();
    if (tid < 128)
        atomicAdd(&rowsum[(size_t)bh * S_ + row0 + tid], red[tid * 2] + red[tid * 2 + 1]);

    float* Crow = scores + ((size_t)bh * S_ + row0) * S_ + col0;
#pragma unroll 1
    for (int i = 0; i < 16; i++) {
        int idx = i * 256 + tid;
        int rr = idx >> 5, c4 = (idx & 31) << 2;
        *(float4*)&Crow[(size_t)rr * S_ + c4] = *(float4*)&stg[rr * 132 + c4];
    }
}

// ---------------- normalize scores in place + PV (single-fp16 epilogue) ----------------
__global__ __launch_bounds__(256, 2) void mma_softmax_pv(
    float* __restrict__ scores, const float* __restrict__ rowsum,
    const h16* __restrict__ Vth, const h16* __restrict__ Vtl,
    h16* __restrict__ attnh)
{
    extern __shared__ __align__(16) char smem[];
    const int tid = threadIdx.x, wid = tid >> 5, lane = tid & 31;
    const int bh = blockIdx.y;
    const int b = bh >> 4, hd = bh & 15;
    const int row0 = blockIdx.x * 128;

    float* rinv = (float*)(smem + AUX_OFF);
    if (tid < 128) rinv[tid] = 1.0f / rowsum[(size_t)bh * S_ + row0 + tid];
    __syncthreads();

    float acc[2][8][4];
    ZERO_ACC(acc)
    gemm_core_pv(acc, scores + ((size_t)bh * S_ + row0) * S_, S_,
                 Vth + (size_t)b * HD_ * S_, Vtl + (size_t)b * HD_ * S_, S_,
                 S_, smem, rinv);

    float* stg = (float*)smem;
    stage_acc(acc, stg, wid, lane);
    __syncthreads();
    h16* Cb = attnh + ((size_t)b * S_ + row0) * DM_ + hd * HD_;
#pragma unroll 1
    for (int i = 0; i < 16; i++) {
        int idx = i * 256 + tid;
        int rr = idx >> 5, c4 = (idx & 31) << 2;
        float4 v = *(float4*)&stg[rr * 132 + c4];
        uint32_t h0, h1; pack4h(v, h0, h1);
        *(uint2*)(Cb + (size_t)rr * DM_ + c4) = make_uint2(h0, h1);
    }
}

// ---------------- output GEMM (fp32 + bias epilogue) ----------------
__global__ __launch_bounds__(256, 2) void mma_out(
    const h16* __restrict__ Ag,
    const h16* __restrict__ Bhg, const h16* __restrict__ Blg,
    const float* __restrict__ bias, float* __restrict__ C)
{
    extern __shared__ __align__(16) char smem[];
    const int tid = threadIdx.x, wid = tid >> 5, lane = tid & 31;
    const int row0 = blockIdx.y * 128, col0 = blockIdx.x * 128;

    float* bs = (float*)(smem + AUX_OFF);
    if (tid < 128) bs[tid] = bias[col0 + tid];

    float acc[2][8][4];
    ZERO_ACC(acc)
    gemm_core_h(acc, Ag + (size_t)row0 * DM_, DM_,
                Bhg + (size_t)col0 * DM_, Blg + (size_t)col0 * DM_, DM_, DM_, smem);

    float* stg = (float*)smem;
    stage_acc(acc, stg, wid, lane);
    __syncthreads();
#pragma unroll 1
    for (int i = 0; i < 16; i++) {
        int idx = i * 256 + tid;
        int rr = idx >> 5, c4 = (idx & 31) << 2;
        float4 v = *(float4*)&stg[rr * 132 + c4];
        v.x += bs[c4]; v.y += bs[c4 + 1]; v.z += bs[c4 + 2]; v.w += bs[c4 + 3];
        *(float4*)&C[(size_t)(row0 + rr) * DM_ + col0 + c4] = v;
    }
}

// ---------------- launch ----------------
extern "C" void kernel_launch(void* const* d_in, const int* in_sizes, int n_in,
                              void* d_out, int out_size)
{
    const float* x  = (const float*)d_in[0];
    const float* Wq = (const float*)d_in[1];
    const float* bq = (const float*)d_in[2];
    const float* Wk = (const float*)d_in[3];
    const float* bk = (const float*)d_in[4];
    const float* Wv = (const float*)d_in[5];
    const float* bv = (const float*)d_in[6];
    const float* Wo = (const float*)d_in[7];
    const float* bo = (const float*)d_in[8];

    float* out = (float*)d_out;
    float* scores = out + (size_t)B_ * S_ * DM_;

    h16 *pxh, *pQh, *pKh, *pKl, *pVth, *pVtl, *pAh;
    h16 *pWqh, *pWql, *pWkh, *pWkl, *pWvh, *pWvl, *pWoh, *pWol;
    float* pRS;
    cudaGetSymbolAddress((void**)&pxh, g_xh);
    cudaGetSymbolAddress((void**)&pQh, g_Qh);
    cudaGetSymbolAddress((void**)&pKh, g_Kh);   cudaGetSymbolAddress((void**)&pKl, g_Kl);
    cudaGetSymbolAddress((void**)&pVth, g_Vth); cudaGetSymbolAddress((void**)&pVtl, g_Vtl);
    cudaGetSymbolAddress((void**)&pAh, g_attnh);
    cudaGetSymbolAddress((void**)&pWqh, g_Wqh); cudaGetSymbolAddress((void**)&pWql, g_Wql);
    cudaGetSymbolAddress((void**)&pWkh, g_Wkh); cudaGetSymbolAddress((void**)&pWkl, g_Wkl);
    cudaGetSymbolAddress((void**)&pWvh, g_Wvh); cudaGetSymbolAddress((void**)&pWvl, g_Wvl);
    cudaGetSymbolAddress((void**)&pWoh, g_Woh); cudaGetSymbolAddress((void**)&pWol, g_Wol);
    cudaGetSymbolAddress((void**)&pRS, g_rowsum);

    static int smem_set = 0;
    if (!smem_set) {
        cudaFuncSetAttribute(mma_proj, cudaFuncAttributeMaxDynamicSharedMemorySize, SMEM_BYTES);
        cudaFuncSetAttribute(mma_vproj, cudaFuncAttributeMaxDynamicSharedMemorySize, SMEM_BYTES);
        cudaFuncSetAttribute(mma_scores, cudaFuncAttributeMaxDynamicSharedMemorySize, SMEM_BYTES);
        cudaFuncSetAttribute(mma_softmax_pv, cudaFuncAttributeMaxDynamicSharedMemorySize, SMEM_BYTES);
        cudaFuncSetAttribute(mma_out, cudaFuncAttributeMaxDynamicSharedMemorySize, SMEM_BYTES);
        smem_set = 1;
    }

    const int M = B_ * S_;   // 8192
    split_x_kernel<<<(M * DM_ / 4 + 255) / 256, 256>>>(x, pxh, M * DM_ / 4);
    transpose_split_kernel<<<dim3(DM_ / 32, DM_ / 32), dim3(32, 8)>>>(Wq, pWqh, pWql, DM_, DM_);
    transpose_split_kernel<<<dim3(HD_ / 32, DM_ / 32), dim3(32, 8)>>>(Wk, pWkh, pWkl, DM_, HD_);
    transpose_split_kernel<<<dim3(HD_ / 32, DM_ / 32), dim3(32, 8)>>>(Wv, pWvh, pWvl, DM_, HD_);
    transpose_split_kernel<<<dim3(DM_ / 32, DM_ / 32), dim3(32, 8)>>>(Wo, pWoh, pWol, DM_, DM_);
    zero_kernel<<<(B_ * H_ * S_ + 255) / 256, 256>>>(pRS, B_ * H_ * S_);

    // Q: single-fp16 epilogue (Cl = nullptr). K: hi/lo epilogue.
    mma_proj<<<dim3(DM_ / 128, M / 128), 256, SMEM_BYTES>>>(
        pxh, DM_, pWqh, pWql, DM_, bq, pQh, (h16*)nullptr, DM_, DM_);
    mma_proj<<<dim3(1, M / 128), 256, SMEM_BYTES>>>(
        pxh, DM_, pWkh, pWkl, DM_, bk, pKh, pKl, HD_, DM_);
    mma_vproj<<<dim3(1, M / 128), 256, SMEM_BYTES>>>(
        pxh, pWvh, pWvl, bv, pVth, pVtl);

    mma_scores<<<dim3(S_ / 128, S_ / 128, B_ * H_), 256, SMEM_BYTES>>>(
        pQh, pKh, pKl, scores, pRS);
    mma_softmax_pv<<<dim3(S_ / 128, B_ * H_), 256, SMEM_BYTES>>>(
        scores, pRS, pVth, pVtl, pAh);

    mma_out<<<dim3(DM_ / 128, M / 128), 256, SMEM_BYTES>>>(
        pAh, pWoh, pWol, bo, out);
}

// round 9
// speedup vs baseline: 2.4106x; 1.2806x over previous
#include <cuda_runtime.h>
#include <cuda_fp16.h>
#include <cstdint>

// Problem dims
#define B_  4
#define S_  2048
#define DM_ 2048
#define H_  16
#define HD_ 128
#define SCALE_ 0.08838834764831843f   // 1/sqrt(128)

typedef __half h16;

// ---------------- scratch (__device__ globals) ----------------
__device__ h16 g_xh[(size_t)B_ * S_ * DM_];       // A-side: single fp16
__device__ h16 g_Qh[(size_t)B_ * S_ * DM_];
__device__ h16 g_Kh[(size_t)B_ * S_ * HD_];       // B-side: hi+lo
__device__ h16 g_Kl[(size_t)B_ * S_ * HD_];
__device__ h16 g_Vth[(size_t)B_ * HD_ * S_];      // [B][128][2048]
__device__ h16 g_Vtl[(size_t)B_ * HD_ * S_];
__device__ h16 g_attnh[(size_t)B_ * S_ * DM_];
__device__ h16 g_Wqh[(size_t)DM_ * DM_];          // transposed [N][K]: hi+lo
__device__ h16 g_Wql[(size_t)DM_ * DM_];
__device__ h16 g_Wkh[(size_t)HD_ * DM_];
__device__ h16 g_Wkl[(size_t)HD_ * DM_];
__device__ h16 g_Wvh[(size_t)HD_ * DM_];
__device__ h16 g_Wvl[(size_t)HD_ * DM_];
__device__ h16 g_Woh[(size_t)DM_ * DM_];
__device__ h16 g_Wol[(size_t)DM_ * DM_];
__device__ float g_rowsum[(size_t)B_ * H_ * S_];

// ---------------- smem layouts ----------------
// BK=64 cores: stage = {A, Bh, Bl}, each 128 x 72 fp16 = 18432 B
#define LDT64   72
#define TILE64  (128 * LDT64 * 2)         // 18432
#define STAGE64 (3 * TILE64)              // 55296
#define AUX64   (2 * STAGE64)             // 110592
#define RED64   (AUX64 + 512)
#define SMEM64  (AUX64 + 1536)            // 112128
// BK=32 PV core: stage = {A, Bh, Bl}, each 128 x 40 fp16 = 10240 B
#define LDT32   40
#define TILE32  10240
#define STAGE32 (3 * TILE32)              // 30720
#define AUX32   67584
#define SMEM32  69632

// ---------------- low-level helpers ----------------
__device__ __forceinline__ uint32_t smem_u32(const void* p) {
    uint32_t a;
    asm("{ .reg .u64 t; cvta.to.shared.u64 t, %1; cvt.u32.u64 %0, t; }" : "=r"(a) : "l"(p));
    return a;
}
__device__ __forceinline__ void cp16(uint32_t s, const void* g) {
    asm volatile("cp.async.ca.shared.global [%0], [%1], 16;"
                 :: "r"(s), "l"(__cvta_generic_to_global(g)));
}
#define CP_COMMIT() asm volatile("cp.async.commit_group;" ::: "memory")
#define CP_WAIT1()  asm volatile("cp.async.wait_group 1;" ::: "memory")
__device__ __forceinline__ void ldsm4(uint32_t* r, uint32_t a) {
    asm volatile("ldmatrix.sync.aligned.m8n8.x4.shared.b16 {%0,%1,%2,%3}, [%4];"
        : "=r"(r[0]), "=r"(r[1]), "=r"(r[2]), "=r"(r[3]) : "r"(a));
}
__device__ __forceinline__ void mma_fp16(float* d, const uint32_t* a, uint32_t b0, uint32_t b1) {
    asm volatile("mma.sync.aligned.m16n8k16.row.col.f32.f16.f16.f32 "
        "{%0,%1,%2,%3}, {%4,%5,%6,%7}, {%8,%9}, {%0,%1,%2,%3};"
        : "+f"(d[0]), "+f"(d[1]), "+f"(d[2]), "+f"(d[3])
        : "r"(a[0]), "r"(a[1]), "r"(a[2]), "r"(a[3]), "r"(b0), "r"(b1));
}
__device__ __forceinline__ uint32_t hbits2(__half2 h) {
    return *reinterpret_cast<uint32_t*>(&h);
}
__device__ __forceinline__ void split4h(float4 v, uint32_t& h0, uint32_t& h1,
                                        uint32_t& l0, uint32_t& l1) {
    __half2 a = __floats2half2_rn(v.x, v.y);
    __half2 b = __floats2half2_rn(v.z, v.w);
    float2 fa = __half22float2(a);
    float2 fb = __half22float2(b);
    __half2 c = __floats2half2_rn(v.x - fa.x, v.y - fa.y);
    __half2 d = __floats2half2_rn(v.z - fb.x, v.w - fb.y);
    h0 = hbits2(a); h1 = hbits2(b); l0 = hbits2(c); l1 = hbits2(d);
}
__device__ __forceinline__ void pack4h(float4 v, uint32_t& h0, uint32_t& h1) {
    __half2 a = __floats2half2_rn(v.x, v.y);
    __half2 b = __floats2half2_rn(v.z, v.w);
    h0 = hbits2(a); h1 = hbits2(b);
}

// ---------------- BK=64 tile movement ----------------
__device__ __forceinline__ void issue_tiles64(char* buf,
    const h16* __restrict__ Ag, size_t lda,
    const h16* __restrict__ Bhg, const h16* __restrict__ Blg, size_t ldb,
    int k0, int tid)
{
    uint32_t sA = smem_u32(buf);
#pragma unroll
    for (int i = 0; i < 4; i++) {
        int idx = i * 256 + tid;              // 0..1023
        int r = idx >> 3, c8 = (idx & 7) * 8;
        cp16(sA + r * (LDT64 * 2) + c8 * 2, Ag + (size_t)r * lda + k0 + c8);
    }
    uint32_t sB = sA + TILE64;
#pragma unroll
    for (int i = 0; i < 4; i++) {
        int idx = i * 256 + tid;
        int r = idx >> 3, c8 = (idx & 7) * 8;
        uint32_t d = sB + r * (LDT64 * 2) + c8 * 2;
        cp16(d, Bhg + (size_t)r * ldb + k0 + c8);
        cp16(d + TILE64, Blg + (size_t)r * ldb + k0 + c8);
    }
}
// BK=32 B-only (PV)
__device__ __forceinline__ void issue_B32(char* buf,
    const h16* __restrict__ Bhg, const h16* __restrict__ Blg, size_t ldb,
    int k0, int tid)
{
    uint32_t sB = smem_u32(buf) + TILE32;
#pragma unroll
    for (int i = 0; i < 2; i++) {
        int idx = i * 256 + tid;
        int r = idx >> 2, c8 = (idx & 3) * 8;
        uint32_t d = sB + r * (LDT32 * 2) + c8 * 2;
        cp16(d, Bhg + (size_t)r * ldb + k0 + c8);
        cp16(d + TILE32, Blg + (size_t)r * ldb + k0 + c8);
    }
}

// ---------------- MMA compute ----------------
template<int LDT, int TILE, int BK>
__device__ __forceinline__ void compute_chunk(float (*acc)[8][4], char* buf,
                                              int wm, int wn, int lane)
{
    h16* Ah = (h16*)buf;
    h16* Bh = (h16*)(buf + TILE);
    h16* Bl = (h16*)(buf + 2 * TILE);
    const int ar = lane & 15;
    const int acs = (lane >> 4) << 3;
#pragma unroll
    for (int kk = 0; kk < BK; kk += 16) {
        const int ac = kk + acs;
        uint32_t aH[2][4];
#pragma unroll
        for (int mt = 0; mt < 2; mt++)
            ldsm4(aH[mt], smem_u32(Ah + (wm * 32 + mt * 16 + ar) * LDT + ac));
#pragma unroll
        for (int p = 0; p < 4; p++) {
            uint32_t bh[4], bl[4];
            ldsm4(bh, smem_u32(Bh + (wn * 64 + p * 16 + ar) * LDT + ac));
            ldsm4(bl, smem_u32(Bl + (wn * 64 + p * 16 + ar) * LDT + ac));
#pragma unroll
            for (int mt = 0; mt < 2; mt++) {
                mma_fp16(acc[mt][2 * p],     aH[mt], bh[0], bh[2]);
                mma_fp16(acc[mt][2 * p + 1], aH[mt], bh[1], bh[3]);
                mma_fp16(acc[mt][2 * p],     aH[mt], bl[0], bl[2]);
                mma_fp16(acc[mt][2 * p + 1], aH[mt], bl[1], bl[3]);
            }
        }
    }
}

// generic BK=64 pipelined core (A single fp16, B hi+lo)
__device__ __forceinline__ void gemm_core_h(float (*acc)[8][4],
    const h16* __restrict__ Ag, size_t lda,
    const h16* __restrict__ Bhg, const h16* __restrict__ Blg, size_t ldb,
    int Kdim, char* smem)
{
    const int tid = threadIdx.x, wid = tid >> 5, lane = tid & 31;
    const int wm = wid & 3, wn = wid >> 2;
    const int nC = Kdim >> 6;
    issue_tiles64(smem, Ag, lda, Bhg, Blg, ldb, 0, tid); CP_COMMIT();
    issue_tiles64(smem + STAGE64, Ag, lda, Bhg, Blg, ldb, 64, tid); CP_COMMIT();
#pragma unroll 1
    for (int c = 0; c < nC; c++) {
        char* buf = smem + (c & 1) * STAGE64;
        CP_WAIT1();
        __syncthreads();
        compute_chunk<LDT64, TILE64, 64>(acc, buf, wm, wn, lane);
        __syncthreads();
        if (c + 2 < nC)
            issue_tiles64(buf, Ag, lda, Bhg, Blg, ldb, (c + 2) * 64, tid);
        CP_COMMIT();
    }
    asm volatile("cp.async.wait_all;" ::: "memory");
    __syncthreads();
}

// PV core: BK=32, A = fp32 scores with register double-buffer prefetch,
// normalize by rinv + write back + split to fp16 smem.
__device__ __forceinline__ void gemm_core_pv(float (*acc)[8][4],
    float* __restrict__ A, size_t lda,
    const h16* __restrict__ Bhg, const h16* __restrict__ Blg, size_t ldb,
    int Kdim, char* smem, const float* __restrict__ rinv)
{
    const int tid = threadIdx.x, wid = tid >> 5, lane = tid & 31;
    const int wm = wid & 3, wn = wid >> 2;
    const int nC = Kdim >> 5;                     // 64
    issue_B32(smem, Bhg, Blg, ldb, 0, tid); CP_COMMIT();
    issue_B32(smem + STAGE32, Bhg, Blg, ldb, 32, tid); CP_COMMIT();

    // prefetch regs: 16 floats = this thread's slice of the next A chunk
    float4 pr[4];
#pragma unroll
    for (int i = 0; i < 4; i++) {
        int idx = i * 256 + tid;
        int rr = idx >> 3, cc = (idx & 7) * 4;
        pr[i] = *(const float4*)(A + (size_t)rr * lda + cc);
    }
#pragma unroll 1
    for (int c = 0; c < nC; c++) {
        char* buf = smem + (c & 1) * STAGE32;
        CP_WAIT1();
        // consume prefetched A chunk c: normalize, write back, split to smem
        h16* Ah = (h16*)buf;
#pragma unroll
        for (int i = 0; i < 4; i++) {
            int idx = i * 256 + tid;
            int rr = idx >> 3, cc = (idx & 7) * 4;
            float ri = rinv[rr];
            float4 v = pr[i];
            v.x *= ri; v.y *= ri; v.z *= ri; v.w *= ri;
            *(float4*)(A + (size_t)rr * lda + c * 32 + cc) = v;
            uint32_t h0, h1; pack4h(v, h0, h1);
            *(uint2*)(Ah + rr * LDT32 + cc) = make_uint2(h0, h1);
        }
        // prefetch A chunk c+1 (LDG latency hidden behind compute below)
        if (c + 1 < nC) {
#pragma unroll
            for (int i = 0; i < 4; i++) {
                int idx = i * 256 + tid;
                int rr = idx >> 3, cc = (idx & 7) * 4;
                pr[i] = *(const float4*)(A + (size_t)rr * lda + (c + 1) * 32 + cc);
            }
        }
        __syncthreads();
        compute_chunk<LDT32, TILE32, 32>(acc, buf, wm, wn, lane);
        __syncthreads();
        if (c + 2 < nC)
            issue_B32(buf, Bhg, Blg, ldb, (c + 2) * 32, tid);
        CP_COMMIT();
    }
    asm volatile("cp.async.wait_all;" ::: "memory");
    __syncthreads();
}

// stage acc (fp32) into smem [128][132]
__device__ __forceinline__ void stage_acc(float (*acc)[8][4], float* stg, int wid, int lane) {
    int wm = wid & 3, wn = wid >> 2;
    int r0 = wm * 32 + (lane >> 2), c0 = wn * 64 + (lane & 3) * 2;
#pragma unroll
    for (int mt = 0; mt < 2; mt++)
#pragma unroll
        for (int nt = 0; nt < 8; nt++) {
            int r = r0 + mt * 16, c = c0 + nt * 8;
            *(float2*)&stg[r * 132 + c] = make_float2(acc[mt][nt][0], acc[mt][nt][1]);
            *(float2*)&stg[(r + 8) * 132 + c] = make_float2(acc[mt][nt][2], acc[mt][nt][3]);
        }
}

#define ZERO_ACC(acc) \
    _Pragma("unroll") for (int i_ = 0; i_ < 2; i_++) \
    _Pragma("unroll") for (int j_ = 0; j_ < 8; j_++) \
    _Pragma("unroll") for (int q_ = 0; q_ < 4; q_++) acc[i_][j_][q_] = 0.0f;

// ---------------- prep kernels ----------------
__global__ void split_x_kernel(const float* __restrict__ x, h16* __restrict__ xh, int n4) {
    int i = blockIdx.x * blockDim.x + threadIdx.x;
    if (i >= n4) return;
    float4 v = *(const float4*)(x + 4 * (size_t)i);
    uint32_t h0, h1; pack4h(v, h0, h1);
    *(uint2*)(xh + 4 * (size_t)i) = make_uint2(h0, h1);
}
__global__ void transpose_split_kernel(const float* __restrict__ src,
                                       h16* __restrict__ dh, h16* __restrict__ dl,
                                       int M, int N) {
    __shared__ float t[32][33];
    int bx = blockIdx.x * 32, by = blockIdx.y * 32;
    int x = threadIdx.x, y0 = threadIdx.y;
#pragma unroll
    for (int j = 0; j < 32; j += 8)
        t[y0 + j][x] = src[(size_t)(by + y0 + j) * N + bx + x];
    __syncthreads();
#pragma unroll
    for (int j = 0; j < 32; j += 8) {
        float v = t[x][y0 + j];
        h16 h = __float2half_rn(v);
        h16 l = __float2half_rn(v - __half2float(h));
        size_t o = (size_t)(bx + y0 + j) * M + by + x;
        dh[o] = h; dl[o] = l;
    }
}
__global__ void zero_kernel(float* p, int n) {
    int i = blockIdx.x * blockDim.x + threadIdx.x;
    if (i < n) p[i] = 0.0f;
}

// ---------------- Q projection (single-fp16 epilogue) ----------------
__global__ __launch_bounds__(256, 2) void mma_proj(
    const h16* __restrict__ Ag, size_t lda,
    const h16* __restrict__ Bhg, const h16* __restrict__ Blg, size_t ldb,
    const float* __restrict__ bias,
    h16* __restrict__ Ch, size_t ldc, int Kdim)
{
    extern __shared__ __align__(16) char smem[];
    const int tid = threadIdx.x, wid = tid >> 5, lane = tid & 31;
    const int row0 = blockIdx.y * 128, col0 = blockIdx.x * 128;

    float* bs = (float*)(smem + AUX64);
    if (tid < 128) bs[tid] = bias[col0 + tid];

    float acc[2][8][4];
    ZERO_ACC(acc)
    gemm_core_h(acc, Ag + (size_t)row0 * lda, lda,
                Bhg + (size_t)col0 * ldb, Blg + (size_t)col0 * ldb, ldb, Kdim, smem);

    float* stg = (float*)smem;
    stage_acc(acc, stg, wid, lane);
    __syncthreads();
#pragma unroll 1
    for (int i = 0; i < 16; i++) {
        int idx = i * 256 + tid;
        int rr = idx >> 5, c4 = (idx & 31) << 2;
        float4 v = *(float4*)&stg[rr * 132 + c4];
        v.x += bs[c4]; v.y += bs[c4 + 1]; v.z += bs[c4 + 2]; v.w += bs[c4 + 3];
        uint32_t h0, h1; pack4h(v, h0, h1);
        *(uint2*)(Ch + (size_t)(row0 + rr) * ldc + col0 + c4) = make_uint2(h0, h1);
    }
}

// ---------------- fused K + V projection (gridDim.z selects) ----------------
__global__ __launch_bounds__(256, 2) void mma_kvproj(
    const h16* __restrict__ Ag,
    const h16* __restrict__ Wkh, const h16* __restrict__ Wkl,
    const h16* __restrict__ Wvh, const h16* __restrict__ Wvl,
    const float* __restrict__ bk, const float* __restrict__ bv,
    h16* __restrict__ Kh, h16* __restrict__ Kl,
    h16* __restrict__ Vth, h16* __restrict__ Vtl)
{
    extern __shared__ __align__(16) char smem[];
    const int tid = threadIdx.x, wid = tid >> 5, lane = tid & 31;
    const int row0 = blockIdx.y * 128;
    const int z = blockIdx.z;                  // 0 = K, 1 = V

    const h16* Bhg = z ? Wvh : Wkh;
    const h16* Blg = z ? Wvl : Wkl;
    const float* bias = z ? bv : bk;

    float* bs = (float*)(smem + AUX64);
    if (tid < 128) bs[tid] = bias[tid];

    float acc[2][8][4];
    ZERO_ACC(acc)
    gemm_core_h(acc, Ag + (size_t)row0 * DM_, DM_, Bhg, Blg, DM_, DM_, smem);

    float* stg = (float*)smem;
    stage_acc(acc, stg, wid, lane);
    __syncthreads();
    if (z == 0) {
        // K: hi/lo, row-major [B*S, HD]
#pragma unroll 1
        for (int i = 0; i < 16; i++) {
            int idx = i * 256 + tid;
            int rr = idx >> 5, c4 = (idx & 31) << 2;
            float4 v = *(float4*)&stg[rr * 132 + c4];
            v.x += bs[c4]; v.y += bs[c4 + 1]; v.z += bs[c4 + 2]; v.w += bs[c4 + 3];
            uint32_t h0, h1, l0, l1; split4h(v, h0, h1, l0, l1);
            size_t o = (size_t)(row0 + rr) * HD_ + c4;
            *(uint2*)(Kh + o) = make_uint2(h0, h1);
            *(uint2*)(Kl + o) = make_uint2(l0, l1);
        }
    } else {
        // V: hi/lo, transposed [B][HD][S]
        int b = row0 >> 11;
        int s0 = row0 & (S_ - 1);
        h16* Vbh = Vth + (size_t)b * HD_ * S_;
        h16* Vbl = Vtl + (size_t)b * HD_ * S_;
#pragma unroll 1
        for (int i = 0; i < 64; i++) {
            int idx = i * 256 + tid;
            int m = idx & 127, n = idx >> 7;
            float v = stg[m * 132 + n] + bs[n];
            h16 h = __float2half_rn(v);
            h16 l = __float2half_rn(v - __half2float(h));
            Vbh[(size_t)n * S_ + s0 + m] = h;
            Vbl[(size_t)n * S_ + s0 + m] = l;
        }
    }
}

// ---------------- scores: E = exp(scale * Q Kt) + rowsums ----------------
__global__ __launch_bounds__(256, 2) void mma_scores(
    const h16* __restrict__ Qh,
    const h16* __restrict__ Kh, const h16* __restrict__ Kl,
    float* __restrict__ scores, float* __restrict__ rowsum)
{
    extern __shared__ __align__(16) char smem[];
    const int tid = threadIdx.x, wid = tid >> 5, lane = tid & 31;
    const int bh = blockIdx.z;
    const int b = bh >> 4, hd = bh & 15;
    const int row0 = blockIdx.y * 128, col0 = blockIdx.x * 128;

    float acc[2][8][4];
    ZERO_ACC(acc)
    gemm_core_h(acc,
        Qh + ((size_t)b * S_ + row0) * DM_ + hd * HD_, DM_,
        Kh + ((size_t)b * S_ + col0) * HD_,
        Kl + ((size_t)b * S_ + col0) * HD_, HD_, HD_, smem);

    float* stg = (float*)smem;
    float* red = (float*)(smem + RED64);
    const int wm = wid & 3, wn = wid >> 2;
    const int r0 = wm * 32 + (lane >> 2), c0 = wn * 64 + (lane & 3) * 2;
    float sums[2][2] = {{0.f, 0.f}, {0.f, 0.f}};
#pragma unroll
    for (int mt = 0; mt < 2; mt++)
#pragma unroll
        for (int nt = 0; nt < 8; nt++) {
            float e0 = __expf(acc[mt][nt][0] * SCALE_);
            float e1 = __expf(acc[mt][nt][1] * SCALE_);
            float e2 = __expf(acc[mt][nt][2] * SCALE_);
            float e3 = __expf(acc[mt][nt][3] * SCALE_);
            int r = r0 + mt * 16, c = c0 + nt * 8;
            *(float2*)&stg[r * 132 + c] = make_float2(e0, e1);
            *(float2*)&stg[(r + 8) * 132 + c] = make_float2(e2, e3);
            sums[mt][0] += e0 + e1;
            sums[mt][1] += e2 + e3;
        }
#pragma unroll
    for (int mt = 0; mt < 2; mt++)
#pragma unroll
        for (int hh = 0; hh < 2; hh++) {
            float v = sums[mt][hh];
            v += __shfl_xor_sync(0xFFFFFFFFu, v, 1);
            v += __shfl_xor_sync(0xFFFFFFFFu, v, 2);
            sums[mt][hh] = v;
        }
    if ((lane & 3) == 0) {
#pragma unroll
        for (int mt = 0; mt < 2; mt++)
#pragma unroll
            for (int hh = 0; hh < 2; hh++)
                red[(wm * 32 + mt * 16 + hh * 8 + (lane >> 2)) * 2 + wn] = sums[mt][hh];
    }
    __syncthreads();
    if (tid < 128)
        atomicAdd(&rowsum[(size_t)bh * S_ + row0 + tid], red[tid * 2] + red[tid * 2 + 1]);

    float* Crow = scores + ((size_t)bh * S_ + row0) * S_ + col0;
#pragma unroll 1
    for (int i = 0; i < 16; i++) {
        int idx = i * 256 + tid;
        int rr = idx >> 5, c4 = (idx & 31) << 2;
        *(float4*)&Crow[(size_t)rr * S_ + c4] = *(float4*)&stg[rr * 132 + c4];
    }
}

// ---------------- normalize scores in place + PV (single-fp16 epilogue) ----------------
__global__ __launch_bounds__(256, 2) void mma_softmax_pv(
    float* __restrict__ scores, const float* __restrict__ rowsum,
    const h16* __restrict__ Vth, const h16* __restrict__ Vtl,
    h16* __restrict__ attnh)
{
    extern __shared__ __align__(16) char smem[];
    const int tid = threadIdx.x, wid = tid >> 5, lane = tid & 31;
    const int bh = blockIdx.y;
    const int b = bh >> 4, hd = bh & 15;
    const int row0 = blockIdx.x * 128;

    float* rinv = (float*)(smem + AUX32);
    if (tid < 128) rinv[tid] = 1.0f / rowsum[(size_t)bh * S_ + row0 + tid];
    __syncthreads();

    float acc[2][8][4];
    ZERO_ACC(acc)
    gemm_core_pv(acc, scores + ((size_t)bh * S_ + row0) * S_, S_,
                 Vth + (size_t)b * HD_ * S_, Vtl + (size_t)b * HD_ * S_, S_,
                 S_, smem, rinv);

    float* stg = (float*)smem;
    stage_acc(acc, stg, wid, lane);
    __syncthreads();
    h16* Cb = attnh + ((size_t)b * S_ + row0) * DM_ + hd * HD_;
#pragma unroll 1
    for (int i = 0; i < 16; i++) {
        int idx = i * 256 + tid;
        int rr = idx >> 5, c4 = (idx & 31) << 2;
        float4 v = *(float4*)&stg[rr * 132 + c4];
        uint32_t h0, h1; pack4h(v, h0, h1);
        *(uint2*)(Cb + (size_t)rr * DM_ + c4) = make_uint2(h0, h1);
    }
}

// ---------------- output GEMM (fp32 + bias epilogue) ----------------
__global__ __launch_bounds__(256, 2) void mma_out(
    const h16* __restrict__ Ag,
    const h16* __restrict__ Bhg, const h16* __restrict__ Blg,
    const float* __restrict__ bias, float* __restrict__ C)
{
    extern __shared__ __align__(16) char smem[];
    const int tid = threadIdx.x, wid = tid >> 5, lane = tid & 31;
    const int row0 = blockIdx.y * 128, col0 = blockIdx.x * 128;

    float* bs = (float*)(smem + AUX64);
    if (tid < 128) bs[tid] = bias[col0 + tid];

    float acc[2][8][4];
    ZERO_ACC(acc)
    gemm_core_h(acc, Ag + (size_t)row0 * DM_, DM_,
                Bhg + (size_t)col0 * DM_, Blg + (size_t)col0 * DM_, DM_, DM_, smem);

    float* stg = (float*)smem;
    stage_acc(acc, stg, wid, lane);
    __syncthreads();
#pragma unroll 1
    for (int i = 0; i < 16; i++) {
        int idx = i * 256 + tid;
        int rr = idx >> 5, c4 = (idx & 31) << 2;
        float4 v = *(float4*)&stg[rr * 132 + c4];
        v.x += bs[c4]; v.y += bs[c4 + 1]; v.z += bs[c4 + 2]; v.w += bs[c4 + 3];
        *(float4*)&C[(size_t)(row0 + rr) * DM_ + col0 + c4] = v;
    }
}

// ---------------- launch ----------------
extern "C" void kernel_launch(void* const* d_in, const int* in_sizes, int n_in,
                              void* d_out, int out_size)
{
    const float* x  = (const float*)d_in[0];
    const float* Wq = (const float*)d_in[1];
    const float* bq = (const float*)d_in[2];
    const float* Wk = (const float*)d_in[3];
    const float* bk = (const float*)d_in[4];
    const float* Wv = (const float*)d_in[5];
    const float* bv = (const float*)d_in[6];
    const float* Wo = (const float*)d_in[7];
    const float* bo = (const float*)d_in[8];

    float* out = (float*)d_out;
    float* scores = out + (size_t)B_ * S_ * DM_;

    h16 *pxh, *pQh, *pKh, *pKl, *pVth, *pVtl, *pAh;
    h16 *pWqh, *pWql, *pWkh, *pWkl, *pWvh, *pWvl, *pWoh, *pWol;
    float* pRS;
    cudaGetSymbolAddress((void**)&pxh, g_xh);
    cudaGetSymbolAddress((void**)&pQh, g_Qh);
    cudaGetSymbolAddress((void**)&pKh, g_Kh);   cudaGetSymbolAddress((void**)&pKl, g_Kl);
    cudaGetSymbolAddress((void**)&pVth, g_Vth); cudaGetSymbolAddress((void**)&pVtl, g_Vtl);
    cudaGetSymbolAddress((void**)&pAh, g_attnh);
    cudaGetSymbolAddress((void**)&pWqh, g_Wqh); cudaGetSymbolAddress((void**)&pWql, g_Wql);
    cudaGetSymbolAddress((void**)&pWkh, g_Wkh); cudaGetSymbolAddress((void**)&pWkl, g_Wkl);
    cudaGetSymbolAddress((void**)&pWvh, g_Wvh); cudaGetSymbolAddress((void**)&pWvl, g_Wvl);
    cudaGetSymbolAddress((void**)&pWoh, g_Woh); cudaGetSymbolAddress((void**)&pWol, g_Wol);
    cudaGetSymbolAddress((void**)&pRS, g_rowsum);

    static int smem_set = 0;
    if (!smem_set) {
        cudaFuncSetAttribute(mma_proj, cudaFuncAttributeMaxDynamicSharedMemorySize, SMEM64);
        cudaFuncSetAttribute(mma_kvproj, cudaFuncAttributeMaxDynamicSharedMemorySize, SMEM64);
        cudaFuncSetAttribute(mma_scores, cudaFuncAttributeMaxDynamicSharedMemorySize, SMEM64);
        cudaFuncSetAttribute(mma_softmax_pv, cudaFuncAttributeMaxDynamicSharedMemorySize, SMEM32);
        cudaFuncSetAttribute(mma_out, cudaFuncAttributeMaxDynamicSharedMemorySize, SMEM64);
        smem_set = 1;
    }

    const int M = B_ * S_;   // 8192
    split_x_kernel<<<(M * DM_ / 4 + 255) / 256, 256>>>(x, pxh, M * DM_ / 4);
    transpose_split_kernel<<<dim3(DM_ / 32, DM_ / 32), dim3(32, 8)>>>(Wq, pWqh, pWql, DM_, DM_);
    transpose_split_kernel<<<dim3(HD_ / 32, DM_ / 32), dim3(32, 8)>>>(Wk, pWkh, pWkl, DM_, HD_);
    transpose_split_kernel<<<dim3(HD_ / 32, DM_ / 32), dim3(32, 8)>>>(Wv, pWvh, pWvl, DM_, HD_);
    transpose_split_kernel<<<dim3(DM_ / 32, DM_ / 32), dim3(32, 8)>>>(Wo, pWoh, pWol, DM_, DM_);
    zero_kernel<<<(B_ * H_ * S_ + 255) / 256, 256>>>(pRS, B_ * H_ * S_);

    mma_proj<<<dim3(DM_ / 128, M / 128), 256, SMEM64>>>(
        pxh, DM_, pWqh, pWql, DM_, bq, pQh, DM_, DM_);
    mma_kvproj<<<dim3(1, M / 128, 2), 256, SMEM64>>>(
        pxh, pWkh, pWkl, pWvh, pWvl, bk, bv, pKh, pKl, pVth, pVtl);

    mma_scores<<<dim3(S_ / 128, S_ / 128, B_ * H_), 256, SMEM64>>>(
        pQh, pKh, pKl, scores, pRS);
    mma_softmax_pv<<<dim3(S_ / 128, B_ * H_), 256, SMEM32>>>(
        scores, pRS, pVth, pVtl, pAh);

    mma_out<<<dim3(DM_ / 128, M / 128), 256, SMEM64>>>(
        pAh, pWoh, pWol, bo, out);
}

// round 10
// speedup vs baseline: 2.4154x; 1.0020x over previous
#include <cuda_runtime.h>
#include <cuda_fp16.h>
#include <cstdint>

// Problem dims
#define B_  4
#define S_  2048
#define DM_ 2048
#define H_  16
#define HD_ 128
#define SCALE_ 0.08838834764831843f   // 1/sqrt(128)

typedef __half h16;

// ---------------- scratch (__device__ globals) ----------------
__device__ h16 g_xh[(size_t)B_ * S_ * DM_];       // A-side: single fp16
__device__ h16 g_Qh[(size_t)B_ * S_ * DM_];
__device__ h16 g_Kh[(size_t)B_ * S_ * HD_];       // B-side: hi+lo
__device__ h16 g_Kl[(size_t)B_ * S_ * HD_];
__device__ h16 g_Vth[(size_t)B_ * HD_ * S_];      // [B][128][2048]
__device__ h16 g_Vtl[(size_t)B_ * HD_ * S_];
__device__ h16 g_attnh[(size_t)B_ * S_ * DM_];
__device__ h16 g_E[(size_t)B_ * H_ * S_ * S_];    // unnormalized exp scores, fp16 (512 MB)
__device__ h16 g_Wqh[(size_t)DM_ * DM_];          // transposed [N][K]: hi+lo
__device__ h16 g_Wql[(size_t)DM_ * DM_];
__device__ h16 g_Wkh[(size_t)HD_ * DM_];
__device__ h16 g_Wkl[(size_t)HD_ * DM_];
__device__ h16 g_Wvh[(size_t)HD_ * DM_];
__device__ h16 g_Wvl[(size_t)HD_ * DM_];
__device__ h16 g_Woh[(size_t)DM_ * DM_];
__device__ h16 g_Wol[(size_t)DM_ * DM_];
__device__ float g_rowsum[(size_t)B_ * H_ * S_];

// ---------------- smem layouts ----------------
// BK=64 cores: stage = {A, Bh, Bl}, each 128 x 72 fp16 = 18432 B
#define LDT64   72
#define TILE64  (128 * LDT64 * 2)         // 18432
#define STAGE64 (3 * TILE64)              // 55296
#define AUX64   (2 * STAGE64)             // 110592
#define RED64   (AUX64 + 512)
#define SMEM64  (AUX64 + 1536)            // 112128
// BK=32 PV core: stage = {A, Bh, Bl}, each 128 x 40 fp16 = 10240 B
#define LDT32   40
#define TILE32  10240
#define STAGE32 (3 * TILE32)              // 30720
#define AUX32   67584
#define SMEM32  69632

// ---------------- low-level helpers ----------------
__device__ __forceinline__ uint32_t smem_u32(const void* p) {
    uint32_t a;
    asm("{ .reg .u64 t; cvta.to.shared.u64 t, %1; cvt.u32.u64 %0, t; }" : "=r"(a) : "l"(p));
    return a;
}
__device__ __forceinline__ void cp16(uint32_t s, const void* g) {
    asm volatile("cp.async.ca.shared.global [%0], [%1], 16;"
                 :: "r"(s), "l"(__cvta_generic_to_global(g)));
}
#define CP_COMMIT() asm volatile("cp.async.commit_group;" ::: "memory")
#define CP_WAIT1()  asm volatile("cp.async.wait_group 1;" ::: "memory")
__device__ __forceinline__ void ldsm4(uint32_t* r, uint32_t a) {
    asm volatile("ldmatrix.sync.aligned.m8n8.x4.shared.b16 {%0,%1,%2,%3}, [%4];"
        : "=r"(r[0]), "=r"(r[1]), "=r"(r[2]), "=r"(r[3]) : "r"(a));
}
__device__ __forceinline__ void mma_fp16(float* d, const uint32_t* a, uint32_t b0, uint32_t b1) {
    asm volatile("mma.sync.aligned.m16n8k16.row.col.f32.f16.f16.f32 "
        "{%0,%1,%2,%3}, {%4,%5,%6,%7}, {%8,%9}, {%0,%1,%2,%3};"
        : "+f"(d[0]), "+f"(d[1]), "+f"(d[2]), "+f"(d[3])
        : "r"(a[0]), "r"(a[1]), "r"(a[2]), "r"(a[3]), "r"(b0), "r"(b1));
}
__device__ __forceinline__ uint32_t hbits2(__half2 h) {
    return *reinterpret_cast<uint32_t*>(&h);
}
__device__ __forceinline__ void split4h(float4 v, uint32_t& h0, uint32_t& h1,
                                        uint32_t& l0, uint32_t& l1) {
    __half2 a = __floats2half2_rn(v.x, v.y);
    __half2 b = __floats2half2_rn(v.z, v.w);
    float2 fa = __half22float2(a);
    float2 fb = __half22float2(b);
    __half2 c = __floats2half2_rn(v.x - fa.x, v.y - fa.y);
    __half2 d = __floats2half2_rn(v.z - fb.x, v.w - fb.y);
    h0 = hbits2(a); h1 = hbits2(b); l0 = hbits2(c); l1 = hbits2(d);
}
__device__ __forceinline__ void pack4h(float4 v, uint32_t& h0, uint32_t& h1) {
    __half2 a = __floats2half2_rn(v.x, v.y);
    __half2 b = __floats2half2_rn(v.z, v.w);
    h0 = hbits2(a); h1 = hbits2(b);
}

// ---------------- BK=64 tile movement ----------------
__device__ __forceinline__ void issue_tiles64(char* buf,
    const h16* __restrict__ Ag, size_t lda,
    const h16* __restrict__ Bhg, const h16* __restrict__ Blg, size_t ldb,
    int k0, int tid)
{
    uint32_t sA = smem_u32(buf);
#pragma unroll
    for (int i = 0; i < 4; i++) {
        int idx = i * 256 + tid;              // 0..1023
        int r = idx >> 3, c8 = (idx & 7) * 8;
        cp16(sA + r * (LDT64 * 2) + c8 * 2, Ag + (size_t)r * lda + k0 + c8);
    }
    uint32_t sB = sA + TILE64;
#pragma unroll
    for (int i = 0; i < 4; i++) {
        int idx = i * 256 + tid;
        int r = idx >> 3, c8 = (idx & 7) * 8;
        uint32_t d = sB + r * (LDT64 * 2) + c8 * 2;
        cp16(d, Bhg + (size_t)r * ldb + k0 + c8);
        cp16(d + TILE64, Blg + (size_t)r * ldb + k0 + c8);
    }
}
// BK=32 B-only (PV)
__device__ __forceinline__ void issue_B32(char* buf,
    const h16* __restrict__ Bhg, const h16* __restrict__ Blg, size_t ldb,
    int k0, int tid)
{
    uint32_t sB = smem_u32(buf) + TILE32;
#pragma unroll
    for (int i = 0; i < 2; i++) {
        int idx = i * 256 + tid;
        int r = idx >> 2, c8 = (idx & 3) * 8;
        uint32_t d = sB + r * (LDT32 * 2) + c8 * 2;
        cp16(d, Bhg + (size_t)r * ldb + k0 + c8);
        cp16(d + TILE32, Blg + (size_t)r * ldb + k0 + c8);
    }
}

// ---------------- MMA compute ----------------
template<int LDT, int TILE, int BK>
__device__ __forceinline__ void compute_chunk(float (*acc)[8][4], char* buf,
                                              int wm, int wn, int lane)
{
    h16* Ah = (h16*)buf;
    h16* Bh = (h16*)(buf + TILE);
    h16* Bl = (h16*)(buf + 2 * TILE);
    const int ar = lane & 15;
    const int acs = (lane >> 4) << 3;
#pragma unroll
    for (int kk = 0; kk < BK; kk += 16) {
        const int ac = kk + acs;
        uint32_t aH[2][4];
#pragma unroll
        for (int mt = 0; mt < 2; mt++)
            ldsm4(aH[mt], smem_u32(Ah + (wm * 32 + mt * 16 + ar) * LDT + ac));
#pragma unroll
        for (int p = 0; p < 4; p++) {
            uint32_t bh[4], bl[4];
            ldsm4(bh, smem_u32(Bh + (wn * 64 + p * 16 + ar) * LDT + ac));
            ldsm4(bl, smem_u32(Bl + (wn * 64 + p * 16 + ar) * LDT + ac));
#pragma unroll
            for (int mt = 0; mt < 2; mt++) {
                mma_fp16(acc[mt][2 * p],     aH[mt], bh[0], bh[2]);
                mma_fp16(acc[mt][2 * p + 1], aH[mt], bh[1], bh[3]);
                mma_fp16(acc[mt][2 * p],     aH[mt], bl[0], bl[2]);
                mma_fp16(acc[mt][2 * p + 1], aH[mt], bl[1], bl[3]);
            }
        }
    }
}

// generic BK=64 pipelined core (A single fp16, B hi+lo)
__device__ __forceinline__ void gemm_core_h(float (*acc)[8][4],
    const h16* __restrict__ Ag, size_t lda,
    const h16* __restrict__ Bhg, const h16* __restrict__ Blg, size_t ldb,
    int Kdim, char* smem)
{
    const int tid = threadIdx.x, wid = tid >> 5, lane = tid & 31;
    const int wm = wid & 3, wn = wid >> 2;
    const int nC = Kdim >> 6;
    issue_tiles64(smem, Ag, lda, Bhg, Blg, ldb, 0, tid); CP_COMMIT();
    issue_tiles64(smem + STAGE64, Ag, lda, Bhg, Blg, ldb, 64, tid); CP_COMMIT();
#pragma unroll 1
    for (int c = 0; c < nC; c++) {
        char* buf = smem + (c & 1) * STAGE64;
        CP_WAIT1();
        __syncthreads();
        compute_chunk<LDT64, TILE64, 64>(acc, buf, wm, wn, lane);
        __syncthreads();
        if (c + 2 < nC)
            issue_tiles64(buf, Ag, lda, Bhg, Blg, ldb, (c + 2) * 64, tid);
        CP_COMMIT();
    }
    asm volatile("cp.async.wait_all;" ::: "memory");
    __syncthreads();
}

// PV core: BK=32. A = fp16 unnormalized E (register double-buffer prefetch):
// normalize by rinv, write fp32 normalized scores to Sout, pack fp16 A to smem.
__device__ __forceinline__ void gemm_core_pv(float (*acc)[8][4],
    const h16* __restrict__ E, float* __restrict__ Sout, size_t lda,
    const h16* __restrict__ Bhg, const h16* __restrict__ Blg, size_t ldb,
    int Kdim, char* smem, const float* __restrict__ rinv)
{
    const int tid = threadIdx.x, wid = tid >> 5, lane = tid & 31;
    const int wm = wid & 3, wn = wid >> 2;
    const int nC = Kdim >> 5;                     // 64
    issue_B32(smem, Bhg, Blg, ldb, 0, tid); CP_COMMIT();
    issue_B32(smem + STAGE32, Bhg, Blg, ldb, 32, tid); CP_COMMIT();

    // prefetch regs: 16 halves = this thread's slice of the next A chunk
    uint4 pr[2];
#pragma unroll
    for (int i = 0; i < 2; i++) {
        int idx = i * 256 + tid;
        int rr = idx >> 2, cc = (idx & 3) * 8;
        pr[i] = *(const uint4*)(E + (size_t)rr * lda + cc);
    }
#pragma unroll 1
    for (int c = 0; c < nC; c++) {
        char* buf = smem + (c & 1) * STAGE32;
        CP_WAIT1();
        // consume prefetched A chunk c: normalize, write fp32 scores, pack to smem
        h16* Ah = (h16*)buf;
#pragma unroll
        for (int i = 0; i < 2; i++) {
            int idx = i * 256 + tid;
            int rr = idx >> 2, cc = (idx & 3) * 8;
            float ri = rinv[rr];
            __half2* ph = (__half2*)&pr[i];
            float2 f0 = __half22float2(ph[0]);
            float2 f1 = __half22float2(ph[1]);
            float2 f2 = __half22float2(ph[2]);
            float2 f3 = __half22float2(ph[3]);
            float4 o1 = make_float4(f0.x * ri, f0.y * ri, f1.x * ri, f1.y * ri);
            float4 o2 = make_float4(f2.x * ri, f2.y * ri, f3.x * ri, f3.y * ri);
            float* sp = Sout + (size_t)rr * lda + c * 32 + cc;
            *(float4*)sp = o1;
            *(float4*)(sp + 4) = o2;
            uint32_t q0, q1, q2, q3;
            pack4h(o1, q0, q1);
            pack4h(o2, q2, q3);
            *(uint4*)(Ah + rr * LDT32 + cc) = make_uint4(q0, q1, q2, q3);
        }
        // prefetch A chunk c+1 (LDG latency hidden behind compute below)
        if (c + 1 < nC) {
#pragma unroll
            for (int i = 0; i < 2; i++) {
                int idx = i * 256 + tid;
                int rr = idx >> 2, cc = (idx & 3) * 8;
                pr[i] = *(const uint4*)(E + (size_t)rr * lda + (c + 1) * 32 + cc);
            }
        }
        __syncthreads();
        compute_chunk<LDT32, TILE32, 32>(acc, buf, wm, wn, lane);
        __syncthreads();
        if (c + 2 < nC)
            issue_B32(buf, Bhg, Blg, ldb, (c + 2) * 32, tid);
        CP_COMMIT();
    }
    asm volatile("cp.async.wait_all;" ::: "memory");
    __syncthreads();
}

// stage acc (fp32) into smem [128][132]
__device__ __forceinline__ void stage_acc(float (*acc)[8][4], float* stg, int wid, int lane) {
    int wm = wid & 3, wn = wid >> 2;
    int r0 = wm * 32 + (lane >> 2), c0 = wn * 64 + (lane & 3) * 2;
#pragma unroll
    for (int mt = 0; mt < 2; mt++)
#pragma unroll
        for (int nt = 0; nt < 8; nt++) {
            int r = r0 + mt * 16, c = c0 + nt * 8;
            *(float2*)&stg[r * 132 + c] = make_float2(acc[mt][nt][0], acc[mt][nt][1]);
            *(float2*)&stg[(r + 8) * 132 + c] = make_float2(acc[mt][nt][2], acc[mt][nt][3]);
        }
}

#define ZERO_ACC(acc) \
    _Pragma("unroll") for (int i_ = 0; i_ < 2; i_++) \
    _Pragma("unroll") for (int j_ = 0; j_ < 8; j_++) \
    _Pragma("unroll") for (int q_ = 0; q_ < 4; q_++) acc[i_][j_][q_] = 0.0f;

// ---------------- prep kernels ----------------
__global__ void split_x_kernel(const float* __restrict__ x, h16* __restrict__ xh, int n4) {
    int i = blockIdx.x * blockDim.x + threadIdx.x;
    if (i >= n4) return;
    float4 v = *(const float4*)(x + 4 * (size_t)i);
    uint32_t h0, h1; pack4h(v, h0, h1);
    *(uint2*)(xh + 4 * (size_t)i) = make_uint2(h0, h1);
}
__global__ void transpose_split_kernel(const float* __restrict__ src,
                                       h16* __restrict__ dh, h16* __restrict__ dl,
                                       int M, int N) {
    __shared__ float t[32][33];
    int bx = blockIdx.x * 32, by = blockIdx.y * 32;
    int x = threadIdx.x, y0 = threadIdx.y;
#pragma unroll
    for (int j = 0; j < 32; j += 8)
        t[y0 + j][x] = src[(size_t)(by + y0 + j) * N + bx + x];
    __syncthreads();
#pragma unroll
    for (int j = 0; j < 32; j += 8) {
        float v = t[x][y0 + j];
        h16 h = __float2half_rn(v);
        h16 l = __float2half_rn(v - __half2float(h));
        size_t o = (size_t)(bx + y0 + j) * M + by + x;
        dh[o] = h; dl[o] = l;
    }
}
__global__ void zero_kernel(float* p, int n) {
    int i = blockIdx.x * blockDim.x + threadIdx.x;
    if (i < n) p[i] = 0.0f;
}

// ---------------- Q projection (single-fp16 epilogue) ----------------
__global__ __launch_bounds__(256, 2) void mma_proj(
    const h16* __restrict__ Ag, size_t lda,
    const h16* __restrict__ Bhg, const h16* __restrict__ Blg, size_t ldb,
    const float* __restrict__ bias,
    h16* __restrict__ Ch, size_t ldc, int Kdim)
{
    extern __shared__ __align__(16) char smem[];
    const int tid = threadIdx.x, wid = tid >> 5, lane = tid & 31;
    const int row0 = blockIdx.y * 128, col0 = blockIdx.x * 128;

    float* bs = (float*)(smem + AUX64);
    if (tid < 128) bs[tid] = bias[col0 + tid];

    float acc[2][8][4];
    ZERO_ACC(acc)
    gemm_core_h(acc, Ag + (size_t)row0 * lda, lda,
                Bhg + (size_t)col0 * ldb, Blg + (size_t)col0 * ldb, ldb, Kdim, smem);

    float* stg = (float*)smem;
    stage_acc(acc, stg, wid, lane);
    __syncthreads();
#pragma unroll 1
    for (int i = 0; i < 16; i++) {
        int idx = i * 256 + tid;
        int rr = idx >> 5, c4 = (idx & 31) << 2;
        float4 v = *(float4*)&stg[rr * 132 + c4];
        v.x += bs[c4]; v.y += bs[c4 + 1]; v.z += bs[c4 + 2]; v.w += bs[c4 + 3];
        uint32_t h0, h1; pack4h(v, h0, h1);
        *(uint2*)(Ch + (size_t)(row0 + rr) * ldc + col0 + c4) = make_uint2(h0, h1);
    }
}

// ---------------- fused K + V projection (gridDim.z selects) ----------------
__global__ __launch_bounds__(256, 2) void mma_kvproj(
    const h16* __restrict__ Ag,
    const h16* __restrict__ Wkh, const h16* __restrict__ Wkl,
    const h16* __restrict__ Wvh, const h16* __restrict__ Wvl,
    const float* __restrict__ bk, const float* __restrict__ bv,
    h16* __restrict__ Kh, h16* __restrict__ Kl,
    h16* __restrict__ Vth, h16* __restrict__ Vtl)
{
    extern __shared__ __align__(16) char smem[];
    const int tid = threadIdx.x, wid = tid >> 5, lane = tid & 31;
    const int row0 = blockIdx.y * 128;
    const int z = blockIdx.z;                  // 0 = K, 1 = V

    const h16* Bhg = z ? Wvh : Wkh;
    const h16* Blg = z ? Wvl : Wkl;
    const float* bias = z ? bv : bk;

    float* bs = (float*)(smem + AUX64);
    if (tid < 128) bs[tid] = bias[tid];

    float acc[2][8][4];
    ZERO_ACC(acc)
    gemm_core_h(acc, Ag + (size_t)row0 * DM_, DM_, Bhg, Blg, DM_, DM_, smem);

    float* stg = (float*)smem;
    stage_acc(acc, stg, wid, lane);
    __syncthreads();
    if (z == 0) {
        // K: hi/lo, row-major [B*S, HD]
#pragma unroll 1
        for (int i = 0; i < 16; i++) {
            int idx = i * 256 + tid;
            int rr = idx >> 5, c4 = (idx & 31) << 2;
            float4 v = *(float4*)&stg[rr * 132 + c4];
            v.x += bs[c4]; v.y += bs[c4 + 1]; v.z += bs[c4 + 2]; v.w += bs[c4 + 3];
            uint32_t h0, h1, l0, l1; split4h(v, h0, h1, l0, l1);
            size_t o = (size_t)(row0 + rr) * HD_ + c4;
            *(uint2*)(Kh + o) = make_uint2(h0, h1);
            *(uint2*)(Kl + o) = make_uint2(l0, l1);
        }
    } else {
        // V: hi/lo, transposed [B][HD][S]
        int b = row0 >> 11;
        int s0 = row0 & (S_ - 1);
        h16* Vbh = Vth + (size_t)b * HD_ * S_;
        h16* Vbl = Vtl + (size_t)b * HD_ * S_;
#pragma unroll 1
        for (int i = 0; i < 64; i++) {
            int idx = i * 256 + tid;
            int m = idx & 127, n = idx >> 7;
            float v = stg[m * 132 + n] + bs[n];
            h16 h = __float2half_rn(v);
            h16 l = __float2half_rn(v - __half2float(h));
            Vbh[(size_t)n * S_ + s0 + m] = h;
            Vbl[(size_t)n * S_ + s0 + m] = l;
        }
    }
}

// ---------------- scores: E = exp(scale * Q Kt) (fp16 out) + rowsums ----------------
__global__ __launch_bounds__(256, 2) void mma_scores(
    const h16* __restrict__ Qh,
    const h16* __restrict__ Kh, const h16* __restrict__ Kl,
    h16* __restrict__ E, float* __restrict__ rowsum)
{
    extern __shared__ __align__(16) char smem[];
    const int tid = threadIdx.x, wid = tid >> 5, lane = tid & 31;
    const int bh = blockIdx.z;
    const int b = bh >> 4, hd = bh & 15;
    const int row0 = blockIdx.y * 128, col0 = blockIdx.x * 128;

    float acc[2][8][4];
    ZERO_ACC(acc)
    gemm_core_h(acc,
        Qh + ((size_t)b * S_ + row0) * DM_ + hd * HD_, DM_,
        Kh + ((size_t)b * S_ + col0) * HD_,
        Kl + ((size_t)b * S_ + col0) * HD_, HD_, HD_, smem);

    float* stg = (float*)smem;
    float* red = (float*)(smem + RED64);
    const int wm = wid & 3, wn = wid >> 2;
    const int r0 = wm * 32 + (lane >> 2), c0 = wn * 64 + (lane & 3) * 2;
    float sums[2][2] = {{0.f, 0.f}, {0.f, 0.f}};
#pragma unroll
    for (int mt = 0; mt < 2; mt++)
#pragma unroll
        for (int nt = 0; nt < 8; nt++) {
            float e0 = __expf(acc[mt][nt][0] * SCALE_);
            float e1 = __expf(acc[mt][nt][1] * SCALE_);
            float e2 = __expf(acc[mt][nt][2] * SCALE_);
            float e3 = __expf(acc[mt][nt][3] * SCALE_);
            int r = r0 + mt * 16, c = c0 + nt * 8;
            *(float2*)&stg[r * 132 + c] = make_float2(e0, e1);
            *(float2*)&stg[(r + 8) * 132 + c] = make_float2(e2, e3);
            sums[mt][0] += e0 + e1;
            sums[mt][1] += e2 + e3;
        }
#pragma unroll
    for (int mt = 0; mt < 2; mt++)
#pragma unroll
        for (int hh = 0; hh < 2; hh++) {
            float v = sums[mt][hh];
            v += __shfl_xor_sync(0xFFFFFFFFu, v, 1);
            v += __shfl_xor_sync(0xFFFFFFFFu, v, 2);
            sums[mt][hh] = v;
        }
    if ((lane & 3) == 0) {
#pragma unroll
        for (int mt = 0; mt < 2; mt++)
#pragma unroll
            for (int hh = 0; hh < 2; hh++)
                red[(wm * 32 + mt * 16 + hh * 8 + (lane >> 2)) * 2 + wn] = sums[mt][hh];
    }
    __syncthreads();
    if (tid < 128)
        atomicAdd(&rowsum[(size_t)bh * S_ + row0 + tid], red[tid * 2] + red[tid * 2 + 1]);

    // write fp16 E
    h16* Crow = E + ((size_t)bh * S_ + row0) * S_ + col0;
#pragma unroll 1
    for (int i = 0; i < 16; i++) {
        int idx = i * 256 + tid;
        int rr = idx >> 5, c4 = (idx & 31) << 2;
        float4 v = *(float4*)&stg[rr * 132 + c4];
        uint32_t h0, h1; pack4h(v, h0, h1);
        *(uint2*)(Crow + (size_t)rr * S_ + c4) = make_uint2(h0, h1);
    }
}

// ---------------- PV: normalize fp16 E -> fp32 scores out + P@V ----------------
__global__ __launch_bounds__(256, 2) void mma_softmax_pv(
    const h16* __restrict__ E, float* __restrict__ scoresOut,
    const float* __restrict__ rowsum,
    const h16* __restrict__ Vth, const h16* __restrict__ Vtl,
    h16* __restrict__ attnh)
{
    extern __shared__ __align__(16) char smem[];
    const int tid = threadIdx.x, wid = tid >> 5, lane = tid & 31;
    const int bh = blockIdx.y;
    const int b = bh >> 4, hd = bh & 15;
    const int row0 = blockIdx.x * 128;

    float* rinv = (float*)(smem + AUX32);
    if (tid < 128) rinv[tid] = 1.0f / rowsum[(size_t)bh * S_ + row0 + tid];
    __syncthreads();

    float acc[2][8][4];
    ZERO_ACC(acc)
    gemm_core_pv(acc,
                 E + ((size_t)bh * S_ + row0) * S_,
                 scoresOut + ((size_t)bh * S_ + row0) * S_, S_,
                 Vth + (size_t)b * HD_ * S_, Vtl + (size_t)b * HD_ * S_, S_,
                 S_, smem, rinv);

    float* stg = (float*)smem;
    stage_acc(acc, stg, wid, lane);
    __syncthreads();
    h16* Cb = attnh + ((size_t)b * S_ + row0) * DM_ + hd * HD_;
#pragma unroll 1
    for (int i = 0; i < 16; i++) {
        int idx = i * 256 + tid;
        int rr = idx >> 5, c4 = (idx & 31) << 2;
        float4 v = *(float4*)&stg[rr * 132 + c4];
        uint32_t h0, h1; pack4h(v, h0, h1);
        *(uint2*)(Cb + (size_t)rr * DM_ + c4) = make_uint2(h0, h1);
    }
}

// ---------------- output GEMM (fp32 + bias epilogue) ----------------
__global__ __launch_bounds__(256, 2) void mma_out(
    const h16* __restrict__ Ag,
    const h16* __restrict__ Bhg, const h16* __restrict__ Blg,
    const float* __restrict__ bias, float* __restrict__ C)
{
    extern __shared__ __align__(16) char smem[];
    const int tid = threadIdx.x, wid = tid >> 5, lane = tid & 31;
    const int row0 = blockIdx.y * 128, col0 = blockIdx.x * 128;

    float* bs = (float*)(smem + AUX64);
    if (tid < 128) bs[tid] = bias[col0 + tid];

    float acc[2][8][4];
    ZERO_ACC(acc)
    gemm_core_h(acc, Ag + (size_t)row0 * DM_, DM_,
                Bhg + (size_t)col0 * DM_, Blg + (size_t)col0 * DM_, DM_, DM_, smem);

    float* stg = (float*)smem;
    stage_acc(acc, stg, wid, lane);
    __syncthreads();
#pragma unroll 1
    for (int i = 0; i < 16; i++) {
        int idx = i * 256 + tid;
        int rr = idx >> 5, c4 = (idx & 31) << 2;
        float4 v = *(float4*)&stg[rr * 132 + c4];
        v.x += bs[c4]; v.y += bs[c4 + 1]; v.z += bs[c4 + 2]; v.w += bs[c4 + 3];
        *(float4*)&C[(size_t)(row0 + rr) * DM_ + col0 + c4] = v;
    }
}

// ---------------- launch ----------------
extern "C" void kernel_launch(void* const* d_in, const int* in_sizes, int n_in,
                              void* d_out, int out_size)
{
    const float* x  = (const float*)d_in[0];
    const float* Wq = (const float*)d_in[1];
    const float* bq = (const float*)d_in[2];
    const float* Wk = (const float*)d_in[3];
    const float* bk = (const float*)d_in[4];
    const float* Wv = (const float*)d_in[5];
    const float* bv = (const float*)d_in[6];
    const float* Wo = (const float*)d_in[7];
    const float* bo = (const float*)d_in[8];

    float* out = (float*)d_out;
    float* scores = out + (size_t)B_ * S_ * DM_;

    h16 *pxh, *pQh, *pKh, *pKl, *pVth, *pVtl, *pAh, *pE;
    h16 *pWqh, *pWql, *pWkh, *pWkl, *pWvh, *pWvl, *pWoh, *pWol;
    float* pRS;
    cudaGetSymbolAddress((void**)&pxh, g_xh);
    cudaGetSymbolAddress((void**)&pQh, g_Qh);
    cudaGetSymbolAddress((void**)&pKh, g_Kh);   cudaGetSymbolAddress((void**)&pKl, g_Kl);
    cudaGetSymbolAddress((void**)&pVth, g_Vth); cudaGetSymbolAddress((void**)&pVtl, g_Vtl);
    cudaGetSymbolAddress((void**)&pAh, g_attnh);
    cudaGetSymbolAddress((void**)&pE, g_E);
    cudaGetSymbolAddress((void**)&pWqh, g_Wqh); cudaGetSymbolAddress((void**)&pWql, g_Wql);
    cudaGetSymbolAddress((void**)&pWkh, g_Wkh); cudaGetSymbolAddress((void**)&pWkl, g_Wkl);
    cudaGetSymbolAddress((void**)&pWvh, g_Wvh); cudaGetSymbolAddress((void**)&pWvl, g_Wvl);
    cudaGetSymbolAddress((void**)&pWoh, g_Woh); cudaGetSymbolAddress((void**)&pWol, g_Wol);
    cudaGetSymbolAddress((void**)&pRS, g_rowsum);

    static int smem_set = 0;
    if (!smem_set) {
        cudaFuncSetAttribute(mma_proj, cudaFuncAttributeMaxDynamicSharedMemorySize, SMEM64);
        cudaFuncSetAttribute(mma_kvproj, cudaFuncAttributeMaxDynamicSharedMemorySize, SMEM64);
        cudaFuncSetAttribute(mma_scores, cudaFuncAttributeMaxDynamicSharedMemorySize, SMEM64);
        cudaFuncSetAttribute(mma_softmax_pv, cudaFuncAttributeMaxDynamicSharedMemorySize, SMEM32);
        cudaFuncSetAttribute(mma_out, cudaFuncAttributeMaxDynamicSharedMemorySize, SMEM64);
        smem_set = 1;
    }

    const int M = B_ * S_;   // 8192
    split_x_kernel<<<(M * DM_ / 4 + 255) / 256, 256>>>(x, pxh, M * DM_ / 4);
    transpose_split_kernel<<<dim3(DM_ / 32, DM_ / 32), dim3(32, 8)>>>(Wq, pWqh, pWql, DM_, DM_);
    transpose_split_kernel<<<dim3(HD_ / 32, DM_ / 32), dim3(32, 8)>>>(Wk, pWkh, pWkl, DM_, HD_);
    transpose_split_kernel<<<dim3(HD_ / 32, DM_ / 32), dim3(32, 8)>>>(Wv, pWvh, pWvl, DM_, HD_);
    transpose_split_kernel<<<dim3(DM_ / 32, DM_ / 32), dim3(32, 8)>>>(Wo, pWoh, pWol, DM_, DM_);
    zero_kernel<<<(B_ * H_ * S_ + 255) / 256, 256>>>(pRS, B_ * H_ * S_);

    mma_proj<<<dim3(DM_ / 128, M / 128), 256, SMEM64>>>(
        pxh, DM_, pWqh, pWql, DM_, bq, pQh, DM_, DM_);
    mma_kvproj<<<dim3(1, M / 128, 2), 256, SMEM64>>>(
        pxh, pWkh, pWkl, pWvh, pWvl, bk, bv, pKh, pKl, pVth, pVtl);

    mma_scores<<<dim3(S_ / 128, S_ / 128, B_ * H_), 256, SMEM64>>>(
        pQh, pKh, pKl, pE, pRS);
    mma_softmax_pv<<<dim3(S_ / 128, B_ * H_), 256, SMEM32>>>(
        pE, scores, pRS, pVth, pVtl, pAh);

    mma_out<<<dim3(DM_ / 128, M / 128), 256, SMEM64>>>(
        pAh, pWoh, pWol, bo, out);
}

// round 11
// speedup vs baseline: 2.9690x; 1.2292x over previous
#include <cuda_runtime.h>
#include <cuda_fp16.h>
#include <cstdint>

// Problem dims
#define B_  4
#define S_  2048
#define DM_ 2048
#define H_  16
#define HD_ 128
#define SCALE_ 0.08838834764831843f   // 1/sqrt(128)

typedef __half h16;

// ---------------- scratch (__device__ globals) ----------------
__device__ h16 g_xh[(size_t)B_ * S_ * DM_];       // single fp16
__device__ h16 g_Qh[(size_t)B_ * S_ * DM_];       // single fp16
__device__ h16 g_Kh[(size_t)B_ * S_ * HD_];       // hi+lo (protects scores)
__device__ h16 g_Kl[(size_t)B_ * S_ * HD_];
__device__ h16 g_Vth[(size_t)B_ * HD_ * S_];      // single fp16, [B][128][2048]
__device__ h16 g_attnh[(size_t)B_ * S_ * DM_];    // single fp16
__device__ h16 g_Wqh[(size_t)DM_ * DM_];          // transposed [N][K], single
__device__ h16 g_Wkh[(size_t)HD_ * DM_];          // hi+lo
__device__ h16 g_Wkl[(size_t)HD_ * DM_];
__device__ h16 g_Wvh[(size_t)HD_ * DM_];          // single
__device__ h16 g_Woh[(size_t)DM_ * DM_];          // single
__device__ float g_rowsum[(size_t)B_ * H_ * S_];

// ---------------- smem layouts ----------------
// BK=64 cores: stage = {A, Bh, Bl}, each 128 x 72 fp16 = 18432 B
#define LDT64   72
#define TILE64  (128 * LDT64 * 2)         // 18432
#define STAGE64 (3 * TILE64)              // 55296
#define AUX64   (2 * STAGE64)             // 110592
#define RED64   (AUX64 + 512)
#define SMEM64  (AUX64 + 1536)            // 112128
// BK=32 PV core: stage = {A, Bh}, padded
#define LDT32   40
#define TILE32  10240
#define STAGE32 (2 * TILE32)              // 20480
#define AUX32   67584                     // after fp32 staging 128x132x4
#define SMEM32  69632

// ---------------- low-level helpers ----------------
__device__ __forceinline__ uint32_t smem_u32(const void* p) {
    uint32_t a;
    asm("{ .reg .u64 t; cvta.to.shared.u64 t, %1; cvt.u32.u64 %0, t; }" : "=r"(a) : "l"(p));
    return a;
}
__device__ __forceinline__ void cp16(uint32_t s, const void* g) {
    asm volatile("cp.async.ca.shared.global [%0], [%1], 16;"
                 :: "r"(s), "l"(__cvta_generic_to_global(g)));
}
#define CP_COMMIT() asm volatile("cp.async.commit_group;" ::: "memory")
#define CP_WAIT1()  asm volatile("cp.async.wait_group 1;" ::: "memory")
__device__ __forceinline__ void ldsm4(uint32_t* r, uint32_t a) {
    asm volatile("ldmatrix.sync.aligned.m8n8.x4.shared.b16 {%0,%1,%2,%3}, [%4];"
        : "=r"(r[0]), "=r"(r[1]), "=r"(r[2]), "=r"(r[3]) : "r"(a));
}
__device__ __forceinline__ void mma_fp16(float* d, const uint32_t* a, uint32_t b0, uint32_t b1) {
    asm volatile("mma.sync.aligned.m16n8k16.row.col.f32.f16.f16.f32 "
        "{%0,%1,%2,%3}, {%4,%5,%6,%7}, {%8,%9}, {%0,%1,%2,%3};"
        : "+f"(d[0]), "+f"(d[1]), "+f"(d[2]), "+f"(d[3])
        : "r"(a[0]), "r"(a[1]), "r"(a[2]), "r"(a[3]), "r"(b0), "r"(b1));
}
__device__ __forceinline__ uint32_t hbits2(__half2 h) {
    return *reinterpret_cast<uint32_t*>(&h);
}
__device__ __forceinline__ void split4h(float4 v, uint32_t& h0, uint32_t& h1,
                                        uint32_t& l0, uint32_t& l1) {
    __half2 a = __floats2half2_rn(v.x, v.y);
    __half2 b = __floats2half2_rn(v.z, v.w);
    float2 fa = __half22float2(a);
    float2 fb = __half22float2(b);
    __half2 c = __floats2half2_rn(v.x - fa.x, v.y - fa.y);
    __half2 d = __floats2half2_rn(v.z - fb.x, v.w - fb.y);
    h0 = hbits2(a); h1 = hbits2(b); l0 = hbits2(c); l1 = hbits2(d);
}
__device__ __forceinline__ void pack4h(float4 v, uint32_t& h0, uint32_t& h1) {
    __half2 a = __floats2half2_rn(v.x, v.y);
    __half2 b = __floats2half2_rn(v.z, v.w);
    h0 = hbits2(a); h1 = hbits2(b);
}

// ---------------- BK=64 tile movement ----------------
template<bool TWO>
__device__ __forceinline__ void issue_tiles64(char* buf,
    const h16* __restrict__ Ag, size_t lda,
    const h16* __restrict__ Bhg, const h16* __restrict__ Blg, size_t ldb,
    int k0, int tid)
{
    uint32_t sA = smem_u32(buf);
#pragma unroll
    for (int i = 0; i < 4; i++) {
        int idx = i * 256 + tid;              // 0..1023
        int r = idx >> 3, c8 = (idx & 7) * 8;
        cp16(sA + r * (LDT64 * 2) + c8 * 2, Ag + (size_t)r * lda + k0 + c8);
    }
    uint32_t sB = sA + TILE64;
#pragma unroll
    for (int i = 0; i < 4; i++) {
        int idx = i * 256 + tid;
        int r = idx >> 3, c8 = (idx & 7) * 8;
        uint32_t d = sB + r * (LDT64 * 2) + c8 * 2;
        cp16(d, Bhg + (size_t)r * ldb + k0 + c8);
        if (TWO) cp16(d + TILE64, Blg + (size_t)r * ldb + k0 + c8);
    }
}
// BK=32 B-only, single term (PV)
__device__ __forceinline__ void issue_B32(char* buf,
    const h16* __restrict__ Bhg, size_t ldb, int k0, int tid)
{
    uint32_t sB = smem_u32(buf) + TILE32;
#pragma unroll
    for (int i = 0; i < 2; i++) {
        int idx = i * 256 + tid;
        int r = idx >> 2, c8 = (idx & 3) * 8;
        cp16(sB + r * (LDT32 * 2) + c8 * 2, Bhg + (size_t)r * ldb + k0 + c8);
    }
}

// ---------------- MMA compute: one chunk, warp 32x64, 1- or 2-term ----------------
template<int LDT, int TILE, int BK, bool TWO>
__device__ __forceinline__ void compute_chunk(float (*acc)[8][4], char* buf,
                                              int wm, int wn, int lane)
{
    h16* Ah = (h16*)buf;
    h16* Bh = (h16*)(buf + TILE);
    h16* Bl = (h16*)(buf + 2 * TILE);
    const int ar = lane & 15;
    const int acs = (lane >> 4) << 3;
#pragma unroll
    for (int kk = 0; kk < BK; kk += 16) {
        const int ac = kk + acs;
        uint32_t aH[2][4];
#pragma unroll
        for (int mt = 0; mt < 2; mt++)
            ldsm4(aH[mt], smem_u32(Ah + (wm * 32 + mt * 16 + ar) * LDT + ac));
#pragma unroll
        for (int p = 0; p < 4; p++) {
            uint32_t bh[4];
            ldsm4(bh, smem_u32(Bh + (wn * 64 + p * 16 + ar) * LDT + ac));
#pragma unroll
            for (int mt = 0; mt < 2; mt++) {
                mma_fp16(acc[mt][2 * p],     aH[mt], bh[0], bh[2]);
                mma_fp16(acc[mt][2 * p + 1], aH[mt], bh[1], bh[3]);
            }
            if (TWO) {
                uint32_t bl[4];
                ldsm4(bl, smem_u32(Bl + (wn * 64 + p * 16 + ar) * LDT + ac));
#pragma unroll
                for (int mt = 0; mt < 2; mt++) {
                    mma_fp16(acc[mt][2 * p],     aH[mt], bl[0], bl[2]);
                    mma_fp16(acc[mt][2 * p + 1], aH[mt], bl[1], bl[3]);
                }
            }
        }
    }
}

// generic BK=64 pipelined core (A single fp16; B single or hi+lo)
template<bool TWO>
__device__ __forceinline__ void gemm_core_h(float (*acc)[8][4],
    const h16* __restrict__ Ag, size_t lda,
    const h16* __restrict__ Bhg, const h16* __restrict__ Blg, size_t ldb,
    int Kdim, char* smem)
{
    const int tid = threadIdx.x, wid = tid >> 5, lane = tid & 31;
    const int wm = wid & 3, wn = wid >> 2;
    const int nC = Kdim >> 6;
    issue_tiles64<TWO>(smem, Ag, lda, Bhg, Blg, ldb, 0, tid); CP_COMMIT();
    issue_tiles64<TWO>(smem + STAGE64, Ag, lda, Bhg, Blg, ldb, 64, tid); CP_COMMIT();
#pragma unroll 1
    for (int c = 0; c < nC; c++) {
        char* buf = smem + (c & 1) * STAGE64;
        CP_WAIT1();
        __syncthreads();
        compute_chunk<LDT64, TILE64, 64, TWO>(acc, buf, wm, wn, lane);
        __syncthreads();
        if (c + 2 < nC)
            issue_tiles64<TWO>(buf, Ag, lda, Bhg, Blg, ldb, (c + 2) * 64, tid);
        CP_COMMIT();
    }
    asm volatile("cp.async.wait_all;" ::: "memory");
    __syncthreads();
}

// PV core: BK=32, 1-term. A = fp32 scores with register double-buffer prefetch:
// normalize by rinv, write normalized fp32 back in place, pack fp16 A to smem.
__device__ __forceinline__ void gemm_core_pv(float (*acc)[8][4],
    float* __restrict__ A, size_t lda,
    const h16* __restrict__ Bhg, size_t ldb,
    int Kdim, char* smem, const float* __restrict__ rinv)
{
    const int tid = threadIdx.x, wid = tid >> 5, lane = tid & 31;
    const int wm = wid & 3, wn = wid >> 2;
    const int nC = Kdim >> 5;                     // 64
    issue_B32(smem, Bhg, ldb, 0, tid); CP_COMMIT();
    issue_B32(smem + STAGE32, Bhg, ldb, 32, tid); CP_COMMIT();

    float4 pr[4];
#pragma unroll
    for (int i = 0; i < 4; i++) {
        int idx = i * 256 + tid;
        int rr = idx >> 3, cc = (idx & 7) * 4;
        pr[i] = *(const float4*)(A + (size_t)rr * lda + cc);
    }
#pragma unroll 1
    for (int c = 0; c < nC; c++) {
        char* buf = smem + (c & 1) * STAGE32;
        CP_WAIT1();
        h16* Ah = (h16*)buf;
#pragma unroll
        for (int i = 0; i < 4; i++) {
            int idx = i * 256 + tid;
            int rr = idx >> 3, cc = (idx & 7) * 4;
            float ri = rinv[rr];
            float4 v = pr[i];
            v.x *= ri; v.y *= ri; v.z *= ri; v.w *= ri;
            *(float4*)(A + (size_t)rr * lda + c * 32 + cc) = v;
            uint32_t h0, h1; pack4h(v, h0, h1);
            *(uint2*)(Ah + rr * LDT32 + cc) = make_uint2(h0, h1);
        }
        if (c + 1 < nC) {
#pragma unroll
            for (int i = 0; i < 4; i++) {
                int idx = i * 256 + tid;
                int rr = idx >> 3, cc = (idx & 7) * 4;
                pr[i] = *(const float4*)(A + (size_t)rr * lda + (c + 1) * 32 + cc);
            }
        }
        __syncthreads();
        compute_chunk<LDT32, TILE32, 32, false>(acc, buf, wm, wn, lane);
        __syncthreads();
        if (c + 2 < nC)
            issue_B32(buf, Bhg, ldb, (c + 2) * 32, tid);
        CP_COMMIT();
    }
    asm volatile("cp.async.wait_all;" ::: "memory");
    __syncthreads();
}

// stage acc (fp32) into smem [128][132]
__device__ __forceinline__ void stage_acc(float (*acc)[8][4], float* stg, int wid, int lane) {
    int wm = wid & 3, wn = wid >> 2;
    int r0 = wm * 32 + (lane >> 2), c0 = wn * 64 + (lane & 3) * 2;
#pragma unroll
    for (int mt = 0; mt < 2; mt++)
#pragma unroll
        for (int nt = 0; nt < 8; nt++) {
            int r = r0 + mt * 16, c = c0 + nt * 8;
            *(float2*)&stg[r * 132 + c] = make_float2(acc[mt][nt][0], acc[mt][nt][1]);
            *(float2*)&stg[(r + 8) * 132 + c] = make_float2(acc[mt][nt][2], acc[mt][nt][3]);
        }
}

#define ZERO_ACC(acc) \
    _Pragma("unroll") for (int i_ = 0; i_ < 2; i_++) \
    _Pragma("unroll") for (int j_ = 0; j_ < 8; j_++) \
    _Pragma("unroll") for (int q_ = 0; q_ < 4; q_++) acc[i_][j_][q_] = 0.0f;

// ---------------- prep kernels ----------------
__global__ void split_x_kernel(const float* __restrict__ x, h16* __restrict__ xh, int n4) {
    int i = blockIdx.x * blockDim.x + threadIdx.x;
    if (i >= n4) return;
    float4 v = *(const float4*)(x + 4 * (size_t)i);
    uint32_t h0, h1; pack4h(v, h0, h1);
    *(uint2*)(xh + 4 * (size_t)i) = make_uint2(h0, h1);
}
// transpose + hi/lo split (for Wk)
__global__ void transpose_split_kernel(const float* __restrict__ src,
                                       h16* __restrict__ dh, h16* __restrict__ dl,
                                       int M, int N) {
    __shared__ float t[32][33];
    int bx = blockIdx.x * 32, by = blockIdx.y * 32;
    int x = threadIdx.x, y0 = threadIdx.y;
#pragma unroll
    for (int j = 0; j < 32; j += 8)
        t[y0 + j][x] = src[(size_t)(by + y0 + j) * N + bx + x];
    __syncthreads();
#pragma unroll
    for (int j = 0; j < 32; j += 8) {
        float v = t[x][y0 + j];
        h16 h = __float2half_rn(v);
        h16 l = __float2half_rn(v - __half2float(h));
        size_t o = (size_t)(bx + y0 + j) * M + by + x;
        dh[o] = h; dl[o] = l;
    }
}
// transpose + single fp16 pack (Wq, Wv, Wo)
__global__ void transpose_pack_kernel(const float* __restrict__ src,
                                      h16* __restrict__ dh, int M, int N) {
    __shared__ float t[32][33];
    int bx = blockIdx.x * 32, by = blockIdx.y * 32;
    int x = threadIdx.x, y0 = threadIdx.y;
#pragma unroll
    for (int j = 0; j < 32; j += 8)
        t[y0 + j][x] = src[(size_t)(by + y0 + j) * N + bx + x];
    __syncthreads();
#pragma unroll
    for (int j = 0; j < 32; j += 8)
        dh[(size_t)(bx + y0 + j) * M + by + x] = __float2half_rn(t[x][y0 + j]);
}
__global__ void zero_kernel(float* p, int n) {
    int i = blockIdx.x * blockDim.x + threadIdx.x;
    if (i < n) p[i] = 0.0f;
}

// ---------------- Q projection (1-term, single-fp16 epilogue) ----------------
__global__ __launch_bounds__(256, 2) void mma_qproj(
    const h16* __restrict__ Ag,
    const h16* __restrict__ Bhg,
    const float* __restrict__ bias,
    h16* __restrict__ Ch)
{
    extern __shared__ __align__(16) char smem[];
    const int tid = threadIdx.x, wid = tid >> 5, lane = tid & 31;
    const int row0 = blockIdx.y * 128, col0 = blockIdx.x * 128;

    float* bs = (float*)(smem + AUX64);
    if (tid < 128) bs[tid] = bias[col0 + tid];

    float acc[2][8][4];
    ZERO_ACC(acc)
    gemm_core_h<false>(acc, Ag + (size_t)row0 * DM_, DM_,
                       Bhg + (size_t)col0 * DM_, nullptr, DM_, DM_, smem);

    float* stg = (float*)smem;
    stage_acc(acc, stg, wid, lane);
    __syncthreads();
#pragma unroll 1
    for (int i = 0; i < 16; i++) {
        int idx = i * 256 + tid;
        int rr = idx >> 5, c4 = (idx & 31) << 2;
        float4 v = *(float4*)&stg[rr * 132 + c4];
        v.x += bs[c4]; v.y += bs[c4 + 1]; v.z += bs[c4 + 2]; v.w += bs[c4 + 3];
        uint32_t h0, h1; pack4h(v, h0, h1);
        *(uint2*)(Ch + (size_t)(row0 + rr) * DM_ + col0 + c4) = make_uint2(h0, h1);
    }
}

// ---------------- fused K (2-term, hi/lo out) + V (1-term, transposed single out) ----------------
__global__ __launch_bounds__(256, 2) void mma_kvproj(
    const h16* __restrict__ Ag,
    const h16* __restrict__ Wkh, const h16* __restrict__ Wkl,
    const h16* __restrict__ Wvh,
    const float* __restrict__ bk, const float* __restrict__ bv,
    h16* __restrict__ Kh, h16* __restrict__ Kl,
    h16* __restrict__ Vth)
{
    extern __shared__ __align__(16) char smem[];
    const int tid = threadIdx.x, wid = tid >> 5, lane = tid & 31;
    const int row0 = blockIdx.y * 128;
    const int z = blockIdx.z;                  // 0 = K, 1 = V

    const float* bias = z ? bv : bk;
    float* bs = (float*)(smem + AUX64);
    if (tid < 128) bs[tid] = bias[tid];

    float acc[2][8][4];
    ZERO_ACC(acc)
    if (z == 0)
        gemm_core_h<true>(acc, Ag + (size_t)row0 * DM_, DM_, Wkh, Wkl, DM_, DM_, smem);
    else
        gemm_core_h<false>(acc, Ag + (size_t)row0 * DM_, DM_, Wvh, nullptr, DM_, DM_, smem);

    float* stg = (float*)smem;
    stage_acc(acc, stg, wid, lane);
    __syncthreads();
    if (z == 0) {
        // K: hi/lo, row-major [B*S, HD]
#pragma unroll 1
        for (int i = 0; i < 16; i++) {
            int idx = i * 256 + tid;
            int rr = idx >> 5, c4 = (idx & 31) << 2;
            float4 v = *(float4*)&stg[rr * 132 + c4];
            v.x += bs[c4]; v.y += bs[c4 + 1]; v.z += bs[c4 + 2]; v.w += bs[c4 + 3];
            uint32_t h0, h1, l0, l1; split4h(v, h0, h1, l0, l1);
            size_t o = (size_t)(row0 + rr) * HD_ + c4;
            *(uint2*)(Kh + o) = make_uint2(h0, h1);
            *(uint2*)(Kl + o) = make_uint2(l0, l1);
        }
    } else {
        // V: single fp16, transposed [B][HD][S]
        int b = row0 >> 11;
        int s0 = row0 & (S_ - 1);
        h16* Vb = Vth + (size_t)b * HD_ * S_;
#pragma unroll 1
        for (int i = 0; i < 64; i++) {
            int idx = i * 256 + tid;
            int m = idx & 127, n = idx >> 7;
            Vb[(size_t)n * S_ + s0 + m] = __float2half_rn(stg[m * 132 + n] + bs[n]);
        }
    }
}

// ---------------- scores: E = exp(scale * Q Kt) fp32 out + rowsums (2-term) ----------------
__global__ __launch_bounds__(256, 2) void mma_scores(
    const h16* __restrict__ Qh,
    const h16* __restrict__ Kh, const h16* __restrict__ Kl,
    float* __restrict__ scores, float* __restrict__ rowsum)
{
    extern __shared__ __align__(16) char smem[];
    const int tid = threadIdx.x, wid = tid >> 5, lane = tid & 31;
    const int bh = blockIdx.z;
    const int b = bh >> 4, hd = bh & 15;
    const int row0 = blockIdx.y * 128, col0 = blockIdx.x * 128;

    float acc[2][8][4];
    ZERO_ACC(acc)
    gemm_core_h<true>(acc,
        Qh + ((size_t)b * S_ + row0) * DM_ + hd * HD_, DM_,
        Kh + ((size_t)b * S_ + col0) * HD_,
        Kl + ((size_t)b * S_ + col0) * HD_, HD_, HD_, smem);

    float* stg = (float*)smem;
    float* red = (float*)(smem + RED64);
    const int wm = wid & 3, wn = wid >> 2;
    const int r0 = wm * 32 + (lane >> 2), c0 = wn * 64 + (lane & 3) * 2;
    float sums[2][2] = {{0.f, 0.f}, {0.f, 0.f}};
#pragma unroll
    for (int mt = 0; mt < 2; mt++)
#pragma unroll
        for (int nt = 0; nt < 8; nt++) {
            float e0 = __expf(acc[mt][nt][0] * SCALE_);
            float e1 = __expf(acc[mt][nt][1] * SCALE_);
            float e2 = __expf(acc[mt][nt][2] * SCALE_);
            float e3 = __expf(acc[mt][nt][3] * SCALE_);
            int r = r0 + mt * 16, c = c0 + nt * 8;
            *(float2*)&stg[r * 132 + c] = make_float2(e0, e1);
            *(float2*)&stg[(r + 8) * 132 + c] = make_float2(e2, e3);
            sums[mt][0] += e0 + e1;
            sums[mt][1] += e2 + e3;
        }
#pragma unroll
    for (int mt = 0; mt < 2; mt++)
#pragma unroll
        for (int hh = 0; hh < 2; hh++) {
            float v = sums[mt][hh];
            v += __shfl_xor_sync(0xFFFFFFFFu, v, 1);
            v += __shfl_xor_sync(0xFFFFFFFFu, v, 2);
            sums[mt][hh] = v;
        }
    if ((lane & 3) == 0) {
#pragma unroll
        for (int mt = 0; mt < 2; mt++)
#pragma unroll
            for (int hh = 0; hh < 2; hh++)
                red[(wm * 32 + mt * 16 + hh * 8 + (lane >> 2)) * 2 + wn] = sums[mt][hh];
    }
    __syncthreads();
    if (tid < 128)
        atomicAdd(&rowsum[(size_t)bh * S_ + row0 + tid], red[tid * 2] + red[tid * 2 + 1]);

    float* Crow = scores + ((size_t)bh * S_ + row0) * S_ + col0;
#pragma unroll 1
    for (int i = 0; i < 16; i++) {
        int idx = i * 256 + tid;
        int rr = idx >> 5, c4 = (idx & 31) << 2;
        *(float4*)&Crow[(size_t)rr * S_ + c4] = *(float4*)&stg[rr * 132 + c4];
    }
}

// ---------------- normalize scores in place + PV (1-term, single-fp16 epilogue) ----------------
__global__ __launch_bounds__(256, 2) void mma_softmax_pv(
    float* __restrict__ scores, const float* __restrict__ rowsum,
    const h16* __restrict__ Vth, h16* __restrict__ attnh)
{
    extern __shared__ __align__(16) char smem[];
    const int tid = threadIdx.x, wid = tid >> 5, lane = tid & 31;
    const int bh = blockIdx.y;
    const int b = bh >> 4, hd = bh & 15;
    const int row0 = blockIdx.x * 128;

    float* rinv = (float*)(smem + AUX32);
    if (tid < 128) rinv[tid] = 1.0f / rowsum[(size_t)bh * S_ + row0 + tid];
    __syncthreads();

    float acc[2][8][4];
    ZERO_ACC(acc)
    gemm_core_pv(acc, scores + ((size_t)bh * S_ + row0) * S_, S_,
                 Vth + (size_t)b * HD_ * S_, S_, S_, smem, rinv);

    float* stg = (float*)smem;
    stage_acc(acc, stg, wid, lane);
    __syncthreads();
    h16* Cb = attnh + ((size_t)b * S_ + row0) * DM_ + hd * HD_;
#pragma unroll 1
    for (int i = 0; i < 16; i++) {
        int idx = i * 256 + tid;
        int rr = idx >> 5, c4 = (idx & 31) << 2;
        float4 v = *(float4*)&stg[rr * 132 + c4];
        uint32_t h0, h1; pack4h(v, h0, h1);
        *(uint2*)(Cb + (size_t)rr * DM_ + c4) = make_uint2(h0, h1);
    }
}

// ---------------- output GEMM (1-term, fp32 + bias epilogue) ----------------
__global__ __launch_bounds__(256, 2) void mma_out(
    const h16* __restrict__ Ag,
    const h16* __restrict__ Bhg,
    const float* __restrict__ bias, float* __restrict__ C)
{
    extern __shared__ __align__(16) char smem[];
    const int tid = threadIdx.x, wid = tid >> 5, lane = tid & 31;
    const int row0 = blockIdx.y * 128, col0 = blockIdx.x * 128;

    float* bs = (float*)(smem + AUX64);
    if (tid < 128) bs[tid] = bias[col0 + tid];

    float acc[2][8][4];
    ZERO_ACC(acc)
    gemm_core_h<false>(acc, Ag + (size_t)row0 * DM_, DM_,
                       Bhg + (size_t)col0 * DM_, nullptr, DM_, DM_, smem);

    float* stg = (float*)smem;
    stage_acc(acc, stg, wid, lane);
    __syncthreads();
#pragma unroll 1
    for (int i = 0; i < 16; i++) {
        int idx = i * 256 + tid;
        int rr = idx >> 5, c4 = (idx & 31) << 2;
        float4 v = *(float4*)&stg[rr * 132 + c4];
        v.x += bs[c4]; v.y += bs[c4 + 1]; v.z += bs[c4 + 2]; v.w += bs[c4 + 3];
        *(float4*)&C[(size_t)(row0 + rr) * DM_ + col0 + c4] = v;
    }
}

// ---------------- launch ----------------
extern "C" void kernel_launch(void* const* d_in, const int* in_sizes, int n_in,
                              void* d_out, int out_size)
{
    const float* x  = (const float*)d_in[0];
    const float* Wq = (const float*)d_in[1];
    const float* bq = (const float*)d_in[2];
    const float* Wk = (const float*)d_in[3];
    const float* bk = (const float*)d_in[4];
    const float* Wv = (const float*)d_in[5];
    const float* bv = (const float*)d_in[6];
    const float* Wo = (const float*)d_in[7];
    const float* bo = (const float*)d_in[8];

    float* out = (float*)d_out;
    float* scores = out + (size_t)B_ * S_ * DM_;

    h16 *pxh, *pQh, *pKh, *pKl, *pVth, *pAh;
    h16 *pWqh, *pWkh, *pWkl, *pWvh, *pWoh;
    float* pRS;
    cudaGetSymbolAddress((void**)&pxh, g_xh);
    cudaGetSymbolAddress((void**)&pQh, g_Qh);
    cudaGetSymbolAddress((void**)&pKh, g_Kh);   cudaGetSymbolAddress((void**)&pKl, g_Kl);
    cudaGetSymbolAddress((void**)&pVth, g_Vth);
    cudaGetSymbolAddress((void**)&pAh, g_attnh);
    cudaGetSymbolAddress((void**)&pWqh, g_Wqh);
    cudaGetSymbolAddress((void**)&pWkh, g_Wkh); cudaGetSymbolAddress((void**)&pWkl, g_Wkl);
    cudaGetSymbolAddress((void**)&pWvh, g_Wvh);
    cudaGetSymbolAddress((void**)&pWoh, g_Woh);
    cudaGetSymbolAddress((void**)&pRS, g_rowsum);

    static int smem_set = 0;
    if (!smem_set) {
        cudaFuncSetAttribute(mma_qproj, cudaFuncAttributeMaxDynamicSharedMemorySize, SMEM64);
        cudaFuncSetAttribute(mma_kvproj, cudaFuncAttributeMaxDynamicSharedMemorySize, SMEM64);
        cudaFuncSetAttribute(mma_scores, cudaFuncAttributeMaxDynamicSharedMemorySize, SMEM64);
        cudaFuncSetAttribute(mma_softmax_pv, cudaFuncAttributeMaxDynamicSharedMemorySize, SMEM32);
        cudaFuncSetAttribute(mma_out, cudaFuncAttributeMaxDynamicSharedMemorySize, SMEM64);
        smem_set = 1;
    }

    const int M = B_ * S_;   // 8192
    split_x_kernel<<<(M * DM_ / 4 + 255) / 256, 256>>>(x, pxh, M * DM_ / 4);
    transpose_pack_kernel<<<dim3(DM_ / 32, DM_ / 32), dim3(32, 8)>>>(Wq, pWqh, DM_, DM_);
    transpose_split_kernel<<<dim3(HD_ / 32, DM_ / 32), dim3(32, 8)>>>(Wk, pWkh, pWkl, DM_, HD_);
    transpose_pack_kernel<<<dim3(HD_ / 32, DM_ / 32), dim3(32, 8)>>>(Wv, pWvh, DM_, HD_);
    transpose_pack_kernel<<<dim3(DM_ / 32, DM_ / 32), dim3(32, 8)>>>(Wo, pWoh, DM_, DM_);
    zero_kernel<<<(B_ * H_ * S_ + 255) / 256, 256>>>(pRS, B_ * H_ * S_);

    mma_qproj<<<dim3(DM_ / 128, M / 128), 256, SMEM64>>>(pxh, pWqh, bq, pQh);
    mma_kvproj<<<dim3(1, M / 128, 2), 256, SMEM64>>>(
        pxh, pWkh, pWkl, pWvh, bk, bv, pKh, pKl, pVth);

    mma_scores<<<dim3(S_ / 128, S_ / 128, B_ * H_), 256, SMEM64>>>(
        pQh, pKh, pKl, scores, pRS);
    mma_softmax_pv<<<dim3(S_ / 128, B_ * H_), 256, SMEM32>>>(
        scores, pRS, pVth, pAh);

    mma_out<<<dim3(DM_ / 128, M / 128), 256, SMEM64>>>(pAh, pWoh, bo, out);
}

// round 12
// speedup vs baseline: 3.6785x; 1.2390x over previous
#include <cuda_runtime.h>
#include <cuda_fp16.h>
#include <cstdint>

// Problem dims
#define B_  4
#define S_  2048
#define DM_ 2048
#define H_  16
#define HD_ 128
#define SCALE_ 0.08838834764831843f   // 1/sqrt(128)

typedef __half h16;

// ---------------- scratch (__device__ globals) ----------------
__device__ h16 g_xh[(size_t)B_ * S_ * DM_];       // single fp16
__device__ h16 g_Qh[(size_t)B_ * S_ * DM_];       // single fp16
__device__ h16 g_Kh[(size_t)B_ * S_ * HD_];       // single fp16
__device__ h16 g_Vth[(size_t)B_ * HD_ * S_];      // single fp16, [B][128][2048]
__device__ h16 g_attnh[(size_t)B_ * S_ * DM_];    // single fp16
__device__ h16 g_Wqh[(size_t)DM_ * DM_];          // transposed [N][K], single
__device__ h16 g_Wkh[(size_t)HD_ * DM_];          // single
__device__ h16 g_Wvh[(size_t)HD_ * DM_];          // single
__device__ h16 g_Woh[(size_t)DM_ * DM_];          // single
__device__ float g_rowsum[(size_t)B_ * H_ * S_];

// ---------------- smem layouts ----------------
// BK=64 cores: stage = {A, B}, each 128 x 72 fp16 = 18432 B
#define LDT64   72
#define TILE64  (128 * LDT64 * 2)         // 18432
#define STAGE64 (2 * TILE64)              // 36864
#define AUX64   73728                     // after 2 stages (73728); staging 67584 fits under
#define RED64   (AUX64 + 512)
#define SMEM64  (AUX64 + 1536)            // 75264
// BK=32 PV core: stage = {A, Bh}, padded
#define LDT32   40
#define TILE32  10240
#define STAGE32 (2 * TILE32)              // 20480
#define AUX32   67584                     // after fp32 staging 128x132x4
#define SMEM32  69632

// ---------------- low-level helpers ----------------
__device__ __forceinline__ uint32_t smem_u32(const void* p) {
    uint32_t a;
    asm("{ .reg .u64 t; cvta.to.shared.u64 t, %1; cvt.u32.u64 %0, t; }" : "=r"(a) : "l"(p));
    return a;
}
__device__ __forceinline__ void cp16(uint32_t s, const void* g) {
    asm volatile("cp.async.ca.shared.global [%0], [%1], 16;"
                 :: "r"(s), "l"(__cvta_generic_to_global(g)));
}
#define CP_COMMIT() asm volatile("cp.async.commit_group;" ::: "memory")
#define CP_WAIT1()  asm volatile("cp.async.wait_group 1;" ::: "memory")
__device__ __forceinline__ void ldsm4(uint32_t* r, uint32_t a) {
    asm volatile("ldmatrix.sync.aligned.m8n8.x4.shared.b16 {%0,%1,%2,%3}, [%4];"
        : "=r"(r[0]), "=r"(r[1]), "=r"(r[2]), "=r"(r[3]) : "r"(a));
}
__device__ __forceinline__ void mma_fp16(float* d, const uint32_t* a, uint32_t b0, uint32_t b1) {
    asm volatile("mma.sync.aligned.m16n8k16.row.col.f32.f16.f16.f32 "
        "{%0,%1,%2,%3}, {%4,%5,%6,%7}, {%8,%9}, {%0,%1,%2,%3};"
        : "+f"(d[0]), "+f"(d[1]), "+f"(d[2]), "+f"(d[3])
        : "r"(a[0]), "r"(a[1]), "r"(a[2]), "r"(a[3]), "r"(b0), "r"(b1));
}
__device__ __forceinline__ uint32_t hbits2(__half2 h) {
    return *reinterpret_cast<uint32_t*>(&h);
}
__device__ __forceinline__ void pack4h(float4 v, uint32_t& h0, uint32_t& h1) {
    __half2 a = __floats2half2_rn(v.x, v.y);
    __half2 b = __floats2half2_rn(v.z, v.w);
    h0 = hbits2(a); h1 = hbits2(b);
}

// ---------------- BK=64 tile movement ----------------
__device__ __forceinline__ void issue_tiles64(char* buf,
    const h16* __restrict__ Ag, size_t lda,
    const h16* __restrict__ Bg, size_t ldb,
    int k0, int tid)
{
    uint32_t sA = smem_u32(buf);
#pragma unroll
    for (int i = 0; i < 4; i++) {
        int idx = i * 256 + tid;              // 0..1023
        int r = idx >> 3, c8 = (idx & 7) * 8;
        cp16(sA + r * (LDT64 * 2) + c8 * 2, Ag + (size_t)r * lda + k0 + c8);
    }
    uint32_t sB = sA + TILE64;
#pragma unroll
    for (int i = 0; i < 4; i++) {
        int idx = i * 256 + tid;
        int r = idx >> 3, c8 = (idx & 7) * 8;
        cp16(sB + r * (LDT64 * 2) + c8 * 2, Bg + (size_t)r * ldb + k0 + c8);
    }
}
// BK=32 B-only (PV)
__device__ __forceinline__ void issue_B32(char* buf,
    const h16* __restrict__ Bg, size_t ldb, int k0, int tid)
{
    uint32_t sB = smem_u32(buf) + TILE32;
#pragma unroll
    for (int i = 0; i < 2; i++) {
        int idx = i * 256 + tid;
        int r = idx >> 2, c8 = (idx & 3) * 8;
        cp16(sB + r * (LDT32 * 2) + c8 * 2, Bg + (size_t)r * ldb + k0 + c8);
    }
}

// ---------------- MMA compute: one chunk, warp 32x64, 1-term ----------------
template<int LDT, int TILE, int BK>
__device__ __forceinline__ void compute_chunk(float (*acc)[8][4], char* buf,
                                              int wm, int wn, int lane)
{
    h16* Ah = (h16*)buf;
    h16* Bh = (h16*)(buf + TILE);
    const int ar = lane & 15;
    const int acs = (lane >> 4) << 3;
#pragma unroll
    for (int kk = 0; kk < BK; kk += 16) {
        const int ac = kk + acs;
        uint32_t aH[2][4];
#pragma unroll
        for (int mt = 0; mt < 2; mt++)
            ldsm4(aH[mt], smem_u32(Ah + (wm * 32 + mt * 16 + ar) * LDT + ac));
#pragma unroll
        for (int p = 0; p < 4; p++) {
            uint32_t bh[4];
            ldsm4(bh, smem_u32(Bh + (wn * 64 + p * 16 + ar) * LDT + ac));
#pragma unroll
            for (int mt = 0; mt < 2; mt++) {
                mma_fp16(acc[mt][2 * p],     aH[mt], bh[0], bh[2]);
                mma_fp16(acc[mt][2 * p + 1], aH[mt], bh[1], bh[3]);
            }
        }
    }
}

// generic BK=64 pipelined core (A, B single fp16)
__device__ __forceinline__ void gemm_core_h(float (*acc)[8][4],
    const h16* __restrict__ Ag, size_t lda,
    const h16* __restrict__ Bg, size_t ldb,
    int Kdim, char* smem)
{
    const int tid = threadIdx.x, wid = tid >> 5, lane = tid & 31;
    const int wm = wid & 3, wn = wid >> 2;
    const int nC = Kdim >> 6;
    issue_tiles64(smem, Ag, lda, Bg, ldb, 0, tid); CP_COMMIT();
    issue_tiles64(smem + STAGE64, Ag, lda, Bg, ldb, 64, tid); CP_COMMIT();
#pragma unroll 1
    for (int c = 0; c < nC; c++) {
        char* buf = smem + (c & 1) * STAGE64;
        CP_WAIT1();
        __syncthreads();
        compute_chunk<LDT64, TILE64, 64>(acc, buf, wm, wn, lane);
        __syncthreads();
        if (c + 2 < nC)
            issue_tiles64(buf, Ag, lda, Bg, ldb, (c + 2) * 64, tid);
        CP_COMMIT();
    }
    asm volatile("cp.async.wait_all;" ::: "memory");
    __syncthreads();
}

// PV core: BK=32, 1-term. A = fp32 scores with register double-buffer prefetch:
// normalize by rinv, write normalized fp32 back in place, pack fp16 A to smem.
__device__ __forceinline__ void gemm_core_pv(float (*acc)[8][4],
    float* __restrict__ A, size_t lda,
    const h16* __restrict__ Bg, size_t ldb,
    int Kdim, char* smem, const float* __restrict__ rinv)
{
    const int tid = threadIdx.x, wid = tid >> 5, lane = tid & 31;
    const int wm = wid & 3, wn = wid >> 2;
    const int nC = Kdim >> 5;                     // 64
    issue_B32(smem, Bg, ldb, 0, tid); CP_COMMIT();
    issue_B32(smem + STAGE32, Bg, ldb, 32, tid); CP_COMMIT();

    float4 pr[4];
#pragma unroll
    for (int i = 0; i < 4; i++) {
        int idx = i * 256 + tid;
        int rr = idx >> 3, cc = (idx & 7) * 4;
        pr[i] = *(const float4*)(A + (size_t)rr * lda + cc);
    }
#pragma unroll 1
    for (int c = 0; c < nC; c++) {
        char* buf = smem + (c & 1) * STAGE32;
        CP_WAIT1();
        h16* Ah = (h16*)buf;
#pragma unroll
        for (int i = 0; i < 4; i++) {
            int idx = i * 256 + tid;
            int rr = idx >> 3, cc = (idx & 7) * 4;
            float ri = rinv[rr];
            float4 v = pr[i];
            v.x *= ri; v.y *= ri; v.z *= ri; v.w *= ri;
            *(float4*)(A + (size_t)rr * lda + c * 32 + cc) = v;
            uint32_t h0, h1; pack4h(v, h0, h1);
            *(uint2*)(Ah + rr * LDT32 + cc) = make_uint2(h0, h1);
        }
        if (c + 1 < nC) {
#pragma unroll
            for (int i = 0; i < 4; i++) {
                int idx = i * 256 + tid;
                int rr = idx >> 3, cc = (idx & 7) * 4;
                pr[i] = *(const float4*)(A + (size_t)rr * lda + (c + 1) * 32 + cc);
            }
        }
        __syncthreads();
        compute_chunk<LDT32, TILE32, 32>(acc, buf, wm, wn, lane);
        __syncthreads();
        if (c + 2 < nC)
            issue_B32(buf, Bg, ldb, (c + 2) * 32, tid);
        CP_COMMIT();
    }
    asm volatile("cp.async.wait_all;" ::: "memory");
    __syncthreads();
}

// stage acc (fp32) into smem [128][132]
__device__ __forceinline__ void stage_acc(float (*acc)[8][4], float* stg, int wid, int lane) {
    int wm = wid & 3, wn = wid >> 2;
    int r0 = wm * 32 + (lane >> 2), c0 = wn * 64 + (lane & 3) * 2;
#pragma unroll
    for (int mt = 0; mt < 2; mt++)
#pragma unroll
        for (int nt = 0; nt < 8; nt++) {
            int r = r0 + mt * 16, c = c0 + nt * 8;
            *(float2*)&stg[r * 132 + c] = make_float2(acc[mt][nt][0], acc[mt][nt][1]);
            *(float2*)&stg[(r + 8) * 132 + c] = make_float2(acc[mt][nt][2], acc[mt][nt][3]);
        }
}

#define ZERO_ACC(acc) \
    _Pragma("unroll") for (int i_ = 0; i_ < 2; i_++) \
    _Pragma("unroll") for (int j_ = 0; j_ < 8; j_++) \
    _Pragma("unroll") for (int q_ = 0; q_ < 4; q_++) acc[i_][j_][q_] = 0.0f;

// ---------------- prep kernels ----------------
__global__ void split_x_kernel(const float* __restrict__ x, h16* __restrict__ xh, int n4) {
    int i = blockIdx.x * blockDim.x + threadIdx.x;
    if (i >= n4) return;
    float4 v = *(const float4*)(x + 4 * (size_t)i);
    uint32_t h0, h1; pack4h(v, h0, h1);
    *(uint2*)(xh + 4 * (size_t)i) = make_uint2(h0, h1);
}
// transpose + single fp16 pack
__global__ void transpose_pack_kernel(const float* __restrict__ src,
                                      h16* __restrict__ dh, int M, int N) {
    __shared__ float t[32][33];
    int bx = blockIdx.x * 32, by = blockIdx.y * 32;
    int x = threadIdx.x, y0 = threadIdx.y;
#pragma unroll
    for (int j = 0; j < 32; j += 8)
        t[y0 + j][x] = src[(size_t)(by + y0 + j) * N + bx + x];
    __syncthreads();
#pragma unroll
    for (int j = 0; j < 32; j += 8)
        dh[(size_t)(bx + y0 + j) * M + by + x] = __float2half_rn(t[x][y0 + j]);
}
__global__ void zero_kernel(float* p, int n) {
    int i = blockIdx.x * blockDim.x + threadIdx.x;
    if (i < n) p[i] = 0.0f;
}

// ---------------- Q projection (single-fp16 epilogue) ----------------
__global__ __launch_bounds__(256, 2) void mma_qproj(
    const h16* __restrict__ Ag,
    const h16* __restrict__ Bg,
    const float* __restrict__ bias,
    h16* __restrict__ Ch)
{
    extern __shared__ __align__(16) char smem[];
    const int tid = threadIdx.x, wid = tid >> 5, lane = tid & 31;
    const int row0 = blockIdx.y * 128, col0 = blockIdx.x * 128;

    float* bs = (float*)(smem + AUX64);
    if (tid < 128) bs[tid] = bias[col0 + tid];

    float acc[2][8][4];
    ZERO_ACC(acc)
    gemm_core_h(acc, Ag + (size_t)row0 * DM_, DM_,
                Bg + (size_t)col0 * DM_, DM_, DM_, smem);

    float* stg = (float*)smem;
    stage_acc(acc, stg, wid, lane);
    __syncthreads();
#pragma unroll 1
    for (int i = 0; i < 16; i++) {
        int idx = i * 256 + tid;
        int rr = idx >> 5, c4 = (idx & 31) << 2;
        float4 v = *(float4*)&stg[rr * 132 + c4];
        v.x += bs[c4]; v.y += bs[c4 + 1]; v.z += bs[c4 + 2]; v.w += bs[c4 + 3];
        uint32_t h0, h1; pack4h(v, h0, h1);
        *(uint2*)(Ch + (size_t)(row0 + rr) * DM_ + col0 + c4) = make_uint2(h0, h1);
    }
}

// ---------------- fused K + V projection (gridDim.z selects) ----------------
__global__ __launch_bounds__(256, 2) void mma_kvproj(
    const h16* __restrict__ Ag,
    const h16* __restrict__ Wkh, const h16* __restrict__ Wvh,
    const float* __restrict__ bk, const float* __restrict__ bv,
    h16* __restrict__ Kh, h16* __restrict__ Vth)
{
    extern __shared__ __align__(16) char smem[];
    const int tid = threadIdx.x, wid = tid >> 5, lane = tid & 31;
    const int row0 = blockIdx.y * 128;
    const int z = blockIdx.z;                  // 0 = K, 1 = V

    const h16* Bg = z ? Wvh : Wkh;
    const float* bias = z ? bv : bk;
    float* bs = (float*)(smem + AUX64);
    if (tid < 128) bs[tid] = bias[tid];

    float acc[2][8][4];
    ZERO_ACC(acc)
    gemm_core_h(acc, Ag + (size_t)row0 * DM_, DM_, Bg, DM_, DM_, smem);

    float* stg = (float*)smem;
    stage_acc(acc, stg, wid, lane);
    __syncthreads();
    if (z == 0) {
        // K: single fp16, row-major [B*S, HD]
#pragma unroll 1
        for (int i = 0; i < 16; i++) {
            int idx = i * 256 + tid;
            int rr = idx >> 5, c4 = (idx & 31) << 2;
            float4 v = *(float4*)&stg[rr * 132 + c4];
            v.x += bs[c4]; v.y += bs[c4 + 1]; v.z += bs[c4 + 2]; v.w += bs[c4 + 3];
            uint32_t h0, h1; pack4h(v, h0, h1);
            *(uint2*)(Kh + (size_t)(row0 + rr) * HD_ + c4) = make_uint2(h0, h1);
        }
    } else {
        // V: single fp16, transposed [B][HD][S]
        int b = row0 >> 11;
        int s0 = row0 & (S_ - 1);
        h16* Vb = Vth + (size_t)b * HD_ * S_;
#pragma unroll 1
        for (int i = 0; i < 64; i++) {
            int idx = i * 256 + tid;
            int m = idx & 127, n = idx >> 7;
            Vb[(size_t)n * S_ + s0 + m] = __float2half_rn(stg[m * 132 + n] + bs[n]);
        }
    }
}

// ---------------- scores: E = exp(scale * Q Kt) fp32 out + rowsums (1-term) ----------------
__global__ __launch_bounds__(256, 2) void mma_scores(
    const h16* __restrict__ Qh,
    const h16* __restrict__ Kh,
    float* __restrict__ scores, float* __restrict__ rowsum)
{
    extern __shared__ __align__(16) char smem[];
    const int tid = threadIdx.x, wid = tid >> 5, lane = tid & 31;
    const int bh = blockIdx.z;
    const int b = bh >> 4, hd = bh & 15;
    const int row0 = blockIdx.y * 128, col0 = blockIdx.x * 128;

    float acc[2][8][4];
    ZERO_ACC(acc)
    gemm_core_h(acc,
        Qh + ((size_t)b * S_ + row0) * DM_ + hd * HD_, DM_,
        Kh + ((size_t)b * S_ + col0) * HD_, HD_, HD_, smem);

    float* stg = (float*)smem;
    float* red = (float*)(smem + RED64);
    const int wm = wid & 3, wn = wid >> 2;
    const int r0 = wm * 32 + (lane >> 2), c0 = wn * 64 + (lane & 3) * 2;
    float sums[2][2] = {{0.f, 0.f}, {0.f, 0.f}};
#pragma unroll
    for (int mt = 0; mt < 2; mt++)
#pragma unroll
        for (int nt = 0; nt < 8; nt++) {
            float e0 = __expf(acc[mt][nt][0] * SCALE_);
            float e1 = __expf(acc[mt][nt][1] * SCALE_);
            float e2 = __expf(acc[mt][nt][2] * SCALE_);
            float e3 = __expf(acc[mt][nt][3] * SCALE_);
            int r = r0 + mt * 16, c = c0 + nt * 8;
            *(float2*)&stg[r * 132 + c] = make_float2(e0, e1);
            *(float2*)&stg[(r + 8) * 132 + c] = make_float2(e2, e3);
            sums[mt][0] += e0 + e1;
            sums[mt][1] += e2 + e3;
        }
#pragma unroll
    for (int mt = 0; mt < 2; mt++)
#pragma unroll
        for (int hh = 0; hh < 2; hh++) {
            float v = sums[mt][hh];
            v += __shfl_xor_sync(0xFFFFFFFFu, v, 1);
            v += __shfl_xor_sync(0xFFFFFFFFu, v, 2);
            sums[mt][hh] = v;
        }
    if ((lane & 3) == 0) {
#pragma unroll
        for (int mt = 0; mt < 2; mt++)
#pragma unroll
            for (int hh = 0; hh < 2; hh++)
                red[(wm * 32 + mt * 16 + hh * 8 + (lane >> 2)) * 2 + wn] = sums[mt][hh];
    }
    __syncthreads();
    if (tid < 128)
        atomicAdd(&rowsum[(size_t)bh * S_ + row0 + tid], red[tid * 2] + red[tid * 2 + 1]);

    float* Crow = scores + ((size_t)bh * S_ + row0) * S_ + col0;
#pragma unroll 1
    for (int i = 0; i < 16; i++) {
        int idx = i * 256 + tid;
        int rr = idx >> 5, c4 = (idx & 31) << 2;
        *(float4*)&Crow[(size_t)rr * S_ + c4] = *(float4*)&stg[rr * 132 + c4];
    }
}

// ---------------- normalize scores in place + PV (1-term, single-fp16 epilogue) ----------------
__global__ __launch_bounds__(256, 2) void mma_softmax_pv(
    float* __restrict__ scores, const float* __restrict__ rowsum,
    const h16* __restrict__ Vth, h16* __restrict__ attnh)
{
    extern __shared__ __align__(16) char smem[];
    const int tid = threadIdx.x, wid = tid >> 5, lane = tid & 31;
    const int bh = blockIdx.y;
    const int b = bh >> 4, hd = bh & 15;
    const int row0 = blockIdx.x * 128;

    float* rinv = (float*)(smem + AUX32);
    if (tid < 128) rinv[tid] = 1.0f / rowsum[(size_t)bh * S_ + row0 + tid];
    __syncthreads();

    float acc[2][8][4];
    ZERO_ACC(acc)
    gemm_core_pv(acc, scores + ((size_t)bh * S_ + row0) * S_, S_,
                 Vth + (size_t)b * HD_ * S_, S_, S_, smem, rinv);

    float* stg = (float*)smem;
    stage_acc(acc, stg, wid, lane);
    __syncthreads();
    h16* Cb = attnh + ((size_t)b * S_ + row0) * DM_ + hd * HD_;
#pragma unroll 1
    for (int i = 0; i < 16; i++) {
        int idx = i * 256 + tid;
        int rr = idx >> 5, c4 = (idx & 31) << 2;
        float4 v = *(float4*)&stg[rr * 132 + c4];
        uint32_t h0, h1; pack4h(v, h0, h1);
        *(uint2*)(Cb + (size_t)rr * DM_ + c4) = make_uint2(h0, h1);
    }
}

// ---------------- output GEMM (1-term, fp32 + bias epilogue) ----------------
__global__ __launch_bounds__(256, 2) void mma_out(
    const h16* __restrict__ Ag,
    const h16* __restrict__ Bg,
    const float* __restrict__ bias, float* __restrict__ C)
{
    extern __shared__ __align__(16) char smem[];
    const int tid = threadIdx.x, wid = tid >> 5, lane = tid & 31;
    const int row0 = blockIdx.y * 128, col0 = blockIdx.x * 128;

    float* bs = (float*)(smem + AUX64);
    if (tid < 128) bs[tid] = bias[col0 + tid];

    float acc[2][8][4];
    ZERO_ACC(acc)
    gemm_core_h(acc, Ag + (size_t)row0 * DM_, DM_,
                Bg + (size_t)col0 * DM_, DM_, DM_, smem);

    float* stg = (float*)smem;
    stage_acc(acc, stg, wid, lane);
    __syncthreads();
#pragma unroll 1
    for (int i = 0; i < 16; i++) {
        int idx = i * 256 + tid;
        int rr = idx >> 5, c4 = (idx & 31) << 2;
        float4 v = *(float4*)&stg[rr * 132 + c4];
        v.x += bs[c4]; v.y += bs[c4 + 1]; v.z += bs[c4 + 2]; v.w += bs[c4 + 3];
        *(float4*)&C[(size_t)(row0 + rr) * DM_ + col0 + c4] = v;
    }
}

// ---------------- launch ----------------
extern "C" void kernel_launch(void* const* d_in, const int* in_sizes, int n_in,
                              void* d_out, int out_size)
{
    const float* x  = (const float*)d_in[0];
    const float* Wq = (const float*)d_in[1];
    const float* bq = (const float*)d_in[2];
    const float* Wk = (const float*)d_in[3];
    const float* bk = (const float*)d_in[4];
    const float* Wv = (const float*)d_in[5];
    const float* bv = (const float*)d_in[6];
    const float* Wo = (const float*)d_in[7];
    const float* bo = (const float*)d_in[8];

    float* out = (float*)d_out;
    float* scores = out + (size_t)B_ * S_ * DM_;

    h16 *pxh, *pQh, *pKh, *pVth, *pAh;
    h16 *pWqh, *pWkh, *pWvh, *pWoh;
    float* pRS;
    cudaGetSymbolAddress((void**)&pxh, g_xh);
    cudaGetSymbolAddress((void**)&pQh, g_Qh);
    cudaGetSymbolAddress((void**)&pKh, g_Kh);
    cudaGetSymbolAddress((void**)&pVth, g_Vth);
    cudaGetSymbolAddress((void**)&pAh, g_attnh);
    cudaGetSymbolAddress((void**)&pWqh, g_Wqh);
    cudaGetSymbolAddress((void**)&pWkh, g_Wkh);
    cudaGetSymbolAddress((void**)&pWvh, g_Wvh);
    cudaGetSymbolAddress((void**)&pWoh, g_Woh);
    cudaGetSymbolAddress((void**)&pRS, g_rowsum);

    static int smem_set = 0;
    if (!smem_set) {
        cudaFuncSetAttribute(mma_qproj, cudaFuncAttributeMaxDynamicSharedMemorySize, SMEM64);
        cudaFuncSetAttribute(mma_kvproj, cudaFuncAttributeMaxDynamicSharedMemorySize, SMEM64);
        cudaFuncSetAttribute(mma_scores, cudaFuncAttributeMaxDynamicSharedMemorySize, SMEM64);
        cudaFuncSetAttribute(mma_softmax_pv, cudaFuncAttributeMaxDynamicSharedMemorySize, SMEM32);
        cudaFuncSetAttribute(mma_out, cudaFuncAttributeMaxDynamicSharedMemorySize, SMEM64);
        smem_set = 1;
    }

    const int M = B_ * S_;   // 8192
    split_x_kernel<<<(M * DM_ / 4 + 255) / 256, 256>>>(x, pxh, M * DM_ / 4);
    transpose_pack_kernel<<<dim3(DM_ / 32, DM_ / 32), dim3(32, 8)>>>(Wq, pWqh, DM_, DM_);
    transpose_pack_kernel<<<dim3(HD_ / 32, DM_ / 32), dim3(32, 8)>>>(Wk, pWkh, DM_, HD_);
    transpose_pack_kernel<<<dim3(HD_ / 32, DM_ / 32), dim3(32, 8)>>>(Wv, pWvh, DM_, HD_);
    transpose_pack_kernel<<<dim3(DM_ / 32, DM_ / 32), dim3(32, 8)>>>(Wo, pWoh, DM_, DM_);
    zero_kernel<<<(B_ * H_ * S_ + 255) / 256, 256>>>(pRS, B_ * H_ * S_);

    mma_qproj<<<dim3(DM_ / 128, M / 128), 256, SMEM64>>>(pxh, pWqh, bq, pQh);
    mma_kvproj<<<dim3(1, M / 128, 2), 256, SMEM64>>>(
        pxh, pWkh, pWvh, bk, bv, pKh, pVth);

    mma_scores<<<dim3(S_ / 128, S_ / 128, B_ * H_), 256, SMEM64>>>(
        pQh, pKh, scores, pRS);
    mma_softmax_pv<<<dim3(S_ / 128, B_ * H_), 256, SMEM32>>>(
        scores, pRS, pVth, pAh);

    mma_out<<<dim3(DM_ / 128, M / 128), 256, SMEM64>>>(pAh, pWoh, bo, out);
}